// round 2
// baseline (speedup 1.0000x reference)
#include <cuda_runtime.h>
#include <math.h>

#define NN 98304
#define NE 786432
#define NB 512

// -------- scratch (device globals; no allocation allowed) --------
__device__ __align__(256) float g_h[NN * 128];    // node states
__device__ __align__(256) float g_e[NE * 64];     // encoded edge features
__device__ __align__(256) float g_agg[NN * 128];  // aggregated messages
__device__ __align__(256) float g_t[NN * 128];    // transformed node states
__device__ int   g_qstart[NB];
__device__ int   g_cstart[NB];

// -------- zero agg --------
__global__ void zero_agg_kernel(int n4) {
    int i = blockIdx.x * 256 + threadIdx.x;
    if (i < n4) ((float4*)g_agg)[i] = make_float4(0.f, 0.f, 0.f, 0.f);
}

// -------- per-pair start offsets --------
__global__ void starts_kernel(const int* __restrict__ qs, const int* __restrict__ cs, int nb) {
    if (blockIdx.x == 0 && threadIdx.x == 0) {
        int s = 0;
        for (int b = 0; b < nb; b++) {
            g_qstart[b] = s; s += qs[b];
            g_cstart[b] = s; s += cs[b];
        }
    }
}

// -------- node encoder: h = nf @ W(32x128) + b --------
__global__ __launch_bounds__(256) void enc_node_kernel(
    const float* __restrict__ nf, const float* __restrict__ W,
    const float* __restrict__ bias, int n)
{
    __shared__ float s_nf[2][32];
    int tid = threadIdx.x;
    int local = tid >> 7;
    int c = tid & 127;
    int node = blockIdx.x * 2 + local;
    if (tid < 64) {
        int e = tid >> 5, k = tid & 31;
        int nn = blockIdx.x * 2 + e;
        s_nf[e][k] = (nn < n) ? nf[(size_t)nn * 32 + k] : 0.f;
    }
    __syncthreads();
    if (node >= n) return;
    float acc = bias[c];
#pragma unroll
    for (int k = 0; k < 32; k++) acc += s_nf[local][k] * W[k * 128 + c];
    g_h[(size_t)node * 128 + c] = acc;
}

// -------- edge encoder: e = ef @ W(16x64) + b --------
__global__ __launch_bounds__(256) void enc_edge_kernel(
    const float* __restrict__ ef, const float* __restrict__ W,
    const float* __restrict__ bias, int ne)
{
    __shared__ float s_ef[4][16];
    int tid = threadIdx.x;
    int le = tid >> 6;
    int c = tid & 63;
    int e = blockIdx.x * 4 + le;
    if (tid < 64) {
        int ee = tid >> 4, k = tid & 15;
        int eg = blockIdx.x * 4 + ee;
        s_ef[ee][k] = (eg < ne) ? ef[(size_t)eg * 16 + k] : 0.f;
    }
    __syncthreads();
    if (e >= ne) return;
    float acc = bias[c];
#pragma unroll
    for (int k = 0; k < 16; k++) acc += s_ef[le][k] * W[k * 64 + c];
    g_e[(size_t)e * 64 + c] = acc;
}

// -------- edge message MLPs (msg + rmsg fused), atomicAdd into agg --------
__global__ __launch_bounds__(256) void edge_msg_kernel(
    const int* __restrict__ fidx, const int* __restrict__ tidx,
    const float* __restrict__ mw1, const float* __restrict__ mb1,
    const float* __restrict__ mw2, const float* __restrict__ mb2,
    const float* __restrict__ rw1, const float* __restrict__ rb1,
    const float* __restrict__ rw2, const float* __restrict__ rb2)
{
    extern __shared__ float sm[];
    float* xs = sm;               // [32][320]
    float* hs = sm + 32 * 320;    // [32][256]
    __shared__ int sfrom[32], sto[32];
    int tid = threadIdx.x;
    int e0 = blockIdx.x * 32;
    if (tid < 32) { sfrom[tid] = fidx[e0 + tid]; sto[tid] = tidx[e0 + tid]; }
    __syncthreads();

    // gather [src|dst|e] as float4 (80 float4 per edge); row stride 320f = 1280B (16B mult)
    for (int idx = tid; idx < 32 * 80; idx += 256) {
        int e = idx / 80, j = idx % 80;
        float4 v;
        if (j < 32)      v = ((const float4*)g_h)[(size_t)sfrom[e] * 32 + j];
        else if (j < 64) v = ((const float4*)g_h)[(size_t)sto[e] * 32 + (j - 32)];
        else             v = ((const float4*)g_e)[(size_t)(e0 + e) * 16 + (j - 64)];
        *((float4*)(xs + e * 320 + j * 4)) = v;
    }
    __syncthreads();

    int c0  = (tid & 63) * 4;    // hidden col group (256 cols)
    int eg  = (tid >> 6) * 8;    // 8 edges per thread (hidden)
    int d0  = (tid & 31) * 4;    // out col group (128 cols)
    int eg2 = (tid >> 5) * 4;    // 4 edges per thread (out)

#pragma unroll
    for (int pass = 0; pass < 2; pass++) {
        const float* W1 = pass ? rw1 : mw1;
        const float* B1 = pass ? rb1 : mb1;
        const float* W2 = pass ? rw2 : mw2;
        const float* B2 = pass ? rb2 : mb2;

        float acc[8][4];
        {
            float4 bb = *(const float4*)(B1 + c0);
#pragma unroll
            for (int i = 0; i < 8; i++) { acc[i][0] = bb.x; acc[i][1] = bb.y; acc[i][2] = bb.z; acc[i][3] = bb.w; }
        }
#pragma unroll 4
        for (int k = 0; k < 320; k++) {
            int xk = pass ? ((k < 256) ? (k ^ 128) : k) : k;
            float4 w = *(const float4*)(W1 + k * 256 + c0);
#pragma unroll
            for (int i = 0; i < 8; i++) {
                float x = xs[(eg + i) * 320 + xk];
                acc[i][0] += x * w.x; acc[i][1] += x * w.y;
                acc[i][2] += x * w.z; acc[i][3] += x * w.w;
            }
        }
        __syncthreads();  // previous pass's hs readers are done
#pragma unroll
        for (int i = 0; i < 8; i++) {
            float4 r;
            r.x = fmaxf(acc[i][0], 0.f); r.y = fmaxf(acc[i][1], 0.f);
            r.z = fmaxf(acc[i][2], 0.f); r.w = fmaxf(acc[i][3], 0.f);
            *((float4*)(hs + (eg + i) * 256 + c0)) = r;
        }
        __syncthreads();

        float acc2[4][4];
        {
            float4 bb = *(const float4*)(B2 + d0);
#pragma unroll
            for (int i = 0; i < 4; i++) { acc2[i][0] = bb.x; acc2[i][1] = bb.y; acc2[i][2] = bb.z; acc2[i][3] = bb.w; }
        }
#pragma unroll 4
        for (int k = 0; k < 256; k++) {
            float4 w = *(const float4*)(W2 + k * 128 + d0);
#pragma unroll
            for (int i = 0; i < 4; i++) {
                float x = hs[(eg2 + i) * 256 + k];
                acc2[i][0] += x * w.x; acc2[i][1] += x * w.y;
                acc2[i][2] += x * w.z; acc2[i][3] += x * w.w;
            }
        }
        const int* tgt = pass ? sfrom : sto;
#pragma unroll
        for (int i = 0; i < 4; i++) {
            float* p = g_agg + (size_t)tgt[eg2 + i] * 128 + d0;
            atomicAdd(p + 0, acc2[i][0]);
            atomicAdd(p + 1, acc2[i][1]);
            atomicAdd(p + 2, acc2[i][2]);
            atomicAdd(p + 3, acc2[i][3]);
        }
        __syncthreads();
    }
}

// -------- node update: h += mlp2([agg, h]) --------
__global__ __launch_bounds__(256) void node_upd_kernel(
    const float* __restrict__ w1, const float* __restrict__ b1,
    const float* __restrict__ w2, const float* __restrict__ b2)
{
    extern __shared__ float sm[];
    float* xs = sm;              // [32][256]
    float* hs = sm + 32 * 256;   // [32][256]
    int tid = threadIdx.x;
    int n0 = blockIdx.x * 32;
    for (int idx = tid; idx < 32 * 64; idx += 256) {
        int r = idx >> 6, j = idx & 63;
        float4 v = (j < 32) ? ((const float4*)g_agg)[(size_t)(n0 + r) * 32 + j]
                            : ((const float4*)g_h)[(size_t)(n0 + r) * 32 + (j - 32)];
        *((float4*)(xs + r * 256 + j * 4)) = v;
    }
    __syncthreads();

    int c0 = (tid & 63) * 4;
    int eg = (tid >> 6) * 8;
    float acc[8][4];
    {
        float4 bb = *(const float4*)(b1 + c0);
#pragma unroll
        for (int i = 0; i < 8; i++) { acc[i][0] = bb.x; acc[i][1] = bb.y; acc[i][2] = bb.z; acc[i][3] = bb.w; }
    }
#pragma unroll 4
    for (int k = 0; k < 256; k++) {
        float4 w = *(const float4*)(w1 + k * 256 + c0);
#pragma unroll
        for (int i = 0; i < 8; i++) {
            float x = xs[(eg + i) * 256 + k];
            acc[i][0] += x * w.x; acc[i][1] += x * w.y;
            acc[i][2] += x * w.z; acc[i][3] += x * w.w;
        }
    }
#pragma unroll
    for (int i = 0; i < 8; i++) {
        float4 r;
        r.x = fmaxf(acc[i][0], 0.f); r.y = fmaxf(acc[i][1], 0.f);
        r.z = fmaxf(acc[i][2], 0.f); r.w = fmaxf(acc[i][3], 0.f);
        *((float4*)(hs + (eg + i) * 256 + c0)) = r;
    }
    __syncthreads();

    int d0 = (tid & 31) * 4;
    int eg2 = (tid >> 5) * 4;
    float acc2[4][4];
    {
        float4 bb = *(const float4*)(b2 + d0);
#pragma unroll
        for (int i = 0; i < 4; i++) { acc2[i][0] = bb.x; acc2[i][1] = bb.y; acc2[i][2] = bb.z; acc2[i][3] = bb.w; }
    }
#pragma unroll 4
    for (int k = 0; k < 256; k++) {
        float4 w = *(const float4*)(w2 + k * 128 + d0);
#pragma unroll
        for (int i = 0; i < 4; i++) {
            float x = hs[(eg2 + i) * 256 + k];
            acc2[i][0] += x * w.x; acc2[i][1] += x * w.y;
            acc2[i][2] += x * w.z; acc2[i][3] += x * w.w;
        }
    }
#pragma unroll
    for (int i = 0; i < 4; i++) {
        float4* p = (float4*)(g_h + (size_t)(n0 + eg2 + i) * 128 + d0);
        float4 hv = *p;
        hv.x += acc2[i][0]; hv.y += acc2[i][1]; hv.z += acc2[i][2]; hv.w += acc2[i][3];
        *p = hv;
    }
}

// -------- t = mlp2(h; fc1, fc2) --------
__global__ __launch_bounds__(256) void t_kernel(
    const float* __restrict__ w1, const float* __restrict__ b1,
    const float* __restrict__ w2, const float* __restrict__ b2)
{
    extern __shared__ float sm[];
    float* xs = sm;              // [32][128]
    float* hs = sm + 32 * 128;   // [32][128]
    int tid = threadIdx.x;
    int n0 = blockIdx.x * 32;
    for (int idx = tid; idx < 32 * 32; idx += 256) {
        int r = idx >> 5, j = idx & 31;
        *((float4*)(xs + r * 128 + j * 4)) = ((const float4*)g_h)[(size_t)(n0 + r) * 32 + j];
    }
    __syncthreads();

    int c0 = (tid & 31) * 4;
    int eg = (tid >> 5) * 4;
    float acc[4][4];
    {
        float4 bb = *(const float4*)(b1 + c0);
#pragma unroll
        for (int i = 0; i < 4; i++) { acc[i][0] = bb.x; acc[i][1] = bb.y; acc[i][2] = bb.z; acc[i][3] = bb.w; }
    }
#pragma unroll 4
    for (int k = 0; k < 128; k++) {
        float4 w = *(const float4*)(w1 + k * 128 + c0);
#pragma unroll
        for (int i = 0; i < 4; i++) {
            float x = xs[(eg + i) * 128 + k];
            acc[i][0] += x * w.x; acc[i][1] += x * w.y;
            acc[i][2] += x * w.z; acc[i][3] += x * w.w;
        }
    }
#pragma unroll
    for (int i = 0; i < 4; i++) {
        float4 r;
        r.x = fmaxf(acc[i][0], 0.f); r.y = fmaxf(acc[i][1], 0.f);
        r.z = fmaxf(acc[i][2], 0.f); r.w = fmaxf(acc[i][3], 0.f);
        *((float4*)(hs + (eg + i) * 128 + c0)) = r;
    }
    __syncthreads();

    float acc2[4][4];
    {
        float4 bb = *(const float4*)(b2 + c0);
#pragma unroll
        for (int i = 0; i < 4; i++) { acc2[i][0] = bb.x; acc2[i][1] = bb.y; acc2[i][2] = bb.z; acc2[i][3] = bb.w; }
    }
#pragma unroll 4
    for (int k = 0; k < 128; k++) {
        float4 w = *(const float4*)(w2 + k * 128 + c0);
#pragma unroll
        for (int i = 0; i < 4; i++) {
            float x = hs[(eg + i) * 128 + k];
            acc2[i][0] += x * w.x; acc2[i][1] += x * w.y;
            acc2[i][2] += x * w.z; acc2[i][3] += x * w.w;
        }
    }
#pragma unroll
    for (int i = 0; i < 4; i++) {
        float4 r = make_float4(acc2[i][0], acc2[i][1], acc2[i][2], acc2[i][3]);
        *((float4*)(g_t + (size_t)(n0 + eg + i) * 128 + c0)) = r;
    }
}

// -------- per-pair: log_alpha GEMM, Sinkhorn(20), plan@sc, relu score --------
__global__ __launch_bounds__(256) void pair_kernel(
    const int* __restrict__ qsizes, const int* __restrict__ csizes,
    float* __restrict__ out)
{
    extern __shared__ float sm[];
    const int LD = 129;
    float* A = sm;                // [128][129] log_alpha / plan
    float* U = sm + 128 * LD;     // [128][129]
    float* V = sm + 2 * 128 * LD; // [128][129]
    __shared__ float red[8];
    int tid = threadIdx.x;
    int b = blockIdx.x;
    int qs = g_qstart[b], cs = g_cstart[b];
    int qn = qsizes[b],  cn = csizes[b];

    // load masked transformed states (scalar smem stores: LD=129 rows are not 16B-aligned)
    for (int idx = tid; idx < 128 * 32; idx += 256) {
        int r = idx >> 5, j = idx & 31;
        float4 z = make_float4(0.f, 0.f, 0.f, 0.f);
        float4 u = (r < qn) ? ((const float4*)g_t)[(size_t)(qs + r) * 32 + j] : z;
        float4 v = (r < cn) ? ((const float4*)g_t)[(size_t)(cs + r) * 32 + j] : z;
        float* pu = U + r * LD + j * 4;
        float* pv = V + r * LD + j * 4;
        pu[0] = u.x; pu[1] = u.y; pu[2] = u.z; pu[3] = u.w;
        pv[0] = v.x; pv[1] = v.y; pv[2] = v.z; pv[3] = v.w;
    }
    __syncthreads();

    int q0 = (tid >> 4) * 8, c0 = (tid & 15) * 8;
    {
        float acc[8][8];
#pragma unroll
        for (int i = 0; i < 8; i++)
#pragma unroll
            for (int j = 0; j < 8; j++) acc[i][j] = 0.f;
        for (int d = 0; d < 128; d++) {
            float uq[8], vc[8];
#pragma unroll
            for (int i = 0; i < 8; i++) uq[i] = U[(q0 + i) * LD + d];
#pragma unroll
            for (int j = 0; j < 8; j++) vc[j] = V[(c0 + j) * LD + d];
#pragma unroll
            for (int i = 0; i < 8; i++)
#pragma unroll
                for (int j = 0; j < 8; j++) acc[i][j] += uq[i] * vc[j];
        }
#pragma unroll
        for (int i = 0; i < 8; i++)
#pragma unroll
            for (int j = 0; j < 8; j++) A[(q0 + i) * LD + c0 + j] = acc[i][j] * 10.0f;
    }
    __syncthreads();

    int warp = tid >> 5, lane = tid & 31;
    for (int it = 0; it < 20; it++) {
        // logsumexp over columns (axis=2), per row
        for (int r = warp; r < 128; r += 8) {
            float v0 = A[r * LD + lane],      v1 = A[r * LD + lane + 32];
            float v2 = A[r * LD + lane + 64], v3 = A[r * LD + lane + 96];
            float m = fmaxf(fmaxf(v0, v1), fmaxf(v2, v3));
#pragma unroll
            for (int o = 16; o > 0; o >>= 1) m = fmaxf(m, __shfl_xor_sync(0xffffffffu, m, o));
            float s = __expf(v0 - m) + __expf(v1 - m) + __expf(v2 - m) + __expf(v3 - m);
#pragma unroll
            for (int o = 16; o > 0; o >>= 1) s += __shfl_xor_sync(0xffffffffu, s, o);
            float lse = m + __logf(s);
            A[r * LD + lane]      = v0 - lse; A[r * LD + lane + 32] = v1 - lse;
            A[r * LD + lane + 64] = v2 - lse; A[r * LD + lane + 96] = v3 - lse;
        }
        __syncthreads();
        // logsumexp over rows (axis=1), per column
        for (int c = warp; c < 128; c += 8) {
            float v0 = A[lane * LD + c],        v1 = A[(lane + 32) * LD + c];
            float v2 = A[(lane + 64) * LD + c], v3 = A[(lane + 96) * LD + c];
            float m = fmaxf(fmaxf(v0, v1), fmaxf(v2, v3));
#pragma unroll
            for (int o = 16; o > 0; o >>= 1) m = fmaxf(m, __shfl_xor_sync(0xffffffffu, m, o));
            float s = __expf(v0 - m) + __expf(v1 - m) + __expf(v2 - m) + __expf(v3 - m);
#pragma unroll
            for (int o = 16; o > 0; o >>= 1) s += __shfl_xor_sync(0xffffffffu, s, o);
            float lse = m + __logf(s);
            A[lane * LD + c]        = v0 - lse; A[(lane + 32) * LD + c] = v1 - lse;
            A[(lane + 64) * LD + c] = v2 - lse; A[(lane + 96) * LD + c] = v3 - lse;
        }
        __syncthreads();
    }

    // plan = exp(log_alpha)
    for (int idx = tid; idx < 128 * 128; idx += 256) {
        int r = idx >> 7, c = idx & 127;
        A[r * LD + c] = __expf(A[r * LD + c]);
    }
    // reload U = stacked_q (h), V = stacked_c (h), masked (scalar smem stores)
    for (int idx = tid; idx < 128 * 32; idx += 256) {
        int r = idx >> 5, j = idx & 31;
        float4 z = make_float4(0.f, 0.f, 0.f, 0.f);
        float4 u = (r < qn) ? ((const float4*)g_h)[(size_t)(qs + r) * 32 + j] : z;
        float4 v = (r < cn) ? ((const float4*)g_h)[(size_t)(cs + r) * 32 + j] : z;
        float* pu = U + r * LD + j * 4;
        float* pv = V + r * LD + j * 4;
        pu[0] = u.x; pu[1] = u.y; pu[2] = u.z; pu[3] = u.w;
        pv[0] = v.x; pv[1] = v.y; pv[2] = v.z; pv[3] = v.w;
    }
    __syncthreads();

    // scores: -sum relu(sq - plan @ sc)
    float local = 0.f;
    {
        int d0 = c0;
        float acc[8][8];
#pragma unroll
        for (int i = 0; i < 8; i++)
#pragma unroll
            for (int j = 0; j < 8; j++) acc[i][j] = 0.f;
        for (int c = 0; c < 128; c++) {
            float pr[8], vv[8];
#pragma unroll
            for (int i = 0; i < 8; i++) pr[i] = A[(q0 + i) * LD + c];
#pragma unroll
            for (int j = 0; j < 8; j++) vv[j] = V[c * LD + d0 + j];
#pragma unroll
            for (int i = 0; i < 8; i++)
#pragma unroll
                for (int j = 0; j < 8; j++) acc[i][j] += pr[i] * vv[j];
        }
#pragma unroll
        for (int i = 0; i < 8; i++)
#pragma unroll
            for (int j = 0; j < 8; j++)
                local += fmaxf(U[(q0 + i) * LD + d0 + j] - acc[i][j], 0.f);
    }
#pragma unroll
    for (int o = 16; o > 0; o >>= 1) local += __shfl_xor_sync(0xffffffffu, local, o);
    if (lane == 0) red[warp] = local;
    __syncthreads();
    if (tid == 0) {
        float tot = 0.f;
#pragma unroll
        for (int w = 0; w < 8; w++) tot += red[w];
        out[b] = -tot;
    }
}

// -------- launch --------
extern "C" void kernel_launch(void* const* d_in, const int* in_sizes, int n_in,
                              void* d_out, int out_size) {
    const float* node_features = (const float*)d_in[0];
    const float* edge_features = (const float*)d_in[1];
    const float* enc_node_w = (const float*)d_in[2];
    const float* enc_node_b = (const float*)d_in[3];
    const float* enc_edge_w = (const float*)d_in[4];
    const float* enc_edge_b = (const float*)d_in[5];
    const float* msg_w1 = (const float*)d_in[6];
    const float* msg_b1 = (const float*)d_in[7];
    const float* msg_w2 = (const float*)d_in[8];
    const float* msg_b2 = (const float*)d_in[9];
    const float* rmsg_w1 = (const float*)d_in[10];
    const float* rmsg_b1 = (const float*)d_in[11];
    const float* rmsg_w2 = (const float*)d_in[12];
    const float* rmsg_b2 = (const float*)d_in[13];
    const float* upd_w1 = (const float*)d_in[14];
    const float* upd_b1 = (const float*)d_in[15];
    const float* upd_w2 = (const float*)d_in[16];
    const float* upd_b2 = (const float*)d_in[17];
    const float* fc1_w = (const float*)d_in[18];
    const float* fc1_b = (const float*)d_in[19];
    const float* fc2_w = (const float*)d_in[20];
    const float* fc2_b = (const float*)d_in[21];
    const int* from_idx = (const int*)d_in[22];
    const int* to_idx = (const int*)d_in[23];
    const int* qsizes = (const int*)d_in[25];
    const int* csizes = (const int*)d_in[26];

    int N = in_sizes[0] / 32;
    int E = in_sizes[1] / 16;
    int B = in_sizes[25];

    int smem_edge = (32 * 320 + 32 * 256) * 4;      // 73984
    int smem_upd  = (32 * 256 * 2) * 4;             // 65536
    int smem_t    = (32 * 128 * 2) * 4;             // 32768
    int smem_pair = 3 * 128 * 129 * 4;              // 198144

    cudaFuncSetAttribute(edge_msg_kernel, cudaFuncAttributeMaxDynamicSharedMemorySize, smem_edge);
    cudaFuncSetAttribute(node_upd_kernel, cudaFuncAttributeMaxDynamicSharedMemorySize, smem_upd);
    cudaFuncSetAttribute(pair_kernel,     cudaFuncAttributeMaxDynamicSharedMemorySize, smem_pair);

    enc_node_kernel<<<(N + 1) / 2, 256>>>(node_features, enc_node_w, enc_node_b, N);
    enc_edge_kernel<<<(E + 3) / 4, 256>>>(edge_features, enc_edge_w, enc_edge_b, E);
    starts_kernel<<<1, 32>>>(qsizes, csizes, B);

    for (int p = 0; p < 5; p++) {
        zero_agg_kernel<<<(N * 32 + 255) / 256, 256>>>(N * 32);
        edge_msg_kernel<<<E / 32, 256, smem_edge>>>(from_idx, to_idx,
            msg_w1, msg_b1, msg_w2, msg_b2, rmsg_w1, rmsg_b1, rmsg_w2, rmsg_b2);
        node_upd_kernel<<<N / 32, 256, smem_upd>>>(upd_w1, upd_b1, upd_w2, upd_b2);
    }
    t_kernel<<<N / 32, 256, smem_t>>>(fc1_w, fc1_b, fc2_w, fc2_b);
    pair_kernel<<<B, 256, smem_pair>>>(qsizes, csizes, (float*)d_out);
}

// round 6
// speedup vs baseline: 2.0630x; 2.0630x over previous
#include <cuda_runtime.h>
#include <cstdint>
#include <math.h>

#define NN 98304
#define NE 786432
#define NB 512

// -------- scratch (device globals; no allocation allowed) --------
__device__ __align__(1024) float g_h[(size_t)NN * 128];
__device__ __align__(1024) float g_e[(size_t)NE * 64];
__device__ __align__(1024) float g_agg[(size_t)NN * 128];
__device__ __align__(1024) float g_t[(size_t)NN * 128];
__device__ __align__(1024) float g_hid[(size_t)NE * 512];
__device__ __align__(1024) float g_w1cat[320 * 512];   // [k][n] msg|rmsg fused
__device__ __align__(1024) float g_b1cat[512];
__device__ int g_qstart[NB];
__device__ int g_cstart[NB];

// -------- mma.sync helpers (sm_80+ PTX, works on plain sm_103 target) --------
__device__ __forceinline__ uint32_t f2tf32(float v) {
    uint32_t r;
    asm("cvt.rna.tf32.f32 %0, %1;" : "=r"(r) : "f"(v));
    return r;
}
__device__ __forceinline__ void mma_tf32(float c[4],
    uint32_t a0, uint32_t a1, uint32_t a2, uint32_t a3, uint32_t b0, uint32_t b1)
{
    asm volatile(
        "mma.sync.aligned.m16n8k8.row.col.f32.tf32.tf32.f32 "
        "{%0,%1,%2,%3}, {%4,%5,%6,%7}, {%8,%9}, {%0,%1,%2,%3};"
        : "+f"(c[0]), "+f"(c[1]), "+f"(c[2]), "+f"(c[3])
        : "r"(a0), "r"(a1), "r"(a2), "r"(a3), "r"(b0), "r"(b1));
}

#define LDA 36    // 128x32 A chunk, padded row (conflict-free frag loads)
#define LDB 132   // 32x128 B chunk, padded row
// dynamic smem layout (bytes):
//  sA:  [0, 36864)          2 x 128*36 u32
//  sB:  [36864, 70656)      2 x 32*132 u32
//  idx0:[70656, 71168)      128 ints
//  idx1:[71168, 71680)      128 ints
#define GEMM_SMEM 71680

// -------- prep: fuse msg/rmsg W1 into [320][512] (rmsg k-swap folded) --------
__global__ void prep_weights(
    const float* __restrict__ mw1, const float* __restrict__ rw1,
    const float* __restrict__ mb1, const float* __restrict__ rb1)
{
    int i = blockIdx.x * 256 + threadIdx.x;
    int stride = gridDim.x * 256;
    for (int idx = i; idx < 320 * 512; idx += stride) {
        int k = idx / 512, n = idx % 512;
        float v;
        if (n < 256) v = mw1[k * 256 + n];
        else {
            int kp = (k < 256) ? (k ^ 128) : k;
            v = rw1[kp * 256 + (n - 256)];
        }
        g_w1cat[idx] = v;
    }
    for (int idx = i; idx < 512; idx += stride)
        g_b1cat[idx] = (idx < 256) ? mb1[idx] : rb1[idx - 256];
}

// -------- GEMM1: g_hid[e, n0:n0+128] = relu(X[e,:320] @ W1cat + b1cat) --------
__global__ __launch_bounds__(256, 2) void gemm1_kernel(
    const int* __restrict__ fidx, const int* __restrict__ tidx)
{
    extern __shared__ char smc[];
    uint32_t* sA = (uint32_t*)smc;
    uint32_t* sB = (uint32_t*)(smc + 36864);
    int* sfrom = (int*)(smc + 70656);
    int* sto   = (int*)(smc + 71168);
    int tid = threadIdx.x, lane = tid & 31, w = tid >> 5;
    int gid = lane >> 2, tig = lane & 3;
    int e0 = blockIdx.x * 128, n0 = blockIdx.y * 128;
    if (tid < 128) { sfrom[tid] = fidx[e0 + tid]; sto[tid] = tidx[e0 + tid]; }
    __syncthreads();

    int m0 = (w >> 1) * 32, nw0 = (w & 1) * 64;
    float C[2][8][4];
#pragma unroll
    for (int mt = 0; mt < 2; mt++)
#pragma unroll
        for (int nt = 0; nt < 8; nt++)
#pragma unroll
            for (int q = 0; q < 4; q++) C[mt][nt][q] = 0.f;

#define STAGE1(c, buf) do { \
    uint32_t* A_ = sA + (buf) * 128 * LDA; \
    uint32_t* B_ = sB + (buf) * 32 * LDB; \
    _Pragma("unroll") \
    for (int t = 0; t < 4; t++) { \
        int f = tid + t * 256; int r = f >> 3, j = f & 7; \
        const float* src; \
        if ((c) < 4)      src = g_h + (size_t)sfrom[r] * 128 + (c) * 32 + j * 4; \
        else if ((c) < 8) src = g_h + (size_t)sto[r] * 128 + ((c) - 4) * 32 + j * 4; \
        else              src = g_e + (size_t)(e0 + r) * 64 + ((c) - 8) * 32 + j * 4; \
        float4 v = *(const float4*)src; \
        uint4 u; u.x = f2tf32(v.x); u.y = f2tf32(v.y); u.z = f2tf32(v.z); u.w = f2tf32(v.w); \
        *(uint4*)(A_ + r * LDA + j * 4) = u; \
    } \
    _Pragma("unroll") \
    for (int t = 0; t < 4; t++) { \
        int f = tid + t * 256; int r = f >> 5, j = f & 31; \
        float4 v = *(const float4*)(g_w1cat + (size_t)((c) * 32 + r) * 512 + n0 + j * 4); \
        uint4 u; u.x = f2tf32(v.x); u.y = f2tf32(v.y); u.z = f2tf32(v.z); u.w = f2tf32(v.w); \
        *(uint4*)(B_ + r * LDB + j * 4) = u; \
    } \
} while (0)

    STAGE1(0, 0);
    __syncthreads();
    for (int c = 0; c < 10; c++) {
        if (c < 9) STAGE1(c + 1, (c + 1) & 1);
        uint32_t* A = sA + (c & 1) * 128 * LDA;
        uint32_t* B = sB + (c & 1) * 32 * LDB;
#pragma unroll
        for (int ks = 0; ks < 4; ks++) {
            int k = ks * 8;
            uint32_t a[2][4], b[8][2];
#pragma unroll
            for (int mt = 0; mt < 2; mt++) {
                int rb = m0 + mt * 16;
                a[mt][0] = A[(rb + gid) * LDA + k + tig];
                a[mt][1] = A[(rb + gid + 8) * LDA + k + tig];
                a[mt][2] = A[(rb + gid) * LDA + k + tig + 4];
                a[mt][3] = A[(rb + gid + 8) * LDA + k + tig + 4];
            }
#pragma unroll
            for (int nt = 0; nt < 8; nt++) {
                int col = nw0 + nt * 8 + gid;
                b[nt][0] = B[(k + tig) * LDB + col];
                b[nt][1] = B[(k + tig + 4) * LDB + col];
            }
#pragma unroll
            for (int mt = 0; mt < 2; mt++)
#pragma unroll
                for (int nt = 0; nt < 8; nt++)
                    mma_tf32(C[mt][nt], a[mt][0], a[mt][1], a[mt][2], a[mt][3],
                             b[nt][0], b[nt][1]);
        }
        __syncthreads();
    }

    // epilogue: bias + relu -> g_hid
#pragma unroll
    for (int mt = 0; mt < 2; mt++) {
        int r0 = m0 + mt * 16 + gid;
#pragma unroll
        for (int nt = 0; nt < 8; nt++) {
            int cl = nw0 + nt * 8 + 2 * tig;
            float b0v = g_b1cat[n0 + cl], b1v = g_b1cat[n0 + cl + 1];
            float2 o;
            o.x = fmaxf(C[mt][nt][0] + b0v, 0.f);
            o.y = fmaxf(C[mt][nt][1] + b1v, 0.f);
            *(float2*)(g_hid + (size_t)(e0 + r0) * 512 + n0 + cl) = o;
            o.x = fmaxf(C[mt][nt][2] + b0v, 0.f);
            o.y = fmaxf(C[mt][nt][3] + b1v, 0.f);
            *(float2*)(g_hid + (size_t)(e0 + r0 + 8) * 512 + n0 + cl) = o;
        }
    }
#undef STAGE1
}

// -------- GEMM2: agg[idx[e]] += H[e, ao:ao+256] @ W2 + b2 --------
__global__ __launch_bounds__(256, 2) void gemm2_kernel(
    const float* __restrict__ W2, const float* __restrict__ bias,
    const int* __restrict__ idx, int ao)
{
    extern __shared__ char smc[];
    uint32_t* sA = (uint32_t*)smc;
    uint32_t* sB = (uint32_t*)(smc + 36864);
    int* sidx = (int*)(smc + 70656);
    int tid = threadIdx.x, lane = tid & 31, w = tid >> 5;
    int gid = lane >> 2, tig = lane & 3;
    int e0 = blockIdx.x * 128;
    if (tid < 128) sidx[tid] = idx[e0 + tid];
    __syncthreads();

    int m0 = (w >> 1) * 32, nw0 = (w & 1) * 64;
    float C[2][8][4];
#pragma unroll
    for (int mt = 0; mt < 2; mt++)
#pragma unroll
        for (int nt = 0; nt < 8; nt++)
#pragma unroll
            for (int q = 0; q < 4; q++) C[mt][nt][q] = 0.f;

#define STAGE2(c, buf) do { \
    uint32_t* A_ = sA + (buf) * 128 * LDA; \
    uint32_t* B_ = sB + (buf) * 32 * LDB; \
    _Pragma("unroll") \
    for (int t = 0; t < 4; t++) { \
        int f = tid + t * 256; int r = f >> 3, j = f & 7; \
        float4 v = *(const float4*)(g_hid + (size_t)(e0 + r) * 512 + ao + (c) * 32 + j * 4); \
        uint4 u; u.x = f2tf32(v.x); u.y = f2tf32(v.y); u.z = f2tf32(v.z); u.w = f2tf32(v.w); \
        *(uint4*)(A_ + r * LDA + j * 4) = u; \
    } \
    _Pragma("unroll") \
    for (int t = 0; t < 4; t++) { \
        int f = tid + t * 256; int r = f >> 5, j = f & 31; \
        float4 v = *(const float4*)(W2 + (size_t)((c) * 32 + r) * 128 + j * 4); \
        uint4 u; u.x = f2tf32(v.x); u.y = f2tf32(v.y); u.z = f2tf32(v.z); u.w = f2tf32(v.w); \
        *(uint4*)(B_ + r * LDB + j * 4) = u; \
    } \
} while (0)

    STAGE2(0, 0);
    __syncthreads();
    for (int c = 0; c < 8; c++) {
        if (c < 7) STAGE2(c + 1, (c + 1) & 1);
        uint32_t* A = sA + (c & 1) * 128 * LDA;
        uint32_t* B = sB + (c & 1) * 32 * LDB;
#pragma unroll
        for (int ks = 0; ks < 4; ks++) {
            int k = ks * 8;
            uint32_t a[2][4], b[8][2];
#pragma unroll
            for (int mt = 0; mt < 2; mt++) {
                int rb = m0 + mt * 16;
                a[mt][0] = A[(rb + gid) * LDA + k + tig];
                a[mt][1] = A[(rb + gid + 8) * LDA + k + tig];
                a[mt][2] = A[(rb + gid) * LDA + k + tig + 4];
                a[mt][3] = A[(rb + gid + 8) * LDA + k + tig + 4];
            }
#pragma unroll
            for (int nt = 0; nt < 8; nt++) {
                int col = nw0 + nt * 8 + gid;
                b[nt][0] = B[(k + tig) * LDB + col];
                b[nt][1] = B[(k + tig + 4) * LDB + col];
            }
#pragma unroll
            for (int mt = 0; mt < 2; mt++)
#pragma unroll
                for (int nt = 0; nt < 8; nt++)
                    mma_tf32(C[mt][nt], a[mt][0], a[mt][1], a[mt][2], a[mt][3],
                             b[nt][0], b[nt][1]);
        }
        __syncthreads();
    }

    // epilogue: bias + atomic scatter into g_agg
#pragma unroll
    for (int mt = 0; mt < 2; mt++) {
        int r0 = m0 + mt * 16 + gid;
        float* p0 = g_agg + (size_t)sidx[r0] * 128;
        float* p1 = g_agg + (size_t)sidx[r0 + 8] * 128;
#pragma unroll
        for (int nt = 0; nt < 8; nt++) {
            int cl = nw0 + nt * 8 + 2 * tig;
            float b0v = bias[cl], b1v = bias[cl + 1];
            atomicAdd(p0 + cl,     C[mt][nt][0] + b0v);
            atomicAdd(p0 + cl + 1, C[mt][nt][1] + b1v);
            atomicAdd(p1 + cl,     C[mt][nt][2] + b0v);
            atomicAdd(p1 + cl + 1, C[mt][nt][3] + b1v);
        }
    }
#undef STAGE2
}

// -------- zero agg --------
__global__ void zero_agg_kernel(int n4) {
    int i = blockIdx.x * 256 + threadIdx.x;
    if (i < n4) ((float4*)g_agg)[i] = make_float4(0.f, 0.f, 0.f, 0.f);
}

// -------- per-pair start offsets --------
__global__ void starts_kernel(const int* __restrict__ qs, const int* __restrict__ cs, int nb) {
    if (blockIdx.x == 0 && threadIdx.x == 0) {
        int s = 0;
        for (int b = 0; b < nb; b++) {
            g_qstart[b] = s; s += qs[b];
            g_cstart[b] = s; s += cs[b];
        }
    }
}

// -------- node encoder --------
__global__ __launch_bounds__(256) void enc_node_kernel(
    const float* __restrict__ nf, const float* __restrict__ W,
    const float* __restrict__ bias, int n)
{
    __shared__ float s_nf[2][32];
    int tid = threadIdx.x;
    int local = tid >> 7;
    int c = tid & 127;
    int node = blockIdx.x * 2 + local;
    if (tid < 64) {
        int e = tid >> 5, k = tid & 31;
        int nn = blockIdx.x * 2 + e;
        s_nf[e][k] = (nn < n) ? nf[(size_t)nn * 32 + k] : 0.f;
    }
    __syncthreads();
    if (node >= n) return;
    float acc = bias[c];
#pragma unroll
    for (int k = 0; k < 32; k++) acc += s_nf[local][k] * W[k * 128 + c];
    g_h[(size_t)node * 128 + c] = acc;
}

// -------- edge encoder --------
__global__ __launch_bounds__(256) void enc_edge_kernel(
    const float* __restrict__ ef, const float* __restrict__ W,
    const float* __restrict__ bias, int ne)
{
    __shared__ float s_ef[4][16];
    int tid = threadIdx.x;
    int le = tid >> 6;
    int c = tid & 63;
    int e = blockIdx.x * 4 + le;
    if (tid < 64) {
        int ee = tid >> 4, k = tid & 15;
        int eg = blockIdx.x * 4 + ee;
        s_ef[ee][k] = (eg < ne) ? ef[(size_t)eg * 16 + k] : 0.f;
    }
    __syncthreads();
    if (e >= ne) return;
    float acc = bias[c];
#pragma unroll
    for (int k = 0; k < 16; k++) acc += s_ef[le][k] * W[k * 64 + c];
    g_e[(size_t)e * 64 + c] = acc;
}

// -------- node update: h += mlp2([agg, h]) (fp32) --------
__global__ __launch_bounds__(256) void node_upd_kernel(
    const float* __restrict__ w1, const float* __restrict__ b1,
    const float* __restrict__ w2, const float* __restrict__ b2)
{
    extern __shared__ float sm[];
    float* xs = sm;              // [32][256]
    float* hs = sm + 32 * 256;   // [32][256]
    int tid = threadIdx.x;
    int n0 = blockIdx.x * 32;
    for (int idx = tid; idx < 32 * 64; idx += 256) {
        int r = idx >> 6, j = idx & 63;
        float4 v = (j < 32) ? ((const float4*)g_agg)[(size_t)(n0 + r) * 32 + j]
                            : ((const float4*)g_h)[(size_t)(n0 + r) * 32 + (j - 32)];
        *((float4*)(xs + r * 256 + j * 4)) = v;
    }
    __syncthreads();

    int c0 = (tid & 63) * 4;
    int eg = (tid >> 6) * 8;
    float acc[8][4];
    {
        float4 bb = *(const float4*)(b1 + c0);
#pragma unroll
        for (int i = 0; i < 8; i++) { acc[i][0] = bb.x; acc[i][1] = bb.y; acc[i][2] = bb.z; acc[i][3] = bb.w; }
    }
#pragma unroll 4
    for (int k = 0; k < 256; k++) {
        float4 w = *(const float4*)(w1 + k * 256 + c0);
#pragma unroll
        for (int i = 0; i < 8; i++) {
            float x = xs[(eg + i) * 256 + k];
            acc[i][0] += x * w.x; acc[i][1] += x * w.y;
            acc[i][2] += x * w.z; acc[i][3] += x * w.w;
        }
    }
#pragma unroll
    for (int i = 0; i < 8; i++) {
        float4 r;
        r.x = fmaxf(acc[i][0], 0.f); r.y = fmaxf(acc[i][1], 0.f);
        r.z = fmaxf(acc[i][2], 0.f); r.w = fmaxf(acc[i][3], 0.f);
        *((float4*)(hs + (eg + i) * 256 + c0)) = r;
    }
    __syncthreads();

    int d0 = (tid & 31) * 4;
    int eg2 = (tid >> 5) * 4;
    float acc2[4][4];
    {
        float4 bb = *(const float4*)(b2 + d0);
#pragma unroll
        for (int i = 0; i < 4; i++) { acc2[i][0] = bb.x; acc2[i][1] = bb.y; acc2[i][2] = bb.z; acc2[i][3] = bb.w; }
    }
#pragma unroll 4
    for (int k = 0; k < 256; k++) {
        float4 w = *(const float4*)(w2 + k * 128 + d0);
#pragma unroll
        for (int i = 0; i < 4; i++) {
            float x = hs[(eg2 + i) * 256 + k];
            acc2[i][0] += x * w.x; acc2[i][1] += x * w.y;
            acc2[i][2] += x * w.z; acc2[i][3] += x * w.w;
        }
    }
#pragma unroll
    for (int i = 0; i < 4; i++) {
        float4* p = (float4*)(g_h + (size_t)(n0 + eg2 + i) * 128 + d0);
        float4 hv = *p;
        hv.x += acc2[i][0]; hv.y += acc2[i][1]; hv.z += acc2[i][2]; hv.w += acc2[i][3];
        *p = hv;
    }
}

// -------- t = mlp2(h; fc1, fc2) --------
__global__ __launch_bounds__(256) void t_kernel(
    const float* __restrict__ w1, const float* __restrict__ b1,
    const float* __restrict__ w2, const float* __restrict__ b2)
{
    extern __shared__ float sm[];
    float* xs = sm;              // [32][128]
    float* hs = sm + 32 * 128;   // [32][128]
    int tid = threadIdx.x;
    int n0 = blockIdx.x * 32;
    for (int idx = tid; idx < 32 * 32; idx += 256) {
        int r = idx >> 5, j = idx & 31;
        *((float4*)(xs + r * 128 + j * 4)) = ((const float4*)g_h)[(size_t)(n0 + r) * 32 + j];
    }
    __syncthreads();

    int c0 = (tid & 31) * 4;
    int eg = (tid >> 5) * 4;
    float acc[4][4];
    {
        float4 bb = *(const float4*)(b1 + c0);
#pragma unroll
        for (int i = 0; i < 4; i++) { acc[i][0] = bb.x; acc[i][1] = bb.y; acc[i][2] = bb.z; acc[i][3] = bb.w; }
    }
#pragma unroll 4
    for (int k = 0; k < 128; k++) {
        float4 w = *(const float4*)(w1 + k * 128 + c0);
#pragma unroll
        for (int i = 0; i < 4; i++) {
            float x = xs[(eg + i) * 128 + k];
            acc[i][0] += x * w.x; acc[i][1] += x * w.y;
            acc[i][2] += x * w.z; acc[i][3] += x * w.w;
        }
    }
#pragma unroll
    for (int i = 0; i < 4; i++) {
        float4 r;
        r.x = fmaxf(acc[i][0], 0.f); r.y = fmaxf(acc[i][1], 0.f);
        r.z = fmaxf(acc[i][2], 0.f); r.w = fmaxf(acc[i][3], 0.f);
        *((float4*)(hs + (eg + i) * 128 + c0)) = r;
    }
    __syncthreads();

    float acc2[4][4];
    {
        float4 bb = *(const float4*)(b2 + c0);
#pragma unroll
        for (int i = 0; i < 4; i++) { acc2[i][0] = bb.x; acc2[i][1] = bb.y; acc2[i][2] = bb.z; acc2[i][3] = bb.w; }
    }
#pragma unroll 4
    for (int k = 0; k < 128; k++) {
        float4 w = *(const float4*)(w2 + k * 128 + c0);
#pragma unroll
        for (int i = 0; i < 4; i++) {
            float x = hs[(eg + i) * 128 + k];
            acc2[i][0] += x * w.x; acc2[i][1] += x * w.y;
            acc2[i][2] += x * w.z; acc2[i][3] += x * w.w;
        }
    }
#pragma unroll
    for (int i = 0; i < 4; i++) {
        float4 r = make_float4(acc2[i][0], acc2[i][1], acc2[i][2], acc2[i][3]);
        *((float4*)(g_t + (size_t)(n0 + eg + i) * 128 + c0)) = r;
    }
}

// -------- per-pair: log_alpha GEMM, Sinkhorn(20), plan@sc, relu score --------
__global__ __launch_bounds__(256) void pair_kernel(
    const int* __restrict__ qsizes, const int* __restrict__ csizes,
    float* __restrict__ out)
{
    extern __shared__ float sm[];
    const int LD = 129;
    float* A = sm;
    float* U = sm + 128 * LD;
    float* V = sm + 2 * 128 * LD;
    __shared__ float red[8];
    int tid = threadIdx.x;
    int b = blockIdx.x;
    int qs = g_qstart[b], cs = g_cstart[b];
    int qn = qsizes[b],  cn = csizes[b];

    for (int idx = tid; idx < 128 * 32; idx += 256) {
        int r = idx >> 5, j = idx & 31;
        float4 z = make_float4(0.f, 0.f, 0.f, 0.f);
        float4 u = (r < qn) ? ((const float4*)g_t)[(size_t)(qs + r) * 32 + j] : z;
        float4 v = (r < cn) ? ((const float4*)g_t)[(size_t)(cs + r) * 32 + j] : z;
        float* pu = U + r * LD + j * 4;
        float* pv = V + r * LD + j * 4;
        pu[0] = u.x; pu[1] = u.y; pu[2] = u.z; pu[3] = u.w;
        pv[0] = v.x; pv[1] = v.y; pv[2] = v.z; pv[3] = v.w;
    }
    __syncthreads();

    int q0 = (tid >> 4) * 8, c0 = (tid & 15) * 8;
    {
        float acc[8][8];
#pragma unroll
        for (int i = 0; i < 8; i++)
#pragma unroll
            for (int j = 0; j < 8; j++) acc[i][j] = 0.f;
        for (int d = 0; d < 128; d++) {
            float uq[8], vc[8];
#pragma unroll
            for (int i = 0; i < 8; i++) uq[i] = U[(q0 + i) * LD + d];
#pragma unroll
            for (int j = 0; j < 8; j++) vc[j] = V[(c0 + j) * LD + d];
#pragma unroll
            for (int i = 0; i < 8; i++)
#pragma unroll
                for (int j = 0; j < 8; j++) acc[i][j] += uq[i] * vc[j];
        }
#pragma unroll
        for (int i = 0; i < 8; i++)
#pragma unroll
            for (int j = 0; j < 8; j++) A[(q0 + i) * LD + c0 + j] = acc[i][j] * 10.0f;
    }
    __syncthreads();

    int warp = tid >> 5, lane = tid & 31;
    for (int it = 0; it < 20; it++) {
        for (int r = warp; r < 128; r += 8) {
            float v0 = A[r * LD + lane],      v1 = A[r * LD + lane + 32];
            float v2 = A[r * LD + lane + 64], v3 = A[r * LD + lane + 96];
            float m = fmaxf(fmaxf(v0, v1), fmaxf(v2, v3));
#pragma unroll
            for (int o = 16; o > 0; o >>= 1) m = fmaxf(m, __shfl_xor_sync(0xffffffffu, m, o));
            float s = __expf(v0 - m) + __expf(v1 - m) + __expf(v2 - m) + __expf(v3 - m);
#pragma unroll
            for (int o = 16; o > 0; o >>= 1) s += __shfl_xor_sync(0xffffffffu, s, o);
            float lse = m + __logf(s);
            A[r * LD + lane]      = v0 - lse; A[r * LD + lane + 32] = v1 - lse;
            A[r * LD + lane + 64] = v2 - lse; A[r * LD + lane + 96] = v3 - lse;
        }
        __syncthreads();
        for (int c = warp; c < 128; c += 8) {
            float v0 = A[lane * LD + c],        v1 = A[(lane + 32) * LD + c];
            float v2 = A[(lane + 64) * LD + c], v3 = A[(lane + 96) * LD + c];
            float m = fmaxf(fmaxf(v0, v1), fmaxf(v2, v3));
#pragma unroll
            for (int o = 16; o > 0; o >>= 1) m = fmaxf(m, __shfl_xor_sync(0xffffffffu, m, o));
            float s = __expf(v0 - m) + __expf(v1 - m) + __expf(v2 - m) + __expf(v3 - m);
#pragma unroll
            for (int o = 16; o > 0; o >>= 1) s += __shfl_xor_sync(0xffffffffu, s, o);
            float lse = m + __logf(s);
            A[lane * LD + c]        = v0 - lse; A[(lane + 32) * LD + c] = v1 - lse;
            A[(lane + 64) * LD + c] = v2 - lse; A[(lane + 96) * LD + c] = v3 - lse;
        }
        __syncthreads();
    }

    for (int idx = tid; idx < 128 * 128; idx += 256) {
        int r = idx >> 7, c = idx & 127;
        A[r * LD + c] = __expf(A[r * LD + c]);
    }
    for (int idx = tid; idx < 128 * 32; idx += 256) {
        int r = idx >> 5, j = idx & 31;
        float4 z = make_float4(0.f, 0.f, 0.f, 0.f);
        float4 u = (r < qn) ? ((const float4*)g_h)[(size_t)(qs + r) * 32 + j] : z;
        float4 v = (r < cn) ? ((const float4*)g_h)[(size_t)(cs + r) * 32 + j] : z;
        float* pu = U + r * LD + j * 4;
        float* pv = V + r * LD + j * 4;
        pu[0] = u.x; pu[1] = u.y; pu[2] = u.z; pu[3] = u.w;
        pv[0] = v.x; pv[1] = v.y; pv[2] = v.z; pv[3] = v.w;
    }
    __syncthreads();

    float local = 0.f;
    {
        int d0 = c0;
        float acc[8][8];
#pragma unroll
        for (int i = 0; i < 8; i++)
#pragma unroll
            for (int j = 0; j < 8; j++) acc[i][j] = 0.f;
        for (int c = 0; c < 128; c++) {
            float pr[8], vv[8];
#pragma unroll
            for (int i = 0; i < 8; i++) pr[i] = A[(q0 + i) * LD + c];
#pragma unroll
            for (int j = 0; j < 8; j++) vv[j] = V[c * LD + d0 + j];
#pragma unroll
            for (int i = 0; i < 8; i++)
#pragma unroll
                for (int j = 0; j < 8; j++) acc[i][j] += pr[i] * vv[j];
        }
#pragma unroll
        for (int i = 0; i < 8; i++)
#pragma unroll
            for (int j = 0; j < 8; j++)
                local += fmaxf(U[(q0 + i) * LD + d0 + j] - acc[i][j], 0.f);
    }
#pragma unroll
    for (int o = 16; o > 0; o >>= 1) local += __shfl_xor_sync(0xffffffffu, local, o);
    if (lane == 0) red[warp] = local;
    __syncthreads();
    if (tid == 0) {
        float tot = 0.f;
#pragma unroll
        for (int w = 0; w < 8; w++) tot += red[w];
        out[b] = -tot;
    }
}

// -------- launch --------
extern "C" void kernel_launch(void* const* d_in, const int* in_sizes, int n_in,
                              void* d_out, int out_size) {
    const float* node_features = (const float*)d_in[0];
    const float* edge_features = (const float*)d_in[1];
    const float* enc_node_w = (const float*)d_in[2];
    const float* enc_node_b = (const float*)d_in[3];
    const float* enc_edge_w = (const float*)d_in[4];
    const float* enc_edge_b = (const float*)d_in[5];
    const float* msg_w1 = (const float*)d_in[6];
    const float* msg_b1 = (const float*)d_in[7];
    const float* msg_w2 = (const float*)d_in[8];
    const float* msg_b2 = (const float*)d_in[9];
    const float* rmsg_w1 = (const float*)d_in[10];
    const float* rmsg_b1 = (const float*)d_in[11];
    const float* rmsg_w2 = (const float*)d_in[12];
    const float* rmsg_b2 = (const float*)d_in[13];
    const float* upd_w1 = (const float*)d_in[14];
    const float* upd_b1 = (const float*)d_in[15];
    const float* upd_w2 = (const float*)d_in[16];
    const float* upd_b2 = (const float*)d_in[17];
    const float* fc1_w = (const float*)d_in[18];
    const float* fc1_b = (const float*)d_in[19];
    const float* fc2_w = (const float*)d_in[20];
    const float* fc2_b = (const float*)d_in[21];
    const int* from_idx = (const int*)d_in[22];
    const int* to_idx = (const int*)d_in[23];
    const int* qsizes = (const int*)d_in[25];
    const int* csizes = (const int*)d_in[26];

    int N = in_sizes[0] / 32;
    int E = in_sizes[1] / 16;
    int B = in_sizes[25];

    int smem_upd  = (32 * 256 * 2) * 4;
    int smem_t    = (32 * 128 * 2) * 4;
    int smem_pair = 3 * 128 * 129 * 4;

    cudaFuncSetAttribute(gemm1_kernel, cudaFuncAttributeMaxDynamicSharedMemorySize, GEMM_SMEM);
    cudaFuncSetAttribute(gemm2_kernel, cudaFuncAttributeMaxDynamicSharedMemorySize, GEMM_SMEM);
    cudaFuncSetAttribute(node_upd_kernel, cudaFuncAttributeMaxDynamicSharedMemorySize, smem_upd);
    cudaFuncSetAttribute(pair_kernel,     cudaFuncAttributeMaxDynamicSharedMemorySize, smem_pair);

    enc_node_kernel<<<(N + 1) / 2, 256>>>(node_features, enc_node_w, enc_node_b, N);
    enc_edge_kernel<<<(E + 3) / 4, 256>>>(edge_features, enc_edge_w, enc_edge_b, E);
    starts_kernel<<<1, 32>>>(qsizes, csizes, B);
    prep_weights<<<320, 256>>>(msg_w1, rmsg_w1, msg_b1, rmsg_b1);

    dim3 g1(E / 128, 4);
    for (int p = 0; p < 5; p++) {
        zero_agg_kernel<<<(N * 32 + 255) / 256, 256>>>(N * 32);
        gemm1_kernel<<<g1, 256, GEMM_SMEM>>>(from_idx, to_idx);
        gemm2_kernel<<<E / 128, 256, GEMM_SMEM>>>(msg_w2, msg_b2, to_idx, 0);
        gemm2_kernel<<<E / 128, 256, GEMM_SMEM>>>(rmsg_w2, rmsg_b2, from_idx, 256);
        node_upd_kernel<<<N / 32, 256, smem_upd>>>(upd_w1, upd_b1, upd_w2, upd_b2);
    }
    t_kernel<<<N / 32, 256, smem_t>>>(fc1_w, fc1_b, fc2_w, fc2_b);
    pair_kernel<<<B, 256, smem_pair>>>(qsizes, csizes, (float*)d_out);
}

// round 9
// speedup vs baseline: 2.8354x; 1.3744x over previous
#include <cuda_runtime.h>
#include <cstdint>
#include <math.h>

#define NN 98304
#define NE 786432
#define NB 512

// -------- scratch (device globals; no allocation allowed) --------
__device__ __align__(1024) float g_h[(size_t)NN * 128];
__device__ __align__(1024) float g_e[(size_t)NE * 64];
__device__ __align__(1024) float g_agg[(size_t)NN * 128];
__device__ __align__(1024) float g_t[(size_t)NN * 128];
__device__ __align__(1024) uint32_t g_mw1t[320 * 256];  // tf32 bits
__device__ __align__(1024) uint32_t g_rw1t[320 * 256];
__device__ __align__(1024) uint32_t g_mw2t[256 * 128];
__device__ __align__(1024) uint32_t g_rw2t[256 * 128];
__device__ __align__(1024) uint32_t g_uw1t[256 * 256];
__device__ __align__(1024) uint32_t g_uw2t[256 * 128];
__device__ int g_qstart[NB];
__device__ int g_cstart[NB];

// -------- mma.sync helpers --------
__device__ __forceinline__ uint32_t f2tf32(float v) {
    uint32_t r;
    asm("cvt.rna.tf32.f32 %0, %1;" : "=r"(r) : "f"(v));
    return r;
}
__device__ __forceinline__ void mma_tf32(float c[4],
    uint32_t a0, uint32_t a1, uint32_t a2, uint32_t a3, uint32_t b0, uint32_t b1)
{
    asm volatile(
        "mma.sync.aligned.m16n8k8.row.col.f32.tf32.tf32.f32 "
        "{%0,%1,%2,%3}, {%4,%5,%6,%7}, {%8,%9}, {%0,%1,%2,%3};"
        : "+f"(c[0]), "+f"(c[1]), "+f"(c[2]), "+f"(c[3])
        : "r"(a0), "r"(a1), "r"(a2), "r"(a3), "r"(b0), "r"(b1));
}

// smem layout (bytes):
//  sH  [0, 133120)        128 x 260 u32 (tf32 H tile)
//  sA  [133120, 169984)   2 x 128 x 36 u32 (double-buffered A chunk)
//  sB  [169984, 203264)   32 x 260 u32 (B chunk; GEMM2 reuses w/ LDB2=132)
//  s0  [203264, 203776)   128 ints
//  s1  [203776, 204288)   128 ints
#define LDH 260
#define LDA 36
#define LDB1 260
#define LDB2 132
#define SA_OFF 133120
#define SB_OFF 169984
#define SI0_OFF 203264
#define SI1_OFF 203776
#define EDGE_SMEM 204288
#define NODE_SMEM 203264

// -------- prep: convert all GEMM weights to tf32 bits once --------
__global__ void prep_tf32(
    const float* __restrict__ mw1, const float* __restrict__ rw1,
    const float* __restrict__ mw2, const float* __restrict__ rw2,
    const float* __restrict__ uw1, const float* __restrict__ uw2)
{
    int i = blockIdx.x * 256 + threadIdx.x;
    int stride = gridDim.x * 256;
    for (int idx = i; idx < 320 * 256; idx += stride) {
        g_mw1t[idx] = f2tf32(mw1[idx]);
        g_rw1t[idx] = f2tf32(rw1[idx]);
    }
    for (int idx = i; idx < 256 * 256; idx += stride)
        g_uw1t[idx] = f2tf32(uw1[idx]);
    for (int idx = i; idx < 256 * 128; idx += stride) {
        g_mw2t[idx] = f2tf32(mw2[idx]);
        g_rw2t[idx] = f2tf32(rw2[idx]);
        g_uw2t[idx] = f2tf32(uw2[idx]);
    }
}

// ======== fused edge kernel: one half (msg or rmsg) ========
// x = [h[g0] | h[g1] | e]  (g0/g1 chosen by caller), H = relu(x@W1+b1) in smem,
// then agg[g1[e]] += H @ W2 + b2 via atomics.
__global__ __launch_bounds__(256, 1) void edge_fused_kernel(
    const uint32_t* __restrict__ W1t, const float* __restrict__ b1,
    const uint32_t* __restrict__ W2t, const float* __restrict__ b2,
    const int* __restrict__ gidx0, const int* __restrict__ gidx1)
{
    extern __shared__ char smc[];
    uint32_t* sH = (uint32_t*)smc;
    uint32_t* sA = (uint32_t*)(smc + SA_OFF);
    uint32_t* sB = (uint32_t*)(smc + SB_OFF);
    int* s0 = (int*)(smc + SI0_OFF);
    int* s1 = (int*)(smc + SI1_OFF);
    int tid = threadIdx.x, lane = tid & 31, w = tid >> 5;
    int gid = lane >> 2, tig = lane & 3;
    int e0 = blockIdx.x * 128;
    if (tid < 128) { s0[tid] = gidx0[e0 + tid]; s1[tid] = gidx1[e0 + tid]; }
    __syncthreads();

    int m0 = (w >> 1) * 32;
    int nb = (w & 1) * 128;   // GEMM1 n-half
    int nw = (w & 1) * 64;    // GEMM2 n-half

    float C1[2][16][4];
#pragma unroll
    for (int mt = 0; mt < 2; mt++)
#pragma unroll
        for (int nt = 0; nt < 16; nt++)
#pragma unroll
            for (int q = 0; q < 4; q++) C1[mt][nt][q] = 0.f;

    float4 va[4];
    uint4 vb[8];

#define LD_A1(c) do { \
    _Pragma("unroll") \
    for (int t = 0; t < 4; t++) { \
        int f = tid + t * 256; int r = f >> 3, j = f & 7; \
        const float* src; \
        if ((c) < 4)      src = g_h + (size_t)s0[r] * 128 + (c) * 32 + j * 4; \
        else if ((c) < 8) src = g_h + (size_t)s1[r] * 128 + ((c) - 4) * 32 + j * 4; \
        else              src = g_e + (size_t)(e0 + r) * 64 + ((c) - 8) * 32 + j * 4; \
        va[t] = *(const float4*)src; \
    } \
} while (0)
#define ST_A1(buf) do { \
    _Pragma("unroll") \
    for (int t = 0; t < 4; t++) { \
        int f = tid + t * 256; int r = f >> 3, j = f & 7; \
        uint4 u; u.x = f2tf32(va[t].x); u.y = f2tf32(va[t].y); \
        u.z = f2tf32(va[t].z); u.w = f2tf32(va[t].w); \
        *(uint4*)(sA + (buf) * 128 * LDA + r * LDA + j * 4) = u; \
    } \
} while (0)
#define LD_B1(c) do { \
    _Pragma("unroll") \
    for (int t = 0; t < 8; t++) { \
        int f = tid + t * 256; int r = f >> 6, j = f & 63; \
        vb[t] = ((const uint4*)(W1t + (size_t)((c) * 32 + r) * 256))[j]; \
    } \
} while (0)
#define ST_B1() do { \
    _Pragma("unroll") \
    for (int t = 0; t < 8; t++) { \
        int f = tid + t * 256; int r = f >> 6, j = f & 63; \
        *(uint4*)(sB + r * LDB1 + j * 4) = vb[t]; \
    } \
} while (0)
#define COMPUTE1(buf) do { \
    uint32_t* A = sA + (buf) * 128 * LDA; \
    _Pragma("unroll") \
    for (int ks = 0; ks < 4; ks++) { \
        int k = ks * 8; \
        uint32_t a[2][4], b[16][2]; \
        _Pragma("unroll") \
        for (int mt = 0; mt < 2; mt++) { \
            int rb = m0 + mt * 16; \
            a[mt][0] = A[(rb + gid) * LDA + k + tig]; \
            a[mt][1] = A[(rb + gid + 8) * LDA + k + tig]; \
            a[mt][2] = A[(rb + gid) * LDA + k + tig + 4]; \
            a[mt][3] = A[(rb + gid + 8) * LDA + k + tig + 4]; \
        } \
        _Pragma("unroll") \
        for (int nt = 0; nt < 16; nt++) { \
            int col = nb + nt * 8 + gid; \
            b[nt][0] = sB[(k + tig) * LDB1 + col]; \
            b[nt][1] = sB[(k + tig + 4) * LDB1 + col]; \
        } \
        _Pragma("unroll") \
        for (int mt = 0; mt < 2; mt++) \
            _Pragma("unroll") \
            for (int nt = 0; nt < 16; nt++) \
                mma_tf32(C1[mt][nt], a[mt][0], a[mt][1], a[mt][2], a[mt][3], \
                         b[nt][0], b[nt][1]); \
    } \
} while (0)

    // GEMM1: K=320, 10 chunks of 32
    LD_A1(0); LD_B1(0);
    ST_A1(0); ST_B1();
    __syncthreads();
    for (int c = 0; c < 10; c++) {
        if (c < 9) { LD_A1(c + 1); LD_B1(c + 1); }
        COMPUTE1(c & 1);
        if (c < 9) {
            ST_A1((c + 1) & 1);
            __syncthreads();
            ST_B1();
            __syncthreads();
        }
    }
    __syncthreads();

    // H = relu(C1 + b1) as tf32 bits into sH
#pragma unroll
    for (int mt = 0; mt < 2; mt++) {
        int r0 = m0 + mt * 16 + gid;
#pragma unroll
        for (int nt = 0; nt < 16; nt++) {
            int cl = nb + nt * 8 + 2 * tig;
            float b0v = b1[cl], b1v = b1[cl + 1];
            sH[r0 * LDH + cl]           = f2tf32(fmaxf(C1[mt][nt][0] + b0v, 0.f));
            sH[r0 * LDH + cl + 1]       = f2tf32(fmaxf(C1[mt][nt][1] + b1v, 0.f));
            sH[(r0 + 8) * LDH + cl]     = f2tf32(fmaxf(C1[mt][nt][2] + b0v, 0.f));
            sH[(r0 + 8) * LDH + cl + 1] = f2tf32(fmaxf(C1[mt][nt][3] + b1v, 0.f));
        }
    }
    __syncthreads();

    // GEMM2: K=256 from sH, N=128 (W2), 8 chunks of 32
    float C2[2][8][4];
#pragma unroll
    for (int mt = 0; mt < 2; mt++)
#pragma unroll
        for (int nt = 0; nt < 8; nt++)
#pragma unroll
            for (int q = 0; q < 4; q++) C2[mt][nt][q] = 0.f;

#define LD_B2(c) do { \
    _Pragma("unroll") \
    for (int t = 0; t < 4; t++) { \
        int f = tid + t * 256; int r = f >> 5, j = f & 31; \
        vb[t] = ((const uint4*)(W2t + (size_t)((c) * 32 + r) * 128))[j]; \
    } \
} while (0)
#define ST_B2() do { \
    _Pragma("unroll") \
    for (int t = 0; t < 4; t++) { \
        int f = tid + t * 256; int r = f >> 5, j = f & 31; \
        *(uint4*)(sB + r * LDB2 + j * 4) = vb[t]; \
    } \
} while (0)

    LD_B2(0); ST_B2();
    __syncthreads();
    for (int c = 0; c < 8; c++) {
        if (c < 7) LD_B2(c + 1);
#pragma unroll
        for (int ks = 0; ks < 4; ks++) {
            int kg = c * 32 + ks * 8;   // global k into sH
            int kl = ks * 8;            // local k into sB
            uint32_t a[2][4], b[8][2];
#pragma unroll
            for (int mt = 0; mt < 2; mt++) {
                int rb = m0 + mt * 16;
                a[mt][0] = sH[(rb + gid) * LDH + kg + tig];
                a[mt][1] = sH[(rb + gid + 8) * LDH + kg + tig];
                a[mt][2] = sH[(rb + gid) * LDH + kg + tig + 4];
                a[mt][3] = sH[(rb + gid + 8) * LDH + kg + tig + 4];
            }
#pragma unroll
            for (int nt = 0; nt < 8; nt++) {
                int col = nw + nt * 8 + gid;
                b[nt][0] = sB[(kl + tig) * LDB2 + col];
                b[nt][1] = sB[(kl + tig + 4) * LDB2 + col];
            }
#pragma unroll
            for (int mt = 0; mt < 2; mt++)
#pragma unroll
                for (int nt = 0; nt < 8; nt++)
                    mma_tf32(C2[mt][nt], a[mt][0], a[mt][1], a[mt][2], a[mt][3],
                             b[nt][0], b[nt][1]);
        }
        if (c < 7) {
            __syncthreads();
            ST_B2();
            __syncthreads();
        }
    }

    // epilogue: atomic scatter to g_agg[s1]
#pragma unroll
    for (int mt = 0; mt < 2; mt++) {
        int r0 = m0 + mt * 16 + gid;
        float* p0 = g_agg + (size_t)s1[r0] * 128;
        float* p1 = g_agg + (size_t)s1[r0 + 8] * 128;
#pragma unroll
        for (int nt = 0; nt < 8; nt++) {
            int cl = nw + nt * 8 + 2 * tig;
            float b0v = b2[cl], b1v = b2[cl + 1];
            atomicAdd(p0 + cl,     C2[mt][nt][0] + b0v);
            atomicAdd(p0 + cl + 1, C2[mt][nt][1] + b1v);
            atomicAdd(p1 + cl,     C2[mt][nt][2] + b0v);
            atomicAdd(p1 + cl + 1, C2[mt][nt][3] + b1v);
        }
    }
#undef LD_A1
#undef ST_A1
#undef LD_B1
#undef ST_B1
#undef COMPUTE1
#undef LD_B2
#undef ST_B2
}

// ======== fused node update: h += relu([agg|h]@uw1+b1)@uw2+b2 ========
__global__ __launch_bounds__(256, 1) void node_fused_kernel(
    const float* __restrict__ b1, const float* __restrict__ b2)
{
    extern __shared__ char smc[];
    uint32_t* sH = (uint32_t*)smc;
    uint32_t* sA = (uint32_t*)(smc + SA_OFF);
    uint32_t* sB = (uint32_t*)(smc + SB_OFF);
    int tid = threadIdx.x, lane = tid & 31, w = tid >> 5;
    int gid = lane >> 2, tig = lane & 3;
    int n0 = blockIdx.x * 128;

    int m0 = (w >> 1) * 32;
    int nb = (w & 1) * 128;
    int nw = (w & 1) * 64;

    float C1[2][16][4];
#pragma unroll
    for (int mt = 0; mt < 2; mt++)
#pragma unroll
        for (int nt = 0; nt < 16; nt++)
#pragma unroll
            for (int q = 0; q < 4; q++) C1[mt][nt][q] = 0.f;

    float4 va[4];
    uint4 vb[8];

#define LD_A1N(c) do { \
    _Pragma("unroll") \
    for (int t = 0; t < 4; t++) { \
        int f = tid + t * 256; int r = f >> 3, j = f & 7; \
        const float* src; \
        if ((c) < 4) src = g_agg + (size_t)(n0 + r) * 128 + (c) * 32 + j * 4; \
        else         src = g_h + (size_t)(n0 + r) * 128 + ((c) - 4) * 32 + j * 4; \
        va[t] = *(const float4*)src; \
    } \
} while (0)
#define ST_A1N(buf) do { \
    _Pragma("unroll") \
    for (int t = 0; t < 4; t++) { \
        int f = tid + t * 256; int r = f >> 3, j = f & 7; \
        uint4 u; u.x = f2tf32(va[t].x); u.y = f2tf32(va[t].y); \
        u.z = f2tf32(va[t].z); u.w = f2tf32(va[t].w); \
        *(uint4*)(sA + (buf) * 128 * LDA + r * LDA + j * 4) = u; \
    } \
} while (0)
#define LD_B1N(c) do { \
    _Pragma("unroll") \
    for (int t = 0; t < 8; t++) { \
        int f = tid + t * 256; int r = f >> 6, j = f & 63; \
        vb[t] = ((const uint4*)(g_uw1t + (size_t)((c) * 32 + r) * 256))[j]; \
    } \
} while (0)
#define ST_B1N() do { \
    _Pragma("unroll") \
    for (int t = 0; t < 8; t++) { \
        int f = tid + t * 256; int r = f >> 6, j = f & 63; \
        *(uint4*)(sB + r * LDB1 + j * 4) = vb[t]; \
    } \
} while (0)

    LD_A1N(0); LD_B1N(0);
    ST_A1N(0); ST_B1N();
    __syncthreads();
    for (int c = 0; c < 8; c++) {
        if (c < 7) { LD_A1N(c + 1); LD_B1N(c + 1); }
        {
            uint32_t* A = sA + (c & 1) * 128 * LDA;
#pragma unroll
            for (int ks = 0; ks < 4; ks++) {
                int k = ks * 8;
                uint32_t a[2][4], b[16][2];
#pragma unroll
                for (int mt = 0; mt < 2; mt++) {
                    int rb = m0 + mt * 16;
                    a[mt][0] = A[(rb + gid) * LDA + k + tig];
                    a[mt][1] = A[(rb + gid + 8) * LDA + k + tig];
                    a[mt][2] = A[(rb + gid) * LDA + k + tig + 4];
                    a[mt][3] = A[(rb + gid + 8) * LDA + k + tig + 4];
                }
#pragma unroll
                for (int nt = 0; nt < 16; nt++) {
                    int col = nb + nt * 8 + gid;
                    b[nt][0] = sB[(k + tig) * LDB1 + col];
                    b[nt][1] = sB[(k + tig + 4) * LDB1 + col];
                }
#pragma unroll
                for (int mt = 0; mt < 2; mt++)
#pragma unroll
                    for (int nt = 0; nt < 16; nt++)
                        mma_tf32(C1[mt][nt], a[mt][0], a[mt][1], a[mt][2], a[mt][3],
                                 b[nt][0], b[nt][1]);
            }
        }
        if (c < 7) {
            ST_A1N((c + 1) & 1);
            __syncthreads();
            ST_B1N();
            __syncthreads();
        }
    }
    __syncthreads();

#pragma unroll
    for (int mt = 0; mt < 2; mt++) {
        int r0 = m0 + mt * 16 + gid;
#pragma unroll
        for (int nt = 0; nt < 16; nt++) {
            int cl = nb + nt * 8 + 2 * tig;
            float b0v = b1[cl], b1v = b1[cl + 1];
            sH[r0 * LDH + cl]           = f2tf32(fmaxf(C1[mt][nt][0] + b0v, 0.f));
            sH[r0 * LDH + cl + 1]       = f2tf32(fmaxf(C1[mt][nt][1] + b1v, 0.f));
            sH[(r0 + 8) * LDH + cl]     = f2tf32(fmaxf(C1[mt][nt][2] + b0v, 0.f));
            sH[(r0 + 8) * LDH + cl + 1] = f2tf32(fmaxf(C1[mt][nt][3] + b1v, 0.f));
        }
    }
    __syncthreads();

    float C2[2][8][4];
#pragma unroll
    for (int mt = 0; mt < 2; mt++)
#pragma unroll
        for (int nt = 0; nt < 8; nt++)
#pragma unroll
            for (int q = 0; q < 4; q++) C2[mt][nt][q] = 0.f;

#define LD_B2N(c) do { \
    _Pragma("unroll") \
    for (int t = 0; t < 4; t++) { \
        int f = tid + t * 256; int r = f >> 5, j = f & 31; \
        vb[t] = ((const uint4*)(g_uw2t + (size_t)((c) * 32 + r) * 128))[j]; \
    } \
} while (0)
#define ST_B2N() do { \
    _Pragma("unroll") \
    for (int t = 0; t < 4; t++) { \
        int f = tid + t * 256; int r = f >> 5, j = f & 31; \
        *(uint4*)(sB + r * LDB2 + j * 4) = vb[t]; \
    } \
} while (0)

    LD_B2N(0); ST_B2N();
    __syncthreads();
    for (int c = 0; c < 8; c++) {
        if (c < 7) LD_B2N(c + 1);
#pragma unroll
        for (int ks = 0; ks < 4; ks++) {
            int kg = c * 32 + ks * 8;
            int kl = ks * 8;
            uint32_t a[2][4], b[8][2];
#pragma unroll
            for (int mt = 0; mt < 2; mt++) {
                int rb = m0 + mt * 16;
                a[mt][0] = sH[(rb + gid) * LDH + kg + tig];
                a[mt][1] = sH[(rb + gid + 8) * LDH + kg + tig];
                a[mt][2] = sH[(rb + gid) * LDH + kg + tig + 4];
                a[mt][3] = sH[(rb + gid + 8) * LDH + kg + tig + 4];
            }
#pragma unroll
            for (int nt = 0; nt < 8; nt++) {
                int col = nw + nt * 8 + gid;
                b[nt][0] = sB[(kl + tig) * LDB2 + col];
                b[nt][1] = sB[(kl + tig + 4) * LDB2 + col];
            }
#pragma unroll
            for (int mt = 0; mt < 2; mt++)
#pragma unroll
                for (int nt = 0; nt < 8; nt++)
                    mma_tf32(C2[mt][nt], a[mt][0], a[mt][1], a[mt][2], a[mt][3],
                             b[nt][0], b[nt][1]);
        }
        if (c < 7) {
            __syncthreads();
            ST_B2N();
            __syncthreads();
        }
    }

    // epilogue: h += C2 + b2  (no atomics; unique rows/cols per thread)
#pragma unroll
    for (int mt = 0; mt < 2; mt++) {
        int r0 = m0 + mt * 16 + gid;
        float* p0 = g_h + (size_t)(n0 + r0) * 128;
        float* p1 = g_h + (size_t)(n0 + r0 + 8) * 128;
#pragma unroll
        for (int nt = 0; nt < 8; nt++) {
            int cl = nw + nt * 8 + 2 * tig;
            float b0v = b2[cl], b1v = b2[cl + 1];
            float2 v0 = *(float2*)(p0 + cl);
            v0.x += C2[mt][nt][0] + b0v; v0.y += C2[mt][nt][1] + b1v;
            *(float2*)(p0 + cl) = v0;
            float2 v1 = *(float2*)(p1 + cl);
            v1.x += C2[mt][nt][2] + b0v; v1.y += C2[mt][nt][3] + b1v;
            *(float2*)(p1 + cl) = v1;
        }
    }
#undef LD_A1N
#undef ST_A1N
#undef LD_B1N
#undef ST_B1N
#undef LD_B2N
#undef ST_B2N
}

// -------- zero agg --------
__global__ void zero_agg_kernel(int n4) {
    int i = blockIdx.x * 256 + threadIdx.x;
    if (i < n4) ((float4*)g_agg)[i] = make_float4(0.f, 0.f, 0.f, 0.f);
}

// -------- per-pair start offsets --------
__global__ void starts_kernel(const int* __restrict__ qs, const int* __restrict__ cs, int nb) {
    if (blockIdx.x == 0 && threadIdx.x == 0) {
        int s = 0;
        for (int b = 0; b < nb; b++) {
            g_qstart[b] = s; s += qs[b];
            g_cstart[b] = s; s += cs[b];
        }
    }
}

// -------- node encoder --------
__global__ __launch_bounds__(256) void enc_node_kernel(
    const float* __restrict__ nf, const float* __restrict__ W,
    const float* __restrict__ bias, int n)
{
    __shared__ float s_nf[2][32];
    int tid = threadIdx.x;
    int local = tid >> 7;
    int c = tid & 127;
    int node = blockIdx.x * 2 + local;
    if (tid < 64) {
        int e = tid >> 5, k = tid & 31;
        int nn = blockIdx.x * 2 + e;
        s_nf[e][k] = (nn < n) ? nf[(size_t)nn * 32 + k] : 0.f;
    }
    __syncthreads();
    if (node >= n) return;
    float acc = bias[c];
#pragma unroll
    for (int k = 0; k < 32; k++) acc += s_nf[local][k] * W[k * 128 + c];
    g_h[(size_t)node * 128 + c] = acc;
}

// -------- edge encoder --------
__global__ __launch_bounds__(256) void enc_edge_kernel(
    const float* __restrict__ ef, const float* __restrict__ W,
    const float* __restrict__ bias, int ne)
{
    __shared__ float s_ef[4][16];
    int tid = threadIdx.x;
    int le = tid >> 6;
    int c = tid & 63;
    int e = blockIdx.x * 4 + le;
    if (tid < 64) {
        int ee = tid >> 4, k = tid & 15;
        int eg = blockIdx.x * 4 + ee;
        s_ef[ee][k] = (eg < ne) ? ef[(size_t)eg * 16 + k] : 0.f;
    }
    __syncthreads();
    if (e >= ne) return;
    float acc = bias[c];
#pragma unroll
    for (int k = 0; k < 16; k++) acc += s_ef[le][k] * W[k * 64 + c];
    g_e[(size_t)e * 64 + c] = acc;
}

// -------- t = mlp2(h; fc1, fc2) --------
__global__ __launch_bounds__(256) void t_kernel(
    const float* __restrict__ w1, const float* __restrict__ b1,
    const float* __restrict__ w2, const float* __restrict__ b2)
{
    extern __shared__ float sm[];
    float* xs = sm;
    float* hs = sm + 32 * 128;
    int tid = threadIdx.x;
    int n0 = blockIdx.x * 32;
    for (int idx = tid; idx < 32 * 32; idx += 256) {
        int r = idx >> 5, j = idx & 31;
        *((float4*)(xs + r * 128 + j * 4)) = ((const float4*)g_h)[(size_t)(n0 + r) * 32 + j];
    }
    __syncthreads();

    int c0 = (tid & 31) * 4;
    int eg = (tid >> 5) * 4;
    float acc[4][4];
    {
        float4 bb = *(const float4*)(b1 + c0);
#pragma unroll
        for (int i = 0; i < 4; i++) { acc[i][0] = bb.x; acc[i][1] = bb.y; acc[i][2] = bb.z; acc[i][3] = bb.w; }
    }
#pragma unroll 4
    for (int k = 0; k < 128; k++) {
        float4 w = *(const float4*)(w1 + k * 128 + c0);
#pragma unroll
        for (int i = 0; i < 4; i++) {
            float x = xs[(eg + i) * 128 + k];
            acc[i][0] += x * w.x; acc[i][1] += x * w.y;
            acc[i][2] += x * w.z; acc[i][3] += x * w.w;
        }
    }
#pragma unroll
    for (int i = 0; i < 4; i++) {
        float4 r;
        r.x = fmaxf(acc[i][0], 0.f); r.y = fmaxf(acc[i][1], 0.f);
        r.z = fmaxf(acc[i][2], 0.f); r.w = fmaxf(acc[i][3], 0.f);
        *((float4*)(hs + (eg + i) * 128 + c0)) = r;
    }
    __syncthreads();

    float acc2[4][4];
    {
        float4 bb = *(const float4*)(b2 + c0);
#pragma unroll
        for (int i = 0; i < 4; i++) { acc2[i][0] = bb.x; acc2[i][1] = bb.y; acc2[i][2] = bb.z; acc2[i][3] = bb.w; }
    }
#pragma unroll 4
    for (int k = 0; k < 128; k++) {
        float4 w = *(const float4*)(w2 + k * 128 + c0);
#pragma unroll
        for (int i = 0; i < 4; i++) {
            float x = hs[(eg + i) * 128 + k];
            acc2[i][0] += x * w.x; acc2[i][1] += x * w.y;
            acc2[i][2] += x * w.z; acc2[i][3] += x * w.w;
        }
    }
#pragma unroll
    for (int i = 0; i < 4; i++) {
        float4 r = make_float4(acc2[i][0], acc2[i][1], acc2[i][2], acc2[i][3]);
        *((float4*)(g_t + (size_t)(n0 + eg + i) * 128 + c0)) = r;
    }
}

// -------- per-pair: log_alpha GEMM, Sinkhorn(20), plan@sc, relu score --------
__global__ __launch_bounds__(256) void pair_kernel(
    const int* __restrict__ qsizes, const int* __restrict__ csizes,
    float* __restrict__ out)
{
    extern __shared__ float sm[];
    const int LD = 129;
    float* A = sm;
    float* U = sm + 128 * LD;
    float* V = sm + 2 * 128 * LD;
    __shared__ float red[8];
    int tid = threadIdx.x;
    int b = blockIdx.x;
    int qs = g_qstart[b], cs = g_cstart[b];
    int qn = qsizes[b],  cn = csizes[b];

    for (int idx = tid; idx < 128 * 32; idx += 256) {
        int r = idx >> 5, j = idx & 31;
        float4 z = make_float4(0.f, 0.f, 0.f, 0.f);
        float4 u = (r < qn) ? ((const float4*)g_t)[(size_t)(qs + r) * 32 + j] : z;
        float4 v = (r < cn) ? ((const float4*)g_t)[(size_t)(cs + r) * 32 + j] : z;
        float* pu = U + r * LD + j * 4;
        float* pv = V + r * LD + j * 4;
        pu[0] = u.x; pu[1] = u.y; pu[2] = u.z; pu[3] = u.w;
        pv[0] = v.x; pv[1] = v.y; pv[2] = v.z; pv[3] = v.w;
    }
    __syncthreads();

    int q0 = (tid >> 4) * 8, c0 = (tid & 15) * 8;
    {
        float acc[8][8];
#pragma unroll
        for (int i = 0; i < 8; i++)
#pragma unroll
            for (int j = 0; j < 8; j++) acc[i][j] = 0.f;
        for (int d = 0; d < 128; d++) {
            float uq[8], vc[8];
#pragma unroll
            for (int i = 0; i < 8; i++) uq[i] = U[(q0 + i) * LD + d];
#pragma unroll
            for (int j = 0; j < 8; j++) vc[j] = V[(c0 + j) * LD + d];
#pragma unroll
            for (int i = 0; i < 8; i++)
#pragma unroll
                for (int j = 0; j < 8; j++) acc[i][j] += uq[i] * vc[j];
        }
#pragma unroll
        for (int i = 0; i < 8; i++)
#pragma unroll
            for (int j = 0; j < 8; j++) A[(q0 + i) * LD + c0 + j] = acc[i][j] * 10.0f;
    }
    __syncthreads();

    int warp = tid >> 5, lane = tid & 31;
    for (int it = 0; it < 20; it++) {
        for (int r = warp; r < 128; r += 8) {
            float v0 = A[r * LD + lane],      v1 = A[r * LD + lane + 32];
            float v2 = A[r * LD + lane + 64], v3 = A[r * LD + lane + 96];
            float m = fmaxf(fmaxf(v0, v1), fmaxf(v2, v3));
#pragma unroll
            for (int o = 16; o > 0; o >>= 1) m = fmaxf(m, __shfl_xor_sync(0xffffffffu, m, o));
            float s = __expf(v0 - m) + __expf(v1 - m) + __expf(v2 - m) + __expf(v3 - m);
#pragma unroll
            for (int o = 16; o > 0; o >>= 1) s += __shfl_xor_sync(0xffffffffu, s, o);
            float lse = m + __logf(s);
            A[r * LD + lane]      = v0 - lse; A[r * LD + lane + 32] = v1 - lse;
            A[r * LD + lane + 64] = v2 - lse; A[r * LD + lane + 96] = v3 - lse;
        }
        __syncthreads();
        for (int c = warp; c < 128; c += 8) {
            float v0 = A[lane * LD + c],        v1 = A[(lane + 32) * LD + c];
            float v2 = A[(lane + 64) * LD + c], v3 = A[(lane + 96) * LD + c];
            float m = fmaxf(fmaxf(v0, v1), fmaxf(v2, v3));
#pragma unroll
            for (int o = 16; o > 0; o >>= 1) m = fmaxf(m, __shfl_xor_sync(0xffffffffu, m, o));
            float s = __expf(v0 - m) + __expf(v1 - m) + __expf(v2 - m) + __expf(v3 - m);
#pragma unroll
            for (int o = 16; o > 0; o >>= 1) s += __shfl_xor_sync(0xffffffffu, s, o);
            float lse = m + __logf(s);
            A[lane * LD + c]        = v0 - lse; A[(lane + 32) * LD + c] = v1 - lse;
            A[(lane + 64) * LD + c] = v2 - lse; A[(lane + 96) * LD + c] = v3 - lse;
        }
        __syncthreads();
    }

    for (int idx = tid; idx < 128 * 128; idx += 256) {
        int r = idx >> 7, c = idx & 127;
        A[r * LD + c] = __expf(A[r * LD + c]);
    }
    for (int idx = tid; idx < 128 * 32; idx += 256) {
        int r = idx >> 5, j = idx & 31;
        float4 z = make_float4(0.f, 0.f, 0.f, 0.f);
        float4 u = (r < qn) ? ((const float4*)g_h)[(size_t)(qs + r) * 32 + j] : z;
        float4 v = (r < cn) ? ((const float4*)g_h)[(size_t)(cs + r) * 32 + j] : z;
        float* pu = U + r * LD + j * 4;
        float* pv = V + r * LD + j * 4;
        pu[0] = u.x; pu[1] = u.y; pu[2] = u.z; pu[3] = u.w;
        pv[0] = v.x; pv[1] = v.y; pv[2] = v.z; pv[3] = v.w;
    }
    __syncthreads();

    float local = 0.f;
    {
        int d0 = c0;
        float acc[8][8];
#pragma unroll
        for (int i = 0; i < 8; i++)
#pragma unroll
            for (int j = 0; j < 8; j++) acc[i][j] = 0.f;
        for (int c = 0; c < 128; c++) {
            float pr[8], vv[8];
#pragma unroll
            for (int i = 0; i < 8; i++) pr[i] = A[(q0 + i) * LD + c];
#pragma unroll
            for (int j = 0; j < 8; j++) vv[j] = V[c * LD + d0 + j];
#pragma unroll
            for (int i = 0; i < 8; i++)
#pragma unroll
                for (int j = 0; j < 8; j++) acc[i][j] += pr[i] * vv[j];
        }
#pragma unroll
        for (int i = 0; i < 8; i++)
#pragma unroll
            for (int j = 0; j < 8; j++)
                local += fmaxf(U[(q0 + i) * LD + d0 + j] - acc[i][j], 0.f);
    }
#pragma unroll
    for (int o = 16; o > 0; o >>= 1) local += __shfl_xor_sync(0xffffffffu, local, o);
    if (lane == 0) red[warp] = local;
    __syncthreads();
    if (tid == 0) {
        float tot = 0.f;
#pragma unroll
        for (int w = 0; w < 8; w++) tot += red[w];
        out[b] = -tot;
    }
}

// -------- launch --------
extern "C" void kernel_launch(void* const* d_in, const int* in_sizes, int n_in,
                              void* d_out, int out_size) {
    const float* node_features = (const float*)d_in[0];
    const float* edge_features = (const float*)d_in[1];
    const float* enc_node_w = (const float*)d_in[2];
    const float* enc_node_b = (const float*)d_in[3];
    const float* enc_edge_w = (const float*)d_in[4];
    const float* enc_edge_b = (const float*)d_in[5];
    const float* msg_w1 = (const float*)d_in[6];
    const float* msg_b1 = (const float*)d_in[7];
    const float* msg_w2 = (const float*)d_in[8];
    const float* msg_b2 = (const float*)d_in[9];
    const float* rmsg_w1 = (const float*)d_in[10];
    const float* rmsg_b1 = (const float*)d_in[11];
    const float* rmsg_w2 = (const float*)d_in[12];
    const float* rmsg_b2 = (const float*)d_in[13];
    const float* upd_w1 = (const float*)d_in[14];
    const float* upd_b1 = (const float*)d_in[15];
    const float* upd_w2 = (const float*)d_in[16];
    const float* upd_b2 = (const float*)d_in[17];
    const float* fc1_w = (const float*)d_in[18];
    const float* fc1_b = (const float*)d_in[19];
    const float* fc2_w = (const float*)d_in[20];
    const float* fc2_b = (const float*)d_in[21];
    const int* from_idx = (const int*)d_in[22];
    const int* to_idx = (const int*)d_in[23];
    const int* qsizes = (const int*)d_in[25];
    const int* csizes = (const int*)d_in[26];

    int N = in_sizes[0] / 32;
    int E = in_sizes[1] / 16;
    int B = in_sizes[25];

    int smem_t    = (32 * 128 * 2) * 4;
    int smem_pair = 3 * 128 * 129 * 4;

    cudaFuncSetAttribute(edge_fused_kernel, cudaFuncAttributeMaxDynamicSharedMemorySize, EDGE_SMEM);
    cudaFuncSetAttribute(node_fused_kernel, cudaFuncAttributeMaxDynamicSharedMemorySize, NODE_SMEM);
    cudaFuncSetAttribute(pair_kernel,       cudaFuncAttributeMaxDynamicSharedMemorySize, smem_pair);

    uint32_t *mw1t, *rw1t, *mw2t, *rw2t;
    cudaGetSymbolAddress((void**)&mw1t, g_mw1t);
    cudaGetSymbolAddress((void**)&rw1t, g_rw1t);
    cudaGetSymbolAddress((void**)&mw2t, g_mw2t);
    cudaGetSymbolAddress((void**)&rw2t, g_rw2t);

    enc_node_kernel<<<(N + 1) / 2, 256>>>(node_features, enc_node_w, enc_node_b, N);
    enc_edge_kernel<<<(E + 3) / 4, 256>>>(edge_features, enc_edge_w, enc_edge_b, E);
    starts_kernel<<<1, 32>>>(qsizes, csizes, B);
    prep_tf32<<<256, 256>>>(msg_w1, rmsg_w1, msg_w2, rmsg_w2, upd_w1, upd_w2);

    for (int p = 0; p < 5; p++) {
        zero_agg_kernel<<<(N * 32 + 255) / 256, 256>>>(N * 32);
        // msg: x=[h[from],h[to],e], scatter to to_idx
        edge_fused_kernel<<<E / 128, 256, EDGE_SMEM>>>(mw1t, msg_b1, mw2t, msg_b2, from_idx, to_idx);
        // rmsg: x=[h[to],h[from],e], scatter to from_idx
        edge_fused_kernel<<<E / 128, 256, EDGE_SMEM>>>(rw1t, rmsg_b1, rw2t, rmsg_b2, to_idx, from_idx);
        node_fused_kernel<<<N / 128, 256, NODE_SMEM>>>(upd_b1, upd_b2);
    }
    t_kernel<<<N / 32, 256, smem_t>>>(fc1_w, fc1_b, fc2_w, fc2_b);
    pair_kernel<<<B, 256, smem_pair>>>(qsizes, csizes, (float*)d_out);
}

// round 11
// speedup vs baseline: 3.0954x; 1.0917x over previous
#include <cuda_runtime.h>
#include <cstdint>
#include <math.h>

#define NN 98304
#define NE 786432
#define NB 512

// -------- scratch (device globals; no allocation allowed) --------
__device__ __align__(1024) float g_h[(size_t)NN * 128];
__device__ __align__(1024) float g_e[(size_t)NE * 64];
__device__ __align__(1024) float g_agg[(size_t)NN * 128];
__device__ __align__(1024) float g_t[(size_t)NN * 128];
__device__ __align__(1024) uint32_t g_mw1t[320 * 256];  // tf32 bits
__device__ __align__(1024) uint32_t g_rw1t[320 * 256];
__device__ __align__(1024) uint32_t g_mw2t[256 * 128];
__device__ __align__(1024) uint32_t g_rw2t[256 * 128];
__device__ __align__(1024) uint32_t g_uw1t[256 * 256];
__device__ __align__(1024) uint32_t g_uw2t[256 * 128];
__device__ int g_qstart[NB];
__device__ int g_cstart[NB];

// -------- helpers --------
__device__ __forceinline__ uint32_t f2tf32(float v) {
    uint32_t r;
    asm("cvt.rna.tf32.f32 %0, %1;" : "=r"(r) : "f"(v));
    return r;
}
__device__ __forceinline__ void mma_tf32(float c[4],
    uint32_t a0, uint32_t a1, uint32_t a2, uint32_t a3, uint32_t b0, uint32_t b1)
{
    asm volatile(
        "mma.sync.aligned.m16n8k8.row.col.f32.tf32.tf32.f32 "
        "{%0,%1,%2,%3}, {%4,%5,%6,%7}, {%8,%9}, {%0,%1,%2,%3};"
        : "+f"(c[0]), "+f"(c[1]), "+f"(c[2]), "+f"(c[3])
        : "r"(a0), "r"(a1), "r"(a2), "r"(a3), "r"(b0), "r"(b1));
}
__device__ __forceinline__ void red_add_v2(float* p, float a, float b) {
    asm volatile("red.global.add.v2.f32 [%0], {%1, %2};" :: "l"(p), "f"(a), "f"(b) : "memory");
}

// smem layout (bytes):
//  sH   [0, 133120)         128 x 260 u32 (tf32 H tile); doubles as GEMM1-B buf1
//  sA   [133120, 169984)    2 x 128 x 36 u32 (A chunk db); doubles as GEMM2-B bufs
//  sB1  [169984, 203776)    32 x 264 u32 (GEMM1-B buf0)
//  s0   [203776, 204288)    128 ints
//  s1   [204288, 204800)    128 ints
#define LDH 260
#define LDA 36
#define LDB1 264
#define LDB2 136
#define SA_OFF 133120
#define SB1_OFF 169984
#define SI0_OFF 203776
#define SI1_OFF 204288
#define EDGE_SMEM 204800

// -------- prep: convert all GEMM weights to tf32 bits once --------
__global__ void prep_tf32(
    const float* __restrict__ mw1, const float* __restrict__ rw1,
    const float* __restrict__ mw2, const float* __restrict__ rw2,
    const float* __restrict__ uw1, const float* __restrict__ uw2)
{
    int i = blockIdx.x * 256 + threadIdx.x;
    int stride = gridDim.x * 256;
    for (int idx = i; idx < 320 * 256; idx += stride) {
        g_mw1t[idx] = f2tf32(mw1[idx]);
        g_rw1t[idx] = f2tf32(rw1[idx]);
    }
    for (int idx = i; idx < 256 * 256; idx += stride)
        g_uw1t[idx] = f2tf32(uw1[idx]);
    for (int idx = i; idx < 256 * 128; idx += stride) {
        g_mw2t[idx] = f2tf32(mw2[idx]);
        g_rw2t[idx] = f2tf32(rw2[idx]);
        g_uw2t[idx] = f2tf32(uw2[idx]);
    }
}

// ======== fused edge kernel: one half (msg or rmsg) ========
__global__ __launch_bounds__(256, 1) void edge_fused_kernel(
    const uint32_t* __restrict__ W1t, const float* __restrict__ b1,
    const uint32_t* __restrict__ W2t, const float* __restrict__ b2,
    const int* __restrict__ gidx0, const int* __restrict__ gidx1)
{
    extern __shared__ char smc[];
    uint32_t* sH = (uint32_t*)smc;
    uint32_t* sA = (uint32_t*)(smc + SA_OFF);
    int* s0 = (int*)(smc + SI0_OFF);
    int* s1 = (int*)(smc + SI1_OFF);
    int tid = threadIdx.x, lane = tid & 31, w = tid >> 5;
    int gid = lane >> 2, tig = lane & 3;
    int e0 = blockIdx.x * 128;
    if (tid < 128) { s0[tid] = gidx0[e0 + tid]; s1[tid] = gidx1[e0 + tid]; }
    __syncthreads();

    // GEMM1 warp tile: 64 rows x 64 cols (8 warps = 2m x 4n)
    int m1 = (w & 1) * 64;
    int n1 = (w >> 1) * 64;
    float C1[4][8][4];
#pragma unroll
    for (int mt = 0; mt < 4; mt++)
#pragma unroll
        for (int nt = 0; nt < 8; nt++)
#pragma unroll
            for (int q = 0; q < 4; q++) C1[mt][nt][q] = 0.f;

    float4 va[4];
    uint4 vb[8];

#define B1PTR(buf) ((buf) ? sH : (uint32_t*)(smc + SB1_OFF))
#define LD_A1(c) do { \
    _Pragma("unroll") \
    for (int t = 0; t < 4; t++) { \
        int f = tid + t * 256; int r = f >> 3, j = f & 7; \
        const float* src; \
        if ((c) < 4)      src = g_h + (size_t)s0[r] * 128 + (c) * 32 + j * 4; \
        else if ((c) < 8) src = g_h + (size_t)s1[r] * 128 + ((c) - 4) * 32 + j * 4; \
        else              src = g_e + (size_t)(e0 + r) * 64 + ((c) - 8) * 32 + j * 4; \
        va[t] = *(const float4*)src; \
    } \
} while (0)
#define ST_A1(buf) do { \
    _Pragma("unroll") \
    for (int t = 0; t < 4; t++) { \
        int f = tid + t * 256; int r = f >> 3, j = f & 7; \
        uint4 u; u.x = f2tf32(va[t].x); u.y = f2tf32(va[t].y); \
        u.z = f2tf32(va[t].z); u.w = f2tf32(va[t].w); \
        *(uint4*)(sA + (buf) * 128 * LDA + r * LDA + j * 4) = u; \
    } \
} while (0)
#define LD_B1(c) do { \
    _Pragma("unroll") \
    for (int t = 0; t < 8; t++) { \
        int f = tid + t * 256; int r = f >> 6, j = f & 63; \
        vb[t] = ((const uint4*)(W1t + (size_t)((c) * 32 + r) * 256))[j]; \
    } \
} while (0)
#define ST_B1(buf) do { \
    uint32_t* B_ = B1PTR(buf); \
    _Pragma("unroll") \
    for (int t = 0; t < 8; t++) { \
        int f = tid + t * 256; int r = f >> 6, j = f & 63; \
        *(uint4*)(B_ + r * LDB1 + j * 4) = vb[t]; \
    } \
} while (0)
#define COMPUTE1(buf) do { \
    uint32_t* A = sA + (buf) * 128 * LDA; \
    uint32_t* B = B1PTR(buf); \
    _Pragma("unroll") \
    for (int ks = 0; ks < 4; ks++) { \
        int k = ks * 8; \
        uint32_t a[4][4], b[8][2]; \
        _Pragma("unroll") \
        for (int mt = 0; mt < 4; mt++) { \
            int rb = m1 + mt * 16; \
            a[mt][0] = A[(rb + gid) * LDA + k + tig]; \
            a[mt][1] = A[(rb + gid + 8) * LDA + k + tig]; \
            a[mt][2] = A[(rb + gid) * LDA + k + tig + 4]; \
            a[mt][3] = A[(rb + gid + 8) * LDA + k + tig + 4]; \
        } \
        _Pragma("unroll") \
        for (int nt = 0; nt < 8; nt++) { \
            int col = n1 + nt * 8 + gid; \
            b[nt][0] = B[(k + tig) * LDB1 + col]; \
            b[nt][1] = B[(k + tig + 4) * LDB1 + col]; \
        } \
        _Pragma("unroll") \
        for (int mt = 0; mt < 4; mt++) \
            _Pragma("unroll") \
            for (int nt = 0; nt < 8; nt++) \
                mma_tf32(C1[mt][nt], a[mt][0], a[mt][1], a[mt][2], a[mt][3], \
                         b[nt][0], b[nt][1]); \
    } \
} while (0)

    // GEMM1: K=320, 10 chunks; double-buffered A+B, 1 sync/chunk
    LD_A1(0); LD_B1(0);
    ST_A1(0); ST_B1(0);
    __syncthreads();
    for (int c = 0; c < 10; c++) {
        if (c < 9) { LD_A1(c + 1); LD_B1(c + 1); }
        COMPUTE1(c & 1);
        if (c < 9) {
            ST_A1((c + 1) & 1); ST_B1((c + 1) & 1);
            __syncthreads();
        }
    }
    __syncthreads();

    // H = relu(C1 + b1) as tf32 bits into sH
#pragma unroll
    for (int mt = 0; mt < 4; mt++) {
        int r0 = m1 + mt * 16 + gid;
#pragma unroll
        for (int nt = 0; nt < 8; nt++) {
            int cl = n1 + nt * 8 + 2 * tig;
            float b0v = b1[cl], b1v = b1[cl + 1];
            sH[r0 * LDH + cl]           = f2tf32(fmaxf(C1[mt][nt][0] + b0v, 0.f));
            sH[r0 * LDH + cl + 1]       = f2tf32(fmaxf(C1[mt][nt][1] + b1v, 0.f));
            sH[(r0 + 8) * LDH + cl]     = f2tf32(fmaxf(C1[mt][nt][2] + b0v, 0.f));
            sH[(r0 + 8) * LDH + cl + 1] = f2tf32(fmaxf(C1[mt][nt][3] + b1v, 0.f));
        }
    }
    __syncthreads();

    // GEMM2: K=256 from sH, N=128; warp tile 32 x 64 (4m x 2n)
    int m2 = (w >> 1) * 32;
    int n2 = (w & 1) * 64;
    float C2[2][8][4];
#pragma unroll
    for (int mt = 0; mt < 2; mt++)
#pragma unroll
        for (int nt = 0; nt < 8; nt++)
#pragma unroll
            for (int q = 0; q < 4; q++) C2[mt][nt][q] = 0.f;

#define B2PTR(buf) (sA + (buf) * 32 * LDB2)
#define LD_B2(c) do { \
    _Pragma("unroll") \
    for (int t = 0; t < 4; t++) { \
        int f = tid + t * 256; int r = f >> 5, j = f & 31; \
        vb[t] = ((const uint4*)(W2t + (size_t)((c) * 32 + r) * 128))[j]; \
    } \
} while (0)
#define ST_B2(buf) do { \
    uint32_t* B_ = B2PTR(buf); \
    _Pragma("unroll") \
    for (int t = 0; t < 4; t++) { \
        int f = tid + t * 256; int r = f >> 5, j = f & 31; \
        *(uint4*)(B_ + r * LDB2 + j * 4) = vb[t]; \
    } \
} while (0)
#define COMPUTE2(c, buf) do { \
    uint32_t* B = B2PTR(buf); \
    _Pragma("unroll") \
    for (int ks = 0; ks < 4; ks++) { \
        int kg = (c) * 32 + ks * 8; \
        int kl = ks * 8; \
        uint32_t a[2][4], b[8][2]; \
        _Pragma("unroll") \
        for (int mt = 0; mt < 2; mt++) { \
            int rb = m2 + mt * 16; \
            a[mt][0] = sH[(rb + gid) * LDH + kg + tig]; \
            a[mt][1] = sH[(rb + gid + 8) * LDH + kg + tig]; \
            a[mt][2] = sH[(rb + gid) * LDH + kg + tig + 4]; \
            a[mt][3] = sH[(rb + gid + 8) * LDH + kg + tig + 4]; \
        } \
        _Pragma("unroll") \
        for (int nt = 0; nt < 8; nt++) { \
            int col = n2 + nt * 8 + gid; \
            b[nt][0] = B[(kl + tig) * LDB2 + col]; \
            b[nt][1] = B[(kl + tig + 4) * LDB2 + col]; \
        } \
        _Pragma("unroll") \
        for (int mt = 0; mt < 2; mt++) \
            _Pragma("unroll") \
            for (int nt = 0; nt < 8; nt++) \
                mma_tf32(C2[mt][nt], a[mt][0], a[mt][1], a[mt][2], a[mt][3], \
                         b[nt][0], b[nt][1]); \
    } \
} while (0)

    LD_B2(0); ST_B2(0);
    __syncthreads();
    for (int c = 0; c < 8; c++) {
        if (c < 7) LD_B2(c + 1);
        COMPUTE2(c, c & 1);
        if (c < 7) {
            ST_B2((c + 1) & 1);
            __syncthreads();
        }
    }

    // epilogue: vector-atomic scatter to g_agg[s1]
#pragma unroll
    for (int mt = 0; mt < 2; mt++) {
        int r0 = m2 + mt * 16 + gid;
        float* p0 = g_agg + (size_t)s1[r0] * 128;
        float* p1 = g_agg + (size_t)s1[r0 + 8] * 128;
#pragma unroll
        for (int nt = 0; nt < 8; nt++) {
            int cl = n2 + nt * 8 + 2 * tig;
            float b0v = b2[cl], b1v = b2[cl + 1];
            red_add_v2(p0 + cl, C2[mt][nt][0] + b0v, C2[mt][nt][1] + b1v);
            red_add_v2(p1 + cl, C2[mt][nt][2] + b0v, C2[mt][nt][3] + b1v);
        }
    }
#undef B1PTR
#undef LD_A1
#undef ST_A1
#undef LD_B1
#undef ST_B1
#undef COMPUTE1
#undef B2PTR
#undef LD_B2
#undef ST_B2
#undef COMPUTE2
}

// ======== fused node update: h += relu([agg|h]@uw1+b1)@uw2+b2 ========
__global__ __launch_bounds__(256, 1) void node_fused_kernel(
    const float* __restrict__ b1, const float* __restrict__ b2)
{
    extern __shared__ char smc[];
    uint32_t* sH = (uint32_t*)smc;
    uint32_t* sA = (uint32_t*)(smc + SA_OFF);
    int tid = threadIdx.x, lane = tid & 31, w = tid >> 5;
    int gid = lane >> 2, tig = lane & 3;
    int n0 = blockIdx.x * 128;

    int m1 = (w & 1) * 64;
    int n1 = (w >> 1) * 64;
    float C1[4][8][4];
#pragma unroll
    for (int mt = 0; mt < 4; mt++)
#pragma unroll
        for (int nt = 0; nt < 8; nt++)
#pragma unroll
            for (int q = 0; q < 4; q++) C1[mt][nt][q] = 0.f;

    float4 va[4];
    uint4 vb[8];

#define B1PTR(buf) ((buf) ? sH : (uint32_t*)(smc + SB1_OFF))
#define LD_A1N(c) do { \
    _Pragma("unroll") \
    for (int t = 0; t < 4; t++) { \
        int f = tid + t * 256; int r = f >> 3, j = f & 7; \
        const float* src; \
        if ((c) < 4) src = g_agg + (size_t)(n0 + r) * 128 + (c) * 32 + j * 4; \
        else         src = g_h + (size_t)(n0 + r) * 128 + ((c) - 4) * 32 + j * 4; \
        va[t] = *(const float4*)src; \
    } \
} while (0)
#define ST_A1N(buf) do { \
    _Pragma("unroll") \
    for (int t = 0; t < 4; t++) { \
        int f = tid + t * 256; int r = f >> 3, j = f & 7; \
        uint4 u; u.x = f2tf32(va[t].x); u.y = f2tf32(va[t].y); \
        u.z = f2tf32(va[t].z); u.w = f2tf32(va[t].w); \
        *(uint4*)(sA + (buf) * 128 * LDA + r * LDA + j * 4) = u; \
    } \
} while (0)
#define LD_B1N(c) do { \
    _Pragma("unroll") \
    for (int t = 0; t < 8; t++) { \
        int f = tid + t * 256; int r = f >> 6, j = f & 63; \
        vb[t] = ((const uint4*)(g_uw1t + (size_t)((c) * 32 + r) * 256))[j]; \
    } \
} while (0)
#define ST_B1N(buf) do { \
    uint32_t* B_ = B1PTR(buf); \
    _Pragma("unroll") \
    for (int t = 0; t < 8; t++) { \
        int f = tid + t * 256; int r = f >> 6, j = f & 63; \
        *(uint4*)(B_ + r * LDB1 + j * 4) = vb[t]; \
    } \
} while (0)
#define COMPUTE1N(buf) do { \
    uint32_t* A = sA + (buf) * 128 * LDA; \
    uint32_t* B = B1PTR(buf); \
    _Pragma("unroll") \
    for (int ks = 0; ks < 4; ks++) { \
        int k = ks * 8; \
        uint32_t a[4][4], b[8][2]; \
        _Pragma("unroll") \
        for (int mt = 0; mt < 4; mt++) { \
            int rb = m1 + mt * 16; \
            a[mt][0] = A[(rb + gid) * LDA + k + tig]; \
            a[mt][1] = A[(rb + gid + 8) * LDA + k + tig]; \
            a[mt][2] = A[(rb + gid) * LDA + k + tig + 4]; \
            a[mt][3] = A[(rb + gid + 8) * LDA + k + tig + 4]; \
        } \
        _Pragma("unroll") \
        for (int nt = 0; nt < 8; nt++) { \
            int col = n1 + nt * 8 + gid; \
            b[nt][0] = B[(k + tig) * LDB1 + col]; \
            b[nt][1] = B[(k + tig + 4) * LDB1 + col]; \
        } \
        _Pragma("unroll") \
        for (int mt = 0; mt < 4; mt++) \
            _Pragma("unroll") \
            for (int nt = 0; nt < 8; nt++) \
                mma_tf32(C1[mt][nt], a[mt][0], a[mt][1], a[mt][2], a[mt][3], \
                         b[nt][0], b[nt][1]); \
    } \
} while (0)

    LD_A1N(0); LD_B1N(0);
    ST_A1N(0); ST_B1N(0);
    __syncthreads();
    for (int c = 0; c < 8; c++) {
        if (c < 7) { LD_A1N(c + 1); LD_B1N(c + 1); }
        COMPUTE1N(c & 1);
        if (c < 7) {
            ST_A1N((c + 1) & 1); ST_B1N((c + 1) & 1);
            __syncthreads();
        }
    }
    __syncthreads();

#pragma unroll
    for (int mt = 0; mt < 4; mt++) {
        int r0 = m1 + mt * 16 + gid;
#pragma unroll
        for (int nt = 0; nt < 8; nt++) {
            int cl = n1 + nt * 8 + 2 * tig;
            float b0v = b1[cl], b1v = b1[cl + 1];
            sH[r0 * LDH + cl]           = f2tf32(fmaxf(C1[mt][nt][0] + b0v, 0.f));
            sH[r0 * LDH + cl + 1]       = f2tf32(fmaxf(C1[mt][nt][1] + b1v, 0.f));
            sH[(r0 + 8) * LDH + cl]     = f2tf32(fmaxf(C1[mt][nt][2] + b0v, 0.f));
            sH[(r0 + 8) * LDH + cl + 1] = f2tf32(fmaxf(C1[mt][nt][3] + b1v, 0.f));
        }
    }
    __syncthreads();

    int m2 = (w >> 1) * 32;
    int n2 = (w & 1) * 64;
    float C2[2][8][4];
#pragma unroll
    for (int mt = 0; mt < 2; mt++)
#pragma unroll
        for (int nt = 0; nt < 8; nt++)
#pragma unroll
            for (int q = 0; q < 4; q++) C2[mt][nt][q] = 0.f;

#define B2PTR(buf) (sA + (buf) * 32 * LDB2)
#define LD_B2N(c) do { \
    _Pragma("unroll") \
    for (int t = 0; t < 4; t++) { \
        int f = tid + t * 256; int r = f >> 5, j = f & 31; \
        vb[t] = ((const uint4*)(g_uw2t + (size_t)((c) * 32 + r) * 128))[j]; \
    } \
} while (0)
#define ST_B2N(buf) do { \
    uint32_t* B_ = B2PTR(buf); \
    _Pragma("unroll") \
    for (int t = 0; t < 4; t++) { \
        int f = tid + t * 256; int r = f >> 5, j = f & 31; \
        *(uint4*)(B_ + r * LDB2 + j * 4) = vb[t]; \
    } \
} while (0)

    LD_B2N(0); ST_B2N(0);
    __syncthreads();
    for (int c = 0; c < 8; c++) {
        if (c < 7) LD_B2N(c + 1);
        {
            uint32_t* B = B2PTR(c & 1);
#pragma unroll
            for (int ks = 0; ks < 4; ks++) {
                int kg = c * 32 + ks * 8;
                int kl = ks * 8;
                uint32_t a[2][4], b[8][2];
#pragma unroll
                for (int mt = 0; mt < 2; mt++) {
                    int rb = m2 + mt * 16;
                    a[mt][0] = sH[(rb + gid) * LDH + kg + tig];
                    a[mt][1] = sH[(rb + gid + 8) * LDH + kg + tig];
                    a[mt][2] = sH[(rb + gid) * LDH + kg + tig + 4];
                    a[mt][3] = sH[(rb + gid + 8) * LDH + kg + tig + 4];
                }
#pragma unroll
                for (int nt = 0; nt < 8; nt++) {
                    int col = n2 + nt * 8 + gid;
                    b[nt][0] = B[(kl + tig) * LDB2 + col];
                    b[nt][1] = B[(kl + tig + 4) * LDB2 + col];
                }
#pragma unroll
                for (int mt = 0; mt < 2; mt++)
#pragma unroll
                    for (int nt = 0; nt < 8; nt++)
                        mma_tf32(C2[mt][nt], a[mt][0], a[mt][1], a[mt][2], a[mt][3],
                                 b[nt][0], b[nt][1]);
            }
        }
        if (c < 7) {
            ST_B2N((c + 1) & 1);
            __syncthreads();
        }
    }

    // epilogue: h += C2 + b2  (no atomics; unique rows/cols per thread)
#pragma unroll
    for (int mt = 0; mt < 2; mt++) {
        int r0 = m2 + mt * 16 + gid;
        float* p0 = g_h + (size_t)(n0 + r0) * 128;
        float* p1 = g_h + (size_t)(n0 + r0 + 8) * 128;
#pragma unroll
        for (int nt = 0; nt < 8; nt++) {
            int cl = n2 + nt * 8 + 2 * tig;
            float b0v = b2[cl], b1v = b2[cl + 1];
            float2 v0 = *(float2*)(p0 + cl);
            v0.x += C2[mt][nt][0] + b0v; v0.y += C2[mt][nt][1] + b1v;
            *(float2*)(p0 + cl) = v0;
            float2 v1 = *(float2*)(p1 + cl);
            v1.x += C2[mt][nt][2] + b0v; v1.y += C2[mt][nt][3] + b1v;
            *(float2*)(p1 + cl) = v1;
        }
    }
#undef B1PTR
#undef LD_A1N
#undef ST_A1N
#undef LD_B1N
#undef ST_B1N
#undef COMPUTE1N
#undef B2PTR
#undef LD_B2N
#undef ST_B2N
}

// -------- zero agg --------
__global__ void zero_agg_kernel(int n4) {
    int i = blockIdx.x * 256 + threadIdx.x;
    if (i < n4) ((float4*)g_agg)[i] = make_float4(0.f, 0.f, 0.f, 0.f);
}

// -------- per-pair start offsets --------
__global__ void starts_kernel(const int* __restrict__ qs, const int* __restrict__ cs, int nb) {
    if (blockIdx.x == 0 && threadIdx.x == 0) {
        int s = 0;
        for (int b = 0; b < nb; b++) {
            g_qstart[b] = s; s += qs[b];
            g_cstart[b] = s; s += cs[b];
        }
    }
}

// -------- node encoder --------
__global__ __launch_bounds__(256) void enc_node_kernel(
    const float* __restrict__ nf, const float* __restrict__ W,
    const float* __restrict__ bias, int n)
{
    __shared__ float s_nf[2][32];
    int tid = threadIdx.x;
    int local = tid >> 7;
    int c = tid & 127;
    int node = blockIdx.x * 2 + local;
    if (tid < 64) {
        int e = tid >> 5, k = tid & 31;
        int nn = blockIdx.x * 2 + e;
        s_nf[e][k] = (nn < n) ? nf[(size_t)nn * 32 + k] : 0.f;
    }
    __syncthreads();
    if (node >= n) return;
    float acc = bias[c];
#pragma unroll
    for (int k = 0; k < 32; k++) acc += s_nf[local][k] * W[k * 128 + c];
    g_h[(size_t)node * 128 + c] = acc;
}

// -------- edge encoder --------
__global__ __launch_bounds__(256) void enc_edge_kernel(
    const float* __restrict__ ef, const float* __restrict__ W,
    const float* __restrict__ bias, int ne)
{
    __shared__ float s_ef[4][16];
    int tid = threadIdx.x;
    int le = tid >> 6;
    int c = tid & 63;
    int e = blockIdx.x * 4 + le;
    if (tid < 64) {
        int ee = tid >> 4, k = tid & 15;
        int eg = blockIdx.x * 4 + ee;
        s_ef[ee][k] = (eg < ne) ? ef[(size_t)eg * 16 + k] : 0.f;
    }
    __syncthreads();
    if (e >= ne) return;
    float acc = bias[c];
#pragma unroll
    for (int k = 0; k < 16; k++) acc += s_ef[le][k] * W[k * 64 + c];
    g_e[(size_t)e * 64 + c] = acc;
}

// -------- t = mlp2(h; fc1, fc2) --------
__global__ __launch_bounds__(256) void t_kernel(
    const float* __restrict__ w1, const float* __restrict__ b1,
    const float* __restrict__ w2, const float* __restrict__ b2)
{
    extern __shared__ float sm[];
    float* xs = sm;
    float* hs = sm + 32 * 128;
    int tid = threadIdx.x;
    int n0 = blockIdx.x * 32;
    for (int idx = tid; idx < 32 * 32; idx += 256) {
        int r = idx >> 5, j = idx & 31;
        *((float4*)(xs + r * 128 + j * 4)) = ((const float4*)g_h)[(size_t)(n0 + r) * 32 + j];
    }
    __syncthreads();

    int c0 = (tid & 31) * 4;
    int eg = (tid >> 5) * 4;
    float acc[4][4];
    {
        float4 bb = *(const float4*)(b1 + c0);
#pragma unroll
        for (int i = 0; i < 4; i++) { acc[i][0] = bb.x; acc[i][1] = bb.y; acc[i][2] = bb.z; acc[i][3] = bb.w; }
    }
#pragma unroll 4
    for (int k = 0; k < 128; k++) {
        float4 w = *(const float4*)(w1 + k * 128 + c0);
#pragma unroll
        for (int i = 0; i < 4; i++) {
            float x = xs[(eg + i) * 128 + k];
            acc[i][0] += x * w.x; acc[i][1] += x * w.y;
            acc[i][2] += x * w.z; acc[i][3] += x * w.w;
        }
    }
#pragma unroll
    for (int i = 0; i < 4; i++) {
        float4 r;
        r.x = fmaxf(acc[i][0], 0.f); r.y = fmaxf(acc[i][1], 0.f);
        r.z = fmaxf(acc[i][2], 0.f); r.w = fmaxf(acc[i][3], 0.f);
        *((float4*)(hs + (eg + i) * 128 + c0)) = r;
    }
    __syncthreads();

    float acc2[4][4];
    {
        float4 bb = *(const float4*)(b2 + c0);
#pragma unroll
        for (int i = 0; i < 4; i++) { acc2[i][0] = bb.x; acc2[i][1] = bb.y; acc2[i][2] = bb.z; acc2[i][3] = bb.w; }
    }
#pragma unroll 4
    for (int k = 0; k < 128; k++) {
        float4 w = *(const float4*)(w2 + k * 128 + c0);
#pragma unroll
        for (int i = 0; i < 4; i++) {
            float x = hs[(eg + i) * 128 + k];
            acc2[i][0] += x * w.x; acc2[i][1] += x * w.y;
            acc2[i][2] += x * w.z; acc2[i][3] += x * w.w;
        }
    }
#pragma unroll
    for (int i = 0; i < 4; i++) {
        float4 r = make_float4(acc2[i][0], acc2[i][1], acc2[i][2], acc2[i][3]);
        *((float4*)(g_t + (size_t)(n0 + eg + i) * 128 + c0)) = r;
    }
}

// -------- per-pair: log_alpha GEMM, Sinkhorn(20), plan@sc, relu score --------
__global__ __launch_bounds__(256) void pair_kernel(
    const int* __restrict__ qsizes, const int* __restrict__ csizes,
    float* __restrict__ out)
{
    extern __shared__ float sm[];
    const int LD = 129;
    float* A = sm;
    float* U = sm + 128 * LD;
    float* V = sm + 2 * 128 * LD;
    __shared__ float red[8];
    int tid = threadIdx.x;
    int b = blockIdx.x;
    int qs = g_qstart[b], cs = g_cstart[b];
    int qn = qsizes[b],  cn = csizes[b];

    for (int idx = tid; idx < 128 * 32; idx += 256) {
        int r = idx >> 5, j = idx & 31;
        float4 z = make_float4(0.f, 0.f, 0.f, 0.f);
        float4 u = (r < qn) ? ((const float4*)g_t)[(size_t)(qs + r) * 32 + j] : z;
        float4 v = (r < cn) ? ((const float4*)g_t)[(size_t)(cs + r) * 32 + j] : z;
        float* pu = U + r * LD + j * 4;
        float* pv = V + r * LD + j * 4;
        pu[0] = u.x; pu[1] = u.y; pu[2] = u.z; pu[3] = u.w;
        pv[0] = v.x; pv[1] = v.y; pv[2] = v.z; pv[3] = v.w;
    }
    __syncthreads();

    int q0 = (tid >> 4) * 8, c0 = (tid & 15) * 8;
    {
        float acc[8][8];
#pragma unroll
        for (int i = 0; i < 8; i++)
#pragma unroll
            for (int j = 0; j < 8; j++) acc[i][j] = 0.f;
        for (int d = 0; d < 128; d++) {
            float uq[8], vc[8];
#pragma unroll
            for (int i = 0; i < 8; i++) uq[i] = U[(q0 + i) * LD + d];
#pragma unroll
            for (int j = 0; j < 8; j++) vc[j] = V[(c0 + j) * LD + d];
#pragma unroll
            for (int i = 0; i < 8; i++)
#pragma unroll
                for (int j = 0; j < 8; j++) acc[i][j] += uq[i] * vc[j];
        }
#pragma unroll
        for (int i = 0; i < 8; i++)
#pragma unroll
            for (int j = 0; j < 8; j++) A[(q0 + i) * LD + c0 + j] = acc[i][j] * 10.0f;
    }
    __syncthreads();

    int warp = tid >> 5, lane = tid & 31;
    for (int it = 0; it < 20; it++) {
        for (int r = warp; r < 128; r += 8) {
            float v0 = A[r * LD + lane],      v1 = A[r * LD + lane + 32];
            float v2 = A[r * LD + lane + 64], v3 = A[r * LD + lane + 96];
            float m = fmaxf(fmaxf(v0, v1), fmaxf(v2, v3));
#pragma unroll
            for (int o = 16; o > 0; o >>= 1) m = fmaxf(m, __shfl_xor_sync(0xffffffffu, m, o));
            float s = __expf(v0 - m) + __expf(v1 - m) + __expf(v2 - m) + __expf(v3 - m);
#pragma unroll
            for (int o = 16; o > 0; o >>= 1) s += __shfl_xor_sync(0xffffffffu, s, o);
            float lse = m + __logf(s);
            A[r * LD + lane]      = v0 - lse; A[r * LD + lane + 32] = v1 - lse;
            A[r * LD + lane + 64] = v2 - lse; A[r * LD + lane + 96] = v3 - lse;
        }
        __syncthreads();
        for (int c = warp; c < 128; c += 8) {
            float v0 = A[lane * LD + c],        v1 = A[(lane + 32) * LD + c];
            float v2 = A[(lane + 64) * LD + c], v3 = A[(lane + 96) * LD + c];
            float m = fmaxf(fmaxf(v0, v1), fmaxf(v2, v3));
#pragma unroll
            for (int o = 16; o > 0; o >>= 1) m = fmaxf(m, __shfl_xor_sync(0xffffffffu, m, o));
            float s = __expf(v0 - m) + __expf(v1 - m) + __expf(v2 - m) + __expf(v3 - m);
#pragma unroll
            for (int o = 16; o > 0; o >>= 1) s += __shfl_xor_sync(0xffffffffu, s, o);
            float lse = m + __logf(s);
            A[lane * LD + c]        = v0 - lse; A[(lane + 32) * LD + c] = v1 - lse;
            A[(lane + 64) * LD + c] = v2 - lse; A[(lane + 96) * LD + c] = v3 - lse;
        }
        __syncthreads();
    }

    for (int idx = tid; idx < 128 * 128; idx += 256) {
        int r = idx >> 7, c = idx & 127;
        A[r * LD + c] = __expf(A[r * LD + c]);
    }
    for (int idx = tid; idx < 128 * 32; idx += 256) {
        int r = idx >> 5, j = idx & 31;
        float4 z = make_float4(0.f, 0.f, 0.f, 0.f);
        float4 u = (r < qn) ? ((const float4*)g_h)[(size_t)(qs + r) * 32 + j] : z;
        float4 v = (r < cn) ? ((const float4*)g_h)[(size_t)(cs + r) * 32 + j] : z;
        float* pu = U + r * LD + j * 4;
        float* pv = V + r * LD + j * 4;
        pu[0] = u.x; pu[1] = u.y; pu[2] = u.z; pu[3] = u.w;
        pv[0] = v.x; pv[1] = v.y; pv[2] = v.z; pv[3] = v.w;
    }
    __syncthreads();

    float local = 0.f;
    {
        int d0 = c0;
        float acc[8][8];
#pragma unroll
        for (int i = 0; i < 8; i++)
#pragma unroll
            for (int j = 0; j < 8; j++) acc[i][j] = 0.f;
        for (int c = 0; c < 128; c++) {
            float pr[8], vv[8];
#pragma unroll
            for (int i = 0; i < 8; i++) pr[i] = A[(q0 + i) * LD + c];
#pragma unroll
            for (int j = 0; j < 8; j++) vv[j] = V[c * LD + d0 + j];
#pragma unroll
            for (int i = 0; i < 8; i++)
#pragma unroll
                for (int j = 0; j < 8; j++) acc[i][j] += pr[i] * vv[j];
        }
#pragma unroll
        for (int i = 0; i < 8; i++)
#pragma unroll
            for (int j = 0; j < 8; j++)
                local += fmaxf(U[(q0 + i) * LD + d0 + j] - acc[i][j], 0.f);
    }
#pragma unroll
    for (int o = 16; o > 0; o >>= 1) local += __shfl_xor_sync(0xffffffffu, local, o);
    if (lane == 0) red[warp] = local;
    __syncthreads();
    if (tid == 0) {
        float tot = 0.f;
#pragma unroll
        for (int w = 0; w < 8; w++) tot += red[w];
        out[b] = -tot;
    }
}

// -------- launch --------
extern "C" void kernel_launch(void* const* d_in, const int* in_sizes, int n_in,
                              void* d_out, int out_size) {
    const float* node_features = (const float*)d_in[0];
    const float* edge_features = (const float*)d_in[1];
    const float* enc_node_w = (const float*)d_in[2];
    const float* enc_node_b = (const float*)d_in[3];
    const float* enc_edge_w = (const float*)d_in[4];
    const float* enc_edge_b = (const float*)d_in[5];
    const float* msg_w1 = (const float*)d_in[6];
    const float* msg_b1 = (const float*)d_in[7];
    const float* msg_w2 = (const float*)d_in[8];
    const float* msg_b2 = (const float*)d_in[9];
    const float* rmsg_w1 = (const float*)d_in[10];
    const float* rmsg_b1 = (const float*)d_in[11];
    const float* rmsg_w2 = (const float*)d_in[12];
    const float* rmsg_b2 = (const float*)d_in[13];
    const float* upd_w1 = (const float*)d_in[14];
    const float* upd_b1 = (const float*)d_in[15];
    const float* upd_w2 = (const float*)d_in[16];
    const float* upd_b2 = (const float*)d_in[17];
    const float* fc1_w = (const float*)d_in[18];
    const float* fc1_b = (const float*)d_in[19];
    const float* fc2_w = (const float*)d_in[20];
    const float* fc2_b = (const float*)d_in[21];
    const int* from_idx = (const int*)d_in[22];
    const int* to_idx = (const int*)d_in[23];
    const int* qsizes = (const int*)d_in[25];
    const int* csizes = (const int*)d_in[26];

    int N = in_sizes[0] / 32;
    int E = in_sizes[1] / 16;
    int B = in_sizes[25];

    int smem_t    = (32 * 128 * 2) * 4;
    int smem_pair = 3 * 128 * 129 * 4;

    cudaFuncSetAttribute(edge_fused_kernel, cudaFuncAttributeMaxDynamicSharedMemorySize, EDGE_SMEM);
    cudaFuncSetAttribute(node_fused_kernel, cudaFuncAttributeMaxDynamicSharedMemorySize, EDGE_SMEM);
    cudaFuncSetAttribute(pair_kernel,       cudaFuncAttributeMaxDynamicSharedMemorySize, smem_pair);

    uint32_t *mw1t, *rw1t, *mw2t, *rw2t;
    cudaGetSymbolAddress((void**)&mw1t, g_mw1t);
    cudaGetSymbolAddress((void**)&rw1t, g_rw1t);
    cudaGetSymbolAddress((void**)&mw2t, g_mw2t);
    cudaGetSymbolAddress((void**)&rw2t, g_rw2t);

    enc_node_kernel<<<(N + 1) / 2, 256>>>(node_features, enc_node_w, enc_node_b, N);
    enc_edge_kernel<<<(E + 3) / 4, 256>>>(edge_features, enc_edge_w, enc_edge_b, E);
    starts_kernel<<<1, 32>>>(qsizes, csizes, B);
    prep_tf32<<<256, 256>>>(msg_w1, rmsg_w1, msg_w2, rmsg_w2, upd_w1, upd_w2);

    for (int p = 0; p < 5; p++) {
        zero_agg_kernel<<<(N * 32 + 255) / 256, 256>>>(N * 32);
        edge_fused_kernel<<<E / 128, 256, EDGE_SMEM>>>(mw1t, msg_b1, mw2t, msg_b2, from_idx, to_idx);
        edge_fused_kernel<<<E / 128, 256, EDGE_SMEM>>>(rw1t, rmsg_b1, rw2t, rmsg_b2, to_idx, from_idx);
        node_fused_kernel<<<N / 128, 256, EDGE_SMEM>>>(upd_b1, upd_b2);
    }
    t_kernel<<<N / 32, 256, smem_t>>>(fc1_w, fc1_b, fc2_w, fc2_b);
    pair_kernel<<<B, 256, smem_pair>>>(qsizes, csizes, (float*)d_out);
}

// round 12
// speedup vs baseline: 5.5879x; 1.8052x over previous
#include <cuda_runtime.h>
#include <cuda_fp16.h>
#include <cstdint>
#include <math.h>

#define NN 98304
#define NE 786432
#define NB 512

// -------- scratch (device globals; no allocation allowed) --------
__device__ __align__(1024) float g_h[(size_t)NN * 128];
__device__ __align__(1024) float g_e[(size_t)NE * 64];
__device__ __align__(1024) float g_agg[(size_t)NN * 128];
__device__ __align__(1024) float g_t[(size_t)NN * 128];
// fp16-packed weights: [kk][n] u32 = half2 over (2kk, 2kk+1)
__device__ __align__(1024) uint32_t g_mw1h[160 * 256];
__device__ __align__(1024) uint32_t g_rw1h[160 * 256];
__device__ __align__(1024) uint32_t g_mw2h[128 * 128];
__device__ __align__(1024) uint32_t g_rw2h[128 * 128];
__device__ __align__(1024) uint32_t g_uw1h[128 * 256];
__device__ __align__(1024) uint32_t g_uw2h[128 * 128];
__device__ int g_qstart[NB];
__device__ int g_cstart[NB];

// -------- helpers --------
__device__ __forceinline__ uint32_t packh2(float a, float b) {
    __half2 h = __floats2half2_rn(a, b);
    return *(uint32_t*)&h;
}
__device__ __forceinline__ void mma_f16(float c[4],
    uint32_t a0, uint32_t a1, uint32_t a2, uint32_t a3, uint32_t b0, uint32_t b1)
{
    asm volatile(
        "mma.sync.aligned.m16n8k16.row.col.f32.f16.f16.f32 "
        "{%0,%1,%2,%3}, {%4,%5,%6,%7}, {%8,%9}, {%0,%1,%2,%3};"
        : "+f"(c[0]), "+f"(c[1]), "+f"(c[2]), "+f"(c[3])
        : "r"(a0), "r"(a1), "r"(a2), "r"(a3), "r"(b0), "r"(b1));
}
__device__ __forceinline__ void red_add_v2(float* p, float a, float b) {
    asm volatile("red.global.add.v2.f32 [%0], {%1, %2};" :: "l"(p), "f"(a), "f"(b) : "memory");
}

// smem layout (u32 strides chosen so 20/264/136/132 mod 32 give conflict-free lanes):
//  sH   [0, 67584)          128 x 132 u32 (half2 H tile)
//  sA   [67584, 88064)      2 x 128 x 20 u32 (half2 A chunk db); GEMM2-B bufs reuse
//  sB1  [88064, 121856)     2 x 16 x 264 u32 (GEMM1-B db)
//  s0   [121856, 122368)    128 ints
//  s1   [122368, 122880)    128 ints
#define LDH 132
#define LDA 20
#define LDB1 264
#define LDB2 136
#define SA_OFF 67584
#define SB1_OFF 88064
#define SI0_OFF 121856
#define SI1_OFF 122368
#define EDGE_SMEM 122880

// -------- prep: pack all GEMM weights into half2 once --------
__global__ void prep_f16(
    const float* __restrict__ mw1, const float* __restrict__ rw1,
    const float* __restrict__ mw2, const float* __restrict__ rw2,
    const float* __restrict__ uw1, const float* __restrict__ uw2)
{
    int i = blockIdx.x * 256 + threadIdx.x;
    int stride = gridDim.x * 256;
    for (int idx = i; idx < 160 * 256; idx += stride) {
        int kk = idx / 256, n = idx % 256;
        g_mw1h[idx] = packh2(mw1[(2 * kk) * 256 + n], mw1[(2 * kk + 1) * 256 + n]);
        g_rw1h[idx] = packh2(rw1[(2 * kk) * 256 + n], rw1[(2 * kk + 1) * 256 + n]);
    }
    for (int idx = i; idx < 128 * 256; idx += stride) {
        int kk = idx / 256, n = idx % 256;
        g_uw1h[idx] = packh2(uw1[(2 * kk) * 256 + n], uw1[(2 * kk + 1) * 256 + n]);
    }
    for (int idx = i; idx < 128 * 128; idx += stride) {
        int kk = idx / 128, n = idx % 128;
        g_mw2h[idx] = packh2(mw2[(2 * kk) * 128 + n], mw2[(2 * kk + 1) * 128 + n]);
        g_rw2h[idx] = packh2(rw2[(2 * kk) * 128 + n], rw2[(2 * kk + 1) * 128 + n]);
        g_uw2h[idx] = packh2(uw2[(2 * kk) * 128 + n], uw2[(2 * kk + 1) * 128 + n]);
    }
}

// ======== fused edge kernel: one half (msg or rmsg) ========
__global__ __launch_bounds__(256, 1) void edge_fused_kernel(
    const uint32_t* __restrict__ W1h, const float* __restrict__ b1,
    const uint32_t* __restrict__ W2h, const float* __restrict__ b2,
    const int* __restrict__ gidx0, const int* __restrict__ gidx1)
{
    extern __shared__ char smc[];
    uint32_t* sH = (uint32_t*)smc;
    uint32_t* sA = (uint32_t*)(smc + SA_OFF);
    uint32_t* sB1 = (uint32_t*)(smc + SB1_OFF);
    int* s0 = (int*)(smc + SI0_OFF);
    int* s1 = (int*)(smc + SI1_OFF);
    int tid = threadIdx.x, lane = tid & 31, w = tid >> 5;
    int gid = lane >> 2, tig = lane & 3;
    int e0 = blockIdx.x * 128;
    if (tid < 128) { s0[tid] = gidx0[e0 + tid]; s1[tid] = gidx1[e0 + tid]; }
    __syncthreads();

    // GEMM1 warp tile: 64 rows x 64 cols (8 warps = 2m x 4n)
    int m1 = (w & 1) * 64;
    int n1 = (w >> 1) * 64;
    float C1[4][8][4];
#pragma unroll
    for (int mt = 0; mt < 4; mt++)
#pragma unroll
        for (int nt = 0; nt < 8; nt++)
#pragma unroll
            for (int q = 0; q < 4; q++) C1[mt][nt][q] = 0.f;

    float4 va[4];
    uint4 vb[4];

#define LD_A1(c) do { \
    _Pragma("unroll") \
    for (int t = 0; t < 4; t++) { \
        int f = tid + t * 256; int r = f >> 3, j = f & 7; \
        const float* src; \
        if ((c) < 4)      src = g_h + (size_t)s0[r] * 128 + (c) * 32 + j * 4; \
        else if ((c) < 8) src = g_h + (size_t)s1[r] * 128 + ((c) - 4) * 32 + j * 4; \
        else              src = g_e + (size_t)(e0 + r) * 64 + ((c) - 8) * 32 + j * 4; \
        va[t] = *(const float4*)src; \
    } \
} while (0)
#define ST_A1(buf) do { \
    _Pragma("unroll") \
    for (int t = 0; t < 4; t++) { \
        int f = tid + t * 256; int r = f >> 3, j = f & 7; \
        uint2 u; u.x = packh2(va[t].x, va[t].y); u.y = packh2(va[t].z, va[t].w); \
        *(uint2*)(sA + (buf) * 128 * LDA + r * LDA + j * 2) = u; \
    } \
} while (0)
#define LD_B1(c) do { \
    _Pragma("unroll") \
    for (int t = 0; t < 4; t++) { \
        int f = tid + t * 256; int r = f >> 6, j = f & 63; \
        vb[t] = ((const uint4*)(W1h + (size_t)((c) * 16 + r) * 256))[j]; \
    } \
} while (0)
#define ST_B1(buf) do { \
    uint32_t* B_ = sB1 + (buf) * 16 * LDB1; \
    _Pragma("unroll") \
    for (int t = 0; t < 4; t++) { \
        int f = tid + t * 256; int r = f >> 6, j = f & 63; \
        *(uint4*)(B_ + r * LDB1 + j * 4) = vb[t]; \
    } \
} while (0)
#define COMPUTE1(buf) do { \
    uint32_t* A = sA + (buf) * 128 * LDA; \
    uint32_t* B = sB1 + (buf) * 16 * LDB1; \
    _Pragma("unroll") \
    for (int ks = 0; ks < 2; ks++) { \
        int kk = ks * 8; \
        uint32_t a[4][4], b[8][2]; \
        _Pragma("unroll") \
        for (int mt = 0; mt < 4; mt++) { \
            int rb = m1 + mt * 16; \
            a[mt][0] = A[(rb + gid) * LDA + kk + tig]; \
            a[mt][1] = A[(rb + gid + 8) * LDA + kk + tig]; \
            a[mt][2] = A[(rb + gid) * LDA + kk + tig + 4]; \
            a[mt][3] = A[(rb + gid + 8) * LDA + kk + tig + 4]; \
        } \
        _Pragma("unroll") \
        for (int nt = 0; nt < 8; nt++) { \
            int col = n1 + nt * 8 + gid; \
            b[nt][0] = B[(kk + tig) * LDB1 + col]; \
            b[nt][1] = B[(kk + tig + 4) * LDB1 + col]; \
        } \
        _Pragma("unroll") \
        for (int mt = 0; mt < 4; mt++) \
            _Pragma("unroll") \
            for (int nt = 0; nt < 8; nt++) \
                mma_f16(C1[mt][nt], a[mt][0], a[mt][1], a[mt][2], a[mt][3], \
                        b[nt][0], b[nt][1]); \
    } \
} while (0)

    // GEMM1: K=320, 10 chunks of 32; double-buffered A+B, 1 sync/chunk
    LD_A1(0); LD_B1(0);
    ST_A1(0); ST_B1(0);
    __syncthreads();
    for (int c = 0; c < 10; c++) {
        if (c < 9) { LD_A1(c + 1); LD_B1(c + 1); }
        COMPUTE1(c & 1);
        if (c < 9) {
            ST_A1((c + 1) & 1); ST_B1((c + 1) & 1);
            __syncthreads();
        }
    }
    __syncthreads();

    // H = relu(C1 + b1) packed half2 into sH (c0,c1 are adjacent cols -> one u32)
#pragma unroll
    for (int mt = 0; mt < 4; mt++) {
        int r0 = m1 + mt * 16 + gid;
#pragma unroll
        for (int nt = 0; nt < 8; nt++) {
            int cl = n1 + nt * 8 + 2 * tig;
            int hk = (cl >> 1);
            float b0v = b1[cl], b1v = b1[cl + 1];
            sH[r0 * LDH + hk] = packh2(fmaxf(C1[mt][nt][0] + b0v, 0.f),
                                       fmaxf(C1[mt][nt][1] + b1v, 0.f));
            sH[(r0 + 8) * LDH + hk] = packh2(fmaxf(C1[mt][nt][2] + b0v, 0.f),
                                             fmaxf(C1[mt][nt][3] + b1v, 0.f));
        }
    }
    __syncthreads();

    // GEMM2: K=256 from sH (kk=128), N=128; warp tile 32 x 64 (4m x 2n)
    int m2 = (w >> 1) * 32;
    int n2 = (w & 1) * 64;
    float C2[2][8][4];
#pragma unroll
    for (int mt = 0; mt < 2; mt++)
#pragma unroll
        for (int nt = 0; nt < 8; nt++)
#pragma unroll
            for (int q = 0; q < 4; q++) C2[mt][nt][q] = 0.f;

#define B2PTR(buf) (sA + (buf) * 16 * LDB2)
#define LD_B2(c) do { \
    _Pragma("unroll") \
    for (int t = 0; t < 2; t++) { \
        int f = tid + t * 256; int r = f >> 5, j = f & 31; \
        vb[t] = ((const uint4*)(W2h + (size_t)((c) * 16 + r) * 128))[j]; \
    } \
} while (0)
#define ST_B2(buf) do { \
    uint32_t* B_ = B2PTR(buf); \
    _Pragma("unroll") \
    for (int t = 0; t < 2; t++) { \
        int f = tid + t * 256; int r = f >> 5, j = f & 31; \
        *(uint4*)(B_ + r * LDB2 + j * 4) = vb[t]; \
    } \
} while (0)
#define COMPUTE2(c, buf) do { \
    uint32_t* B = B2PTR(buf); \
    _Pragma("unroll") \
    for (int ks = 0; ks < 2; ks++) { \
        int kg = (c) * 16 + ks * 8; \
        int kl = ks * 8; \
        uint32_t a[2][4], b[8][2]; \
        _Pragma("unroll") \
        for (int mt = 0; mt < 2; mt++) { \
            int rb = m2 + mt * 16; \
            a[mt][0] = sH[(rb + gid) * LDH + kg + tig]; \
            a[mt][1] = sH[(rb + gid + 8) * LDH + kg + tig]; \
            a[mt][2] = sH[(rb + gid) * LDH + kg + tig + 4]; \
            a[mt][3] = sH[(rb + gid + 8) * LDH + kg + tig + 4]; \
        } \
        _Pragma("unroll") \
        for (int nt = 0; nt < 8; nt++) { \
            int col = n2 + nt * 8 + gid; \
            b[nt][0] = B[(kl + tig) * LDB2 + col]; \
            b[nt][1] = B[(kl + tig + 4) * LDB2 + col]; \
        } \
        _Pragma("unroll") \
        for (int mt = 0; mt < 2; mt++) \
            _Pragma("unroll") \
            for (int nt = 0; nt < 8; nt++) \
                mma_f16(C2[mt][nt], a[mt][0], a[mt][1], a[mt][2], a[mt][3], \
                        b[nt][0], b[nt][1]); \
    } \
} while (0)

    LD_B2(0); ST_B2(0);
    __syncthreads();
    for (int c = 0; c < 8; c++) {
        if (c < 7) LD_B2(c + 1);
        COMPUTE2(c, c & 1);
        if (c < 7) {
            ST_B2((c + 1) & 1);
            __syncthreads();
        }
    }

    // epilogue: vector-atomic scatter to g_agg[s1]
#pragma unroll
    for (int mt = 0; mt < 2; mt++) {
        int r0 = m2 + mt * 16 + gid;
        float* p0 = g_agg + (size_t)s1[r0] * 128;
        float* p1 = g_agg + (size_t)s1[r0 + 8] * 128;
#pragma unroll
        for (int nt = 0; nt < 8; nt++) {
            int cl = n2 + nt * 8 + 2 * tig;
            float b0v = b2[cl], b1v = b2[cl + 1];
            red_add_v2(p0 + cl, C2[mt][nt][0] + b0v, C2[mt][nt][1] + b1v);
            red_add_v2(p1 + cl, C2[mt][nt][2] + b0v, C2[mt][nt][3] + b1v);
        }
    }
#undef LD_A1
#undef ST_A1
#undef LD_B1
#undef ST_B1
#undef COMPUTE1
#undef B2PTR
#undef LD_B2
#undef ST_B2
#undef COMPUTE2
}

// ======== fused node update: h += relu([agg|h]@uw1+b1)@uw2+b2 ========
__global__ __launch_bounds__(256, 1) void node_fused_kernel(
    const float* __restrict__ b1, const float* __restrict__ b2)
{
    extern __shared__ char smc[];
    uint32_t* sH = (uint32_t*)smc;
    uint32_t* sA = (uint32_t*)(smc + SA_OFF);
    uint32_t* sB1 = (uint32_t*)(smc + SB1_OFF);
    int tid = threadIdx.x, lane = tid & 31, w = tid >> 5;
    int gid = lane >> 2, tig = lane & 3;
    int n0 = blockIdx.x * 128;

    int m1 = (w & 1) * 64;
    int n1 = (w >> 1) * 64;
    float C1[4][8][4];
#pragma unroll
    for (int mt = 0; mt < 4; mt++)
#pragma unroll
        for (int nt = 0; nt < 8; nt++)
#pragma unroll
            for (int q = 0; q < 4; q++) C1[mt][nt][q] = 0.f;

    float4 va[4];
    uint4 vb[4];

#define LD_A1N(c) do { \
    _Pragma("unroll") \
    for (int t = 0; t < 4; t++) { \
        int f = tid + t * 256; int r = f >> 3, j = f & 7; \
        const float* src; \
        if ((c) < 4) src = g_agg + (size_t)(n0 + r) * 128 + (c) * 32 + j * 4; \
        else         src = g_h + (size_t)(n0 + r) * 128 + ((c) - 4) * 32 + j * 4; \
        va[t] = *(const float4*)src; \
    } \
} while (0)
#define ST_A1N(buf) do { \
    _Pragma("unroll") \
    for (int t = 0; t < 4; t++) { \
        int f = tid + t * 256; int r = f >> 3, j = f & 7; \
        uint2 u; u.x = packh2(va[t].x, va[t].y); u.y = packh2(va[t].z, va[t].w); \
        *(uint2*)(sA + (buf) * 128 * LDA + r * LDA + j * 2) = u; \
    } \
} while (0)
#define LD_B1N(c) do { \
    _Pragma("unroll") \
    for (int t = 0; t < 4; t++) { \
        int f = tid + t * 256; int r = f >> 6, j = f & 63; \
        vb[t] = ((const uint4*)(g_uw1h + (size_t)((c) * 16 + r) * 256))[j]; \
    } \
} while (0)
#define ST_B1N(buf) do { \
    uint32_t* B_ = sB1 + (buf) * 16 * LDB1; \
    _Pragma("unroll") \
    for (int t = 0; t < 4; t++) { \
        int f = tid + t * 256; int r = f >> 6, j = f & 63; \
        *(uint4*)(B_ + r * LDB1 + j * 4) = vb[t]; \
    } \
} while (0)
#define COMPUTE1N(buf) do { \
    uint32_t* A = sA + (buf) * 128 * LDA; \
    uint32_t* B = sB1 + (buf) * 16 * LDB1; \
    _Pragma("unroll") \
    for (int ks = 0; ks < 2; ks++) { \
        int kk = ks * 8; \
        uint32_t a[4][4], b[8][2]; \
        _Pragma("unroll") \
        for (int mt = 0; mt < 4; mt++) { \
            int rb = m1 + mt * 16; \
            a[mt][0] = A[(rb + gid) * LDA + kk + tig]; \
            a[mt][1] = A[(rb + gid + 8) * LDA + kk + tig]; \
            a[mt][2] = A[(rb + gid) * LDA + kk + tig + 4]; \
            a[mt][3] = A[(rb + gid + 8) * LDA + kk + tig + 4]; \
        } \
        _Pragma("unroll") \
        for (int nt = 0; nt < 8; nt++) { \
            int col = n1 + nt * 8 + gid; \
            b[nt][0] = B[(kk + tig) * LDB1 + col]; \
            b[nt][1] = B[(kk + tig + 4) * LDB1 + col]; \
        } \
        _Pragma("unroll") \
        for (int mt = 0; mt < 4; mt++) \
            _Pragma("unroll") \
            for (int nt = 0; nt < 8; nt++) \
                mma_f16(C1[mt][nt], a[mt][0], a[mt][1], a[mt][2], a[mt][3], \
                        b[nt][0], b[nt][1]); \
    } \
} while (0)

    LD_A1N(0); LD_B1N(0);
    ST_A1N(0); ST_B1N(0);
    __syncthreads();
    for (int c = 0; c < 8; c++) {
        if (c < 7) { LD_A1N(c + 1); LD_B1N(c + 1); }
        COMPUTE1N(c & 1);
        if (c < 7) {
            ST_A1N((c + 1) & 1); ST_B1N((c + 1) & 1);
            __syncthreads();
        }
    }
    __syncthreads();

#pragma unroll
    for (int mt = 0; mt < 4; mt++) {
        int r0 = m1 + mt * 16 + gid;
#pragma unroll
        for (int nt = 0; nt < 8; nt++) {
            int cl = n1 + nt * 8 + 2 * tig;
            int hk = (cl >> 1);
            float b0v = b1[cl], b1v = b1[cl + 1];
            sH[r0 * LDH + hk] = packh2(fmaxf(C1[mt][nt][0] + b0v, 0.f),
                                       fmaxf(C1[mt][nt][1] + b1v, 0.f));
            sH[(r0 + 8) * LDH + hk] = packh2(fmaxf(C1[mt][nt][2] + b0v, 0.f),
                                             fmaxf(C1[mt][nt][3] + b1v, 0.f));
        }
    }
    __syncthreads();

    int m2 = (w >> 1) * 32;
    int n2 = (w & 1) * 64;
    float C2[2][8][4];
#pragma unroll
    for (int mt = 0; mt < 2; mt++)
#pragma unroll
        for (int nt = 0; nt < 8; nt++)
#pragma unroll
            for (int q = 0; q < 4; q++) C2[mt][nt][q] = 0.f;

#define B2PTR(buf) (sA + (buf) * 16 * LDB2)
#define LD_B2N(c) do { \
    _Pragma("unroll") \
    for (int t = 0; t < 2; t++) { \
        int f = tid + t * 256; int r = f >> 5, j = f & 31; \
        vb[t] = ((const uint4*)(g_uw2h + (size_t)((c) * 16 + r) * 128))[j]; \
    } \
} while (0)
#define ST_B2N(buf) do { \
    uint32_t* B_ = B2PTR(buf); \
    _Pragma("unroll") \
    for (int t = 0; t < 2; t++) { \
        int f = tid + t * 256; int r = f >> 5, j = f & 31; \
        *(uint4*)(B_ + r * LDB2 + j * 4) = vb[t]; \
    } \
} while (0)

    LD_B2N(0); ST_B2N(0);
    __syncthreads();
    for (int c = 0; c < 8; c++) {
        if (c < 7) LD_B2N(c + 1);
        {
            uint32_t* B = B2PTR(c & 1);
#pragma unroll
            for (int ks = 0; ks < 2; ks++) {
                int kg = c * 16 + ks * 8;
                int kl = ks * 8;
                uint32_t a[2][4], b[8][2];
#pragma unroll
                for (int mt = 0; mt < 2; mt++) {
                    int rb = m2 + mt * 16;
                    a[mt][0] = sH[(rb + gid) * LDH + kg + tig];
                    a[mt][1] = sH[(rb + gid + 8) * LDH + kg + tig];
                    a[mt][2] = sH[(rb + gid) * LDH + kg + tig + 4];
                    a[mt][3] = sH[(rb + gid + 8) * LDH + kg + tig + 4];
                }
#pragma unroll
                for (int nt = 0; nt < 8; nt++) {
                    int col = n2 + nt * 8 + gid;
                    b[nt][0] = B[(kl + tig) * LDB2 + col];
                    b[nt][1] = B[(kl + tig + 4) * LDB2 + col];
                }
#pragma unroll
                for (int mt = 0; mt < 2; mt++)
#pragma unroll
                    for (int nt = 0; nt < 8; nt++)
                        mma_f16(C2[mt][nt], a[mt][0], a[mt][1], a[mt][2], a[mt][3],
                                b[nt][0], b[nt][1]);
            }
        }
        if (c < 7) {
            ST_B2N((c + 1) & 1);
            __syncthreads();
        }
    }

    // epilogue: h += C2 + b2
#pragma unroll
    for (int mt = 0; mt < 2; mt++) {
        int r0 = m2 + mt * 16 + gid;
        float* p0 = g_h + (size_t)(n0 + r0) * 128;
        float* p1 = g_h + (size_t)(n0 + r0 + 8) * 128;
#pragma unroll
        for (int nt = 0; nt < 8; nt++) {
            int cl = n2 + nt * 8 + 2 * tig;
            float b0v = b2[cl], b1v = b2[cl + 1];
            float2 v0 = *(float2*)(p0 + cl);
            v0.x += C2[mt][nt][0] + b0v; v0.y += C2[mt][nt][1] + b1v;
            *(float2*)(p0 + cl) = v0;
            float2 v1 = *(float2*)(p1 + cl);
            v1.x += C2[mt][nt][2] + b0v; v1.y += C2[mt][nt][3] + b1v;
            *(float2*)(p1 + cl) = v1;
        }
    }
#undef LD_A1N
#undef ST_A1N
#undef LD_B1N
#undef ST_B1N
#undef COMPUTE1N
#undef B2PTR
#undef LD_B2N
#undef ST_B2N
}

// -------- zero agg --------
__global__ void zero_agg_kernel(int n4) {
    int i = blockIdx.x * 256 + threadIdx.x;
    if (i < n4) ((float4*)g_agg)[i] = make_float4(0.f, 0.f, 0.f, 0.f);
}

// -------- per-pair start offsets --------
__global__ void starts_kernel(const int* __restrict__ qs, const int* __restrict__ cs, int nb) {
    if (blockIdx.x == 0 && threadIdx.x == 0) {
        int s = 0;
        for (int b = 0; b < nb; b++) {
            g_qstart[b] = s; s += qs[b];
            g_cstart[b] = s; s += cs[b];
        }
    }
}

// -------- node encoder --------
__global__ __launch_bounds__(256) void enc_node_kernel(
    const float* __restrict__ nf, const float* __restrict__ W,
    const float* __restrict__ bias, int n)
{
    __shared__ float s_nf[2][32];
    int tid = threadIdx.x;
    int local = tid >> 7;
    int c = tid & 127;
    int node = blockIdx.x * 2 + local;
    if (tid < 64) {
        int e = tid >> 5, k = tid & 31;
        int nn = blockIdx.x * 2 + e;
        s_nf[e][k] = (nn < n) ? nf[(size_t)nn * 32 + k] : 0.f;
    }
    __syncthreads();
    if (node >= n) return;
    float acc = bias[c];
#pragma unroll
    for (int k = 0; k < 32; k++) acc += s_nf[local][k] * W[k * 128 + c];
    g_h[(size_t)node * 128 + c] = acc;
}

// -------- edge encoder --------
__global__ __launch_bounds__(256) void enc_edge_kernel(
    const float* __restrict__ ef, const float* __restrict__ W,
    const float* __restrict__ bias, int ne)
{
    __shared__ float s_ef[4][16];
    int tid = threadIdx.x;
    int le = tid >> 6;
    int c = tid & 63;
    int e = blockIdx.x * 4 + le;
    if (tid < 64) {
        int ee = tid >> 4, k = tid & 15;
        int eg = blockIdx.x * 4 + ee;
        s_ef[ee][k] = (eg < ne) ? ef[(size_t)eg * 16 + k] : 0.f;
    }
    __syncthreads();
    if (e >= ne) return;
    float acc = bias[c];
#pragma unroll
    for (int k = 0; k < 16; k++) acc += s_ef[le][k] * W[k * 64 + c];
    g_e[(size_t)e * 64 + c] = acc;
}

// -------- t = mlp2(h; fc1, fc2) --------
__global__ __launch_bounds__(256) void t_kernel(
    const float* __restrict__ w1, const float* __restrict__ b1,
    const float* __restrict__ w2, const float* __restrict__ b2)
{
    extern __shared__ float sm[];
    float* xs = sm;
    float* hs = sm + 32 * 128;
    int tid = threadIdx.x;
    int n0 = blockIdx.x * 32;
    for (int idx = tid; idx < 32 * 32; idx += 256) {
        int r = idx >> 5, j = idx & 31;
        *((float4*)(xs + r * 128 + j * 4)) = ((const float4*)g_h)[(size_t)(n0 + r) * 32 + j];
    }
    __syncthreads();

    int c0 = (tid & 31) * 4;
    int eg = (tid >> 5) * 4;
    float acc[4][4];
    {
        float4 bb = *(const float4*)(b1 + c0);
#pragma unroll
        for (int i = 0; i < 4; i++) { acc[i][0] = bb.x; acc[i][1] = bb.y; acc[i][2] = bb.z; acc[i][3] = bb.w; }
    }
#pragma unroll 4
    for (int k = 0; k < 128; k++) {
        float4 w = *(const float4*)(w1 + k * 128 + c0);
#pragma unroll
        for (int i = 0; i < 4; i++) {
            float x = xs[(eg + i) * 128 + k];
            acc[i][0] += x * w.x; acc[i][1] += x * w.y;
            acc[i][2] += x * w.z; acc[i][3] += x * w.w;
        }
    }
#pragma unroll
    for (int i = 0; i < 4; i++) {
        float4 r;
        r.x = fmaxf(acc[i][0], 0.f); r.y = fmaxf(acc[i][1], 0.f);
        r.z = fmaxf(acc[i][2], 0.f); r.w = fmaxf(acc[i][3], 0.f);
        *((float4*)(hs + (eg + i) * 128 + c0)) = r;
    }
    __syncthreads();

    float acc2[4][4];
    {
        float4 bb = *(const float4*)(b2 + c0);
#pragma unroll
        for (int i = 0; i < 4; i++) { acc2[i][0] = bb.x; acc2[i][1] = bb.y; acc2[i][2] = bb.z; acc2[i][3] = bb.w; }
    }
#pragma unroll 4
    for (int k = 0; k < 128; k++) {
        float4 w = *(const float4*)(w2 + k * 128 + c0);
#pragma unroll
        for (int i = 0; i < 4; i++) {
            float x = hs[(eg + i) * 128 + k];
            acc2[i][0] += x * w.x; acc2[i][1] += x * w.y;
            acc2[i][2] += x * w.z; acc2[i][3] += x * w.w;
        }
    }
#pragma unroll
    for (int i = 0; i < 4; i++) {
        float4 r = make_float4(acc2[i][0], acc2[i][1], acc2[i][2], acc2[i][3]);
        *((float4*)(g_t + (size_t)(n0 + eg + i) * 128 + c0)) = r;
    }
}

// -------- per-pair: log_alpha GEMM, Sinkhorn(20), plan@sc, relu score --------
__global__ __launch_bounds__(256) void pair_kernel(
    const int* __restrict__ qsizes, const int* __restrict__ csizes,
    float* __restrict__ out)
{
    extern __shared__ float sm[];
    const int LD = 129;
    float* A = sm;
    float* U = sm + 128 * LD;
    float* V = sm + 2 * 128 * LD;
    __shared__ float red[8];
    int tid = threadIdx.x;
    int b = blockIdx.x;
    int qs = g_qstart[b], cs = g_cstart[b];
    int qn = qsizes[b],  cn = csizes[b];

    for (int idx = tid; idx < 128 * 32; idx += 256) {
        int r = idx >> 5, j = idx & 31;
        float4 z = make_float4(0.f, 0.f, 0.f, 0.f);
        float4 u = (r < qn) ? ((const float4*)g_t)[(size_t)(qs + r) * 32 + j] : z;
        float4 v = (r < cn) ? ((const float4*)g_t)[(size_t)(cs + r) * 32 + j] : z;
        float* pu = U + r * LD + j * 4;
        float* pv = V + r * LD + j * 4;
        pu[0] = u.x; pu[1] = u.y; pu[2] = u.z; pu[3] = u.w;
        pv[0] = v.x; pv[1] = v.y; pv[2] = v.z; pv[3] = v.w;
    }
    __syncthreads();

    int q0 = (tid >> 4) * 8, c0 = (tid & 15) * 8;
    {
        float acc[8][8];
#pragma unroll
        for (int i = 0; i < 8; i++)
#pragma unroll
            for (int j = 0; j < 8; j++) acc[i][j] = 0.f;
        for (int d = 0; d < 128; d++) {
            float uq[8], vc[8];
#pragma unroll
            for (int i = 0; i < 8; i++) uq[i] = U[(q0 + i) * LD + d];
#pragma unroll
            for (int j = 0; j < 8; j++) vc[j] = V[(c0 + j) * LD + d];
#pragma unroll
            for (int i = 0; i < 8; i++)
#pragma unroll
                for (int j = 0; j < 8; j++) acc[i][j] += uq[i] * vc[j];
        }
#pragma unroll
        for (int i = 0; i < 8; i++)
#pragma unroll
            for (int j = 0; j < 8; j++) A[(q0 + i) * LD + c0 + j] = acc[i][j] * 10.0f;
    }
    __syncthreads();

    int warp = tid >> 5, lane = tid & 31;
    for (int it = 0; it < 20; it++) {
        for (int r = warp; r < 128; r += 8) {
            float v0 = A[r * LD + lane],      v1 = A[r * LD + lane + 32];
            float v2 = A[r * LD + lane + 64], v3 = A[r * LD + lane + 96];
            float m = fmaxf(fmaxf(v0, v1), fmaxf(v2, v3));
#pragma unroll
            for (int o = 16; o > 0; o >>= 1) m = fmaxf(m, __shfl_xor_sync(0xffffffffu, m, o));
            float s = __expf(v0 - m) + __expf(v1 - m) + __expf(v2 - m) + __expf(v3 - m);
#pragma unroll
            for (int o = 16; o > 0; o >>= 1) s += __shfl_xor_sync(0xffffffffu, s, o);
            float lse = m + __logf(s);
            A[r * LD + lane]      = v0 - lse; A[r * LD + lane + 32] = v1 - lse;
            A[r * LD + lane + 64] = v2 - lse; A[r * LD + lane + 96] = v3 - lse;
        }
        __syncthreads();
        for (int c = warp; c < 128; c += 8) {
            float v0 = A[lane * LD + c],        v1 = A[(lane + 32) * LD + c];
            float v2 = A[(lane + 64) * LD + c], v3 = A[(lane + 96) * LD + c];
            float m = fmaxf(fmaxf(v0, v1), fmaxf(v2, v3));
#pragma unroll
            for (int o = 16; o > 0; o >>= 1) m = fmaxf(m, __shfl_xor_sync(0xffffffffu, m, o));
            float s = __expf(v0 - m) + __expf(v1 - m) + __expf(v2 - m) + __expf(v3 - m);
#pragma unroll
            for (int o = 16; o > 0; o >>= 1) s += __shfl_xor_sync(0xffffffffu, s, o);
            float lse = m + __logf(s);
            A[lane * LD + c]        = v0 - lse; A[(lane + 32) * LD + c] = v1 - lse;
            A[(lane + 64) * LD + c] = v2 - lse; A[(lane + 96) * LD + c] = v3 - lse;
        }
        __syncthreads();
    }

    for (int idx = tid; idx < 128 * 128; idx += 256) {
        int r = idx >> 7, c = idx & 127;
        A[r * LD + c] = __expf(A[r * LD + c]);
    }
    for (int idx = tid; idx < 128 * 32; idx += 256) {
        int r = idx >> 5, j = idx & 31;
        float4 z = make_float4(0.f, 0.f, 0.f, 0.f);
        float4 u = (r < qn) ? ((const float4*)g_h)[(size_t)(qs + r) * 32 + j] : z;
        float4 v = (r < cn) ? ((const float4*)g_h)[(size_t)(cs + r) * 32 + j] : z;
        float* pu = U + r * LD + j * 4;
        float* pv = V + r * LD + j * 4;
        pu[0] = u.x; pu[1] = u.y; pu[2] = u.z; pu[3] = u.w;
        pv[0] = v.x; pv[1] = v.y; pv[2] = v.z; pv[3] = v.w;
    }
    __syncthreads();

    float local = 0.f;
    {
        int d0 = c0;
        float acc[8][8];
#pragma unroll
        for (int i = 0; i < 8; i++)
#pragma unroll
            for (int j = 0; j < 8; j++) acc[i][j] = 0.f;
        for (int c = 0; c < 128; c++) {
            float pr[8], vv[8];
#pragma unroll
            for (int i = 0; i < 8; i++) pr[i] = A[(q0 + i) * LD + c];
#pragma unroll
            for (int j = 0; j < 8; j++) vv[j] = V[c * LD + d0 + j];
#pragma unroll
            for (int i = 0; i < 8; i++)
#pragma unroll
                for (int j = 0; j < 8; j++) acc[i][j] += pr[i] * vv[j];
        }
#pragma unroll
        for (int i = 0; i < 8; i++)
#pragma unroll
            for (int j = 0; j < 8; j++)
                local += fmaxf(U[(q0 + i) * LD + d0 + j] - acc[i][j], 0.f);
    }
#pragma unroll
    for (int o = 16; o > 0; o >>= 1) local += __shfl_xor_sync(0xffffffffu, local, o);
    if (lane == 0) red[warp] = local;
    __syncthreads();
    if (tid == 0) {
        float tot = 0.f;
#pragma unroll
        for (int w = 0; w < 8; w++) tot += red[w];
        out[b] = -tot;
    }
}

// -------- launch --------
extern "C" void kernel_launch(void* const* d_in, const int* in_sizes, int n_in,
                              void* d_out, int out_size) {
    const float* node_features = (const float*)d_in[0];
    const float* edge_features = (const float*)d_in[1];
    const float* enc_node_w = (const float*)d_in[2];
    const float* enc_node_b = (const float*)d_in[3];
    const float* enc_edge_w = (const float*)d_in[4];
    const float* enc_edge_b = (const float*)d_in[5];
    const float* msg_w1 = (const float*)d_in[6];
    const float* msg_b1 = (const float*)d_in[7];
    const float* msg_w2 = (const float*)d_in[8];
    const float* msg_b2 = (const float*)d_in[9];
    const float* rmsg_w1 = (const float*)d_in[10];
    const float* rmsg_b1 = (const float*)d_in[11];
    const float* rmsg_w2 = (const float*)d_in[12];
    const float* rmsg_b2 = (const float*)d_in[13];
    const float* upd_w1 = (const float*)d_in[14];
    const float* upd_b1 = (const float*)d_in[15];
    const float* upd_w2 = (const float*)d_in[16];
    const float* upd_b2 = (const float*)d_in[17];
    const float* fc1_w = (const float*)d_in[18];
    const float* fc1_b = (const float*)d_in[19];
    const float* fc2_w = (const float*)d_in[20];
    const float* fc2_b = (const float*)d_in[21];
    const int* from_idx = (const int*)d_in[22];
    const int* to_idx = (const int*)d_in[23];
    const int* qsizes = (const int*)d_in[25];
    const int* csizes = (const int*)d_in[26];

    int N = in_sizes[0] / 32;
    int E = in_sizes[1] / 16;
    int B = in_sizes[25];

    int smem_t    = (32 * 128 * 2) * 4;
    int smem_pair = 3 * 128 * 129 * 4;

    cudaFuncSetAttribute(edge_fused_kernel, cudaFuncAttributeMaxDynamicSharedMemorySize, EDGE_SMEM);
    cudaFuncSetAttribute(node_fused_kernel, cudaFuncAttributeMaxDynamicSharedMemorySize, EDGE_SMEM);
    cudaFuncSetAttribute(pair_kernel,       cudaFuncAttributeMaxDynamicSharedMemorySize, smem_pair);

    uint32_t *mw1h, *rw1h, *mw2h, *rw2h;
    cudaGetSymbolAddress((void**)&mw1h, g_mw1h);
    cudaGetSymbolAddress((void**)&rw1h, g_rw1h);
    cudaGetSymbolAddress((void**)&mw2h, g_mw2h);
    cudaGetSymbolAddress((void**)&rw2h, g_rw2h);

    enc_node_kernel<<<(N + 1) / 2, 256>>>(node_features, enc_node_w, enc_node_b, N);
    enc_edge_kernel<<<(E + 3) / 4, 256>>>(edge_features, enc_edge_w, enc_edge_b, E);
    starts_kernel<<<1, 32>>>(qsizes, csizes, B);
    prep_f16<<<256, 256>>>(msg_w1, rmsg_w1, msg_w2, rmsg_w2, upd_w1, upd_w2);

    for (int p = 0; p < 5; p++) {
        zero_agg_kernel<<<(N * 32 + 255) / 256, 256>>>(N * 32);
        edge_fused_kernel<<<E / 128, 256, EDGE_SMEM>>>(mw1h, msg_b1, mw2h, msg_b2, from_idx, to_idx);
        edge_fused_kernel<<<E / 128, 256, EDGE_SMEM>>>(rw1h, rmsg_b1, rw2h, rmsg_b2, to_idx, from_idx);
        node_fused_kernel<<<N / 128, 256, EDGE_SMEM>>>(upd_b1, upd_b2);
    }
    t_kernel<<<N / 32, 256, smem_t>>>(fc1_w, fc1_b, fc2_w, fc2_b);
    pair_kernel<<<B, 256, smem_pair>>>(qsizes, csizes, (float*)d_out);
}

// round 13
// speedup vs baseline: 6.5980x; 1.1808x over previous
#include <cuda_runtime.h>
#include <cuda_fp16.h>
#include <cstdint>
#include <math.h>

#define NN 98304
#define NE 786432
#define NB 512

// -------- scratch (device globals; no allocation allowed) --------
__device__ __align__(1024) float g_h[(size_t)NN * 128];
__device__ __align__(1024) float g_e[(size_t)NE * 64];
__device__ __align__(1024) float g_agg[(size_t)NN * 128];
__device__ __align__(1024) float g_t[(size_t)NN * 128];
// node-level P/Q (h @ W1a / W1b), half2-packed: [node][64 cols of half2] -> 128 u32/row... (256 halves)
__device__ __align__(1024) uint32_t g_pm[(size_t)NN * 128];
__device__ __align__(1024) uint32_t g_qm[(size_t)NN * 128];
__device__ __align__(1024) uint32_t g_pr[(size_t)NN * 128];
__device__ __align__(1024) uint32_t g_qr[(size_t)NN * 128];
// per-edge constant: e @ W1e + b1, half2-packed
__device__ __align__(1024) uint32_t g_basem[(size_t)NE * 128];
__device__ __align__(1024) uint32_t g_baser[(size_t)NE * 128];
// fp16-packed weights: [kk][n] u32 = half2 over rows (2kk, 2kk+1)
__device__ __align__(1024) uint32_t g_w1am[64 * 256];
__device__ __align__(1024) uint32_t g_w1bm[64 * 256];
__device__ __align__(1024) uint32_t g_w1em[32 * 256];
__device__ __align__(1024) uint32_t g_w1ar[64 * 256];
__device__ __align__(1024) uint32_t g_w1br[64 * 256];
__device__ __align__(1024) uint32_t g_w1er[32 * 256];
__device__ __align__(1024) uint32_t g_mw2h[128 * 128];
__device__ __align__(1024) uint32_t g_rw2h[128 * 128];
__device__ __align__(1024) uint32_t g_uw1h[128 * 256];
__device__ __align__(1024) uint32_t g_uw2h[128 * 128];
__device__ int g_qstart[NB];
__device__ int g_cstart[NB];

// -------- helpers --------
__device__ __forceinline__ uint32_t packh2(float a, float b) {
    __half2 h = __floats2half2_rn(a, b);
    return *(uint32_t*)&h;
}
__device__ __forceinline__ uint32_t h2add3_relu(uint32_t a, uint32_t b, uint32_t c) {
    __half2 s = __hadd2(__hadd2(*(__half2*)&a, *(__half2*)&b), *(__half2*)&c);
    const __half2 z = __float2half2_rn(0.f);
    s = __hmax2(s, z);
    return *(uint32_t*)&s;
}
__device__ __forceinline__ void mma_f16(float c[4],
    uint32_t a0, uint32_t a1, uint32_t a2, uint32_t a3, uint32_t b0, uint32_t b1)
{
    asm volatile(
        "mma.sync.aligned.m16n8k16.row.col.f32.f16.f16.f32 "
        "{%0,%1,%2,%3}, {%4,%5,%6,%7}, {%8,%9}, {%0,%1,%2,%3};"
        : "+f"(c[0]), "+f"(c[1]), "+f"(c[2]), "+f"(c[3])
        : "r"(a0), "r"(a1), "r"(a2), "r"(a3), "r"(b0), "r"(b1));
}
__device__ __forceinline__ void red_add_v2(float* p, float a, float b) {
    asm volatile("red.global.add.v2.f32 [%0], {%1, %2};" :: "l"(p), "f"(a), "f"(b) : "memory");
}

// ---- shared strides (conflict-free, verified mod 32) ----
#define LDH 132
#define LDA 20
#define LDB1 264
#define LDB2 136
// node_fused layout (unchanged from R12):
#define SA_OFF 67584
#define SB1_OFF 88064
#define NODE_SMEM 122880
// edge_fused2 layout: sH [0,67584), sB2 [67584,84992), s0/s1
#define E2_SB_OFF 67584
#define E2_I0_OFF 84992
#define E2_I1_OFF 85504
#define EDGE2_SMEM 86016
// pq/base kernels: sA [0,20480), sB [20480,54272)
#define PQ_SB_OFF 20480
#define PQ_SMEM 54272

// -------- prep: pack all weights into half2 once --------
__global__ void prep_f16(
    const float* __restrict__ mw1, const float* __restrict__ rw1,
    const float* __restrict__ mw2, const float* __restrict__ rw2,
    const float* __restrict__ uw1, const float* __restrict__ uw2)
{
    int i = blockIdx.x * 256 + threadIdx.x;
    int stride = gridDim.x * 256;
    for (int idx = i; idx < 64 * 256; idx += stride) {
        int kk = idx / 256, n = idx % 256;
        g_w1am[idx] = packh2(mw1[(2 * kk) * 256 + n],       mw1[(2 * kk + 1) * 256 + n]);
        g_w1bm[idx] = packh2(mw1[(128 + 2 * kk) * 256 + n], mw1[(129 + 2 * kk) * 256 + n]);
        g_w1ar[idx] = packh2(rw1[(2 * kk) * 256 + n],       rw1[(2 * kk + 1) * 256 + n]);
        g_w1br[idx] = packh2(rw1[(128 + 2 * kk) * 256 + n], rw1[(129 + 2 * kk) * 256 + n]);
    }
    for (int idx = i; idx < 32 * 256; idx += stride) {
        int kk = idx / 256, n = idx % 256;
        g_w1em[idx] = packh2(mw1[(256 + 2 * kk) * 256 + n], mw1[(257 + 2 * kk) * 256 + n]);
        g_w1er[idx] = packh2(rw1[(256 + 2 * kk) * 256 + n], rw1[(257 + 2 * kk) * 256 + n]);
    }
    for (int idx = i; idx < 128 * 256; idx += stride) {
        int kk = idx / 256, n = idx % 256;
        g_uw1h[idx] = packh2(uw1[(2 * kk) * 256 + n], uw1[(2 * kk + 1) * 256 + n]);
    }
    for (int idx = i; idx < 128 * 128; idx += stride) {
        int kk = idx / 128, n = idx % 128;
        g_mw2h[idx] = packh2(mw2[(2 * kk) * 128 + n], mw2[(2 * kk + 1) * 128 + n]);
        g_rw2h[idx] = packh2(rw2[(2 * kk) * 128 + n], rw2[(2 * kk + 1) * 128 + n]);
        g_uw2h[idx] = packh2(uw2[(2 * kk) * 128 + n], uw2[(2 * kk + 1) * 128 + n]);
    }
}

// ======== pq_kernel: out[n] = h[n] @ Wh  (128x128 @ 128x256, half2 out) ========
__global__ __launch_bounds__(256, 1) void pq_kernel(
    const uint32_t* __restrict__ Wh, uint32_t* __restrict__ out)
{
    extern __shared__ char smc[];
    uint32_t* sA = (uint32_t*)smc;
    uint32_t* sB = (uint32_t*)(smc + PQ_SB_OFF);
    int tid = threadIdx.x, lane = tid & 31, w = tid >> 5;
    int gid = lane >> 2, tig = lane & 3;
    int n0 = blockIdx.x * 128;
    int m1 = (w & 1) * 64;
    int n1 = (w >> 1) * 64;
    float C1[4][8][4];
#pragma unroll
    for (int mt = 0; mt < 4; mt++)
#pragma unroll
        for (int nt = 0; nt < 8; nt++)
#pragma unroll
            for (int q = 0; q < 4; q++) C1[mt][nt][q] = 0.f;
    float4 va[4];
    uint4 vb[4];

#define LD_APQ(c) do { \
    _Pragma("unroll") \
    for (int t = 0; t < 4; t++) { \
        int f = tid + t * 256; int r = f >> 3, j = f & 7; \
        va[t] = *(const float4*)(g_h + (size_t)(n0 + r) * 128 + (c) * 32 + j * 4); \
    } \
} while (0)
#define ST_APQ(buf) do { \
    _Pragma("unroll") \
    for (int t = 0; t < 4; t++) { \
        int f = tid + t * 256; int r = f >> 3, j = f & 7; \
        uint2 u; u.x = packh2(va[t].x, va[t].y); u.y = packh2(va[t].z, va[t].w); \
        *(uint2*)(sA + (buf) * 128 * LDA + r * LDA + j * 2) = u; \
    } \
} while (0)
#define LD_BPQ(c) do { \
    _Pragma("unroll") \
    for (int t = 0; t < 4; t++) { \
        int f = tid + t * 256; int r = f >> 6, j = f & 63; \
        vb[t] = ((const uint4*)(Wh + (size_t)((c) * 16 + r) * 256))[j]; \
    } \
} while (0)
#define ST_BPQ(buf) do { \
    uint32_t* B_ = sB + (buf) * 16 * LDB1; \
    _Pragma("unroll") \
    for (int t = 0; t < 4; t++) { \
        int f = tid + t * 256; int r = f >> 6, j = f & 63; \
        *(uint4*)(B_ + r * LDB1 + j * 4) = vb[t]; \
    } \
} while (0)
#define CMP_PQ(buf) do { \
    uint32_t* A = sA + (buf) * 128 * LDA; \
    uint32_t* B = sB + (buf) * 16 * LDB1; \
    _Pragma("unroll") \
    for (int ks = 0; ks < 2; ks++) { \
        int kk = ks * 8; \
        uint32_t a[4][4], b[8][2]; \
        _Pragma("unroll") \
        for (int mt = 0; mt < 4; mt++) { \
            int rb = m1 + mt * 16; \
            a[mt][0] = A[(rb + gid) * LDA + kk + tig]; \
            a[mt][1] = A[(rb + gid + 8) * LDA + kk + tig]; \
            a[mt][2] = A[(rb + gid) * LDA + kk + tig + 4]; \
            a[mt][3] = A[(rb + gid + 8) * LDA + kk + tig + 4]; \
        } \
        _Pragma("unroll") \
        for (int nt = 0; nt < 8; nt++) { \
            int col = n1 + nt * 8 + gid; \
            b[nt][0] = B[(kk + tig) * LDB1 + col]; \
            b[nt][1] = B[(kk + tig + 4) * LDB1 + col]; \
        } \
        _Pragma("unroll") \
        for (int mt = 0; mt < 4; mt++) \
            _Pragma("unroll") \
            for (int nt = 0; nt < 8; nt++) \
                mma_f16(C1[mt][nt], a[mt][0], a[mt][1], a[mt][2], a[mt][3], \
                        b[nt][0], b[nt][1]); \
    } \
} while (0)

    LD_APQ(0); LD_BPQ(0);
    ST_APQ(0); ST_BPQ(0);
    __syncthreads();
    for (int c = 0; c < 4; c++) {
        if (c < 3) { LD_APQ(c + 1); LD_BPQ(c + 1); }
        CMP_PQ(c & 1);
        if (c < 3) {
            ST_APQ((c + 1) & 1); ST_BPQ((c + 1) & 1);
            __syncthreads();
        }
    }
    // epilogue: pack half2, no bias
#pragma unroll
    for (int mt = 0; mt < 4; mt++) {
        int r0 = m1 + mt * 16 + gid;
#pragma unroll
        for (int nt = 0; nt < 8; nt++) {
            int cl = n1 + nt * 8 + 2 * tig;
            int hk = cl >> 1;
            out[(size_t)(n0 + r0) * 128 + hk]     = packh2(C1[mt][nt][0], C1[mt][nt][1]);
            out[(size_t)(n0 + r0 + 8) * 128 + hk] = packh2(C1[mt][nt][2], C1[mt][nt][3]);
        }
    }
#undef LD_APQ
#undef ST_APQ
#undef LD_BPQ
#undef ST_BPQ
#undef CMP_PQ
}

// ======== base_kernel: out[edge] = e @ We + b1 (128x64 @ 64x256, half2 out) ========
__global__ __launch_bounds__(256, 1) void base_kernel(
    const uint32_t* __restrict__ Weh, const float* __restrict__ b1,
    uint32_t* __restrict__ out)
{
    extern __shared__ char smc[];
    uint32_t* sA = (uint32_t*)smc;
    uint32_t* sB = (uint32_t*)(smc + PQ_SB_OFF);
    int tid = threadIdx.x, lane = tid & 31, w = tid >> 5;
    int gid = lane >> 2, tig = lane & 3;
    int e0 = blockIdx.x * 128;
    int m1 = (w & 1) * 64;
    int n1 = (w >> 1) * 64;
    float C1[4][8][4];
#pragma unroll
    for (int mt = 0; mt < 4; mt++)
#pragma unroll
        for (int nt = 0; nt < 8; nt++)
#pragma unroll
            for (int q = 0; q < 4; q++) C1[mt][nt][q] = 0.f;
    float4 va[4];
    uint4 vb[4];

#define LD_AB(c) do { \
    _Pragma("unroll") \
    for (int t = 0; t < 4; t++) { \
        int f = tid + t * 256; int r = f >> 3, j = f & 7; \
        va[t] = *(const float4*)(g_e + (size_t)(e0 + r) * 64 + (c) * 32 + j * 4); \
    } \
} while (0)
#define ST_AB(buf) do { \
    _Pragma("unroll") \
    for (int t = 0; t < 4; t++) { \
        int f = tid + t * 256; int r = f >> 3, j = f & 7; \
        uint2 u; u.x = packh2(va[t].x, va[t].y); u.y = packh2(va[t].z, va[t].w); \
        *(uint2*)(sA + (buf) * 128 * LDA + r * LDA + j * 2) = u; \
    } \
} while (0)
#define LD_BB(c) do { \
    _Pragma("unroll") \
    for (int t = 0; t < 4; t++) { \
        int f = tid + t * 256; int r = f >> 6, j = f & 63; \
        vb[t] = ((const uint4*)(Weh + (size_t)((c) * 16 + r) * 256))[j]; \
    } \
} while (0)
#define ST_BB(buf) do { \
    uint32_t* B_ = sB + (buf) * 16 * LDB1; \
    _Pragma("unroll") \
    for (int t = 0; t < 4; t++) { \
        int f = tid + t * 256; int r = f >> 6, j = f & 63; \
        *(uint4*)(B_ + r * LDB1 + j * 4) = vb[t]; \
    } \
} while (0)
#define CMP_B(buf) do { \
    uint32_t* A = sA + (buf) * 128 * LDA; \
    uint32_t* B = sB + (buf) * 16 * LDB1; \
    _Pragma("unroll") \
    for (int ks = 0; ks < 2; ks++) { \
        int kk = ks * 8; \
        uint32_t a[4][4], b[8][2]; \
        _Pragma("unroll") \
        for (int mt = 0; mt < 4; mt++) { \
            int rb = m1 + mt * 16; \
            a[mt][0] = A[(rb + gid) * LDA + kk + tig]; \
            a[mt][1] = A[(rb + gid + 8) * LDA + kk + tig]; \
            a[mt][2] = A[(rb + gid) * LDA + kk + tig + 4]; \
            a[mt][3] = A[(rb + gid + 8) * LDA + kk + tig + 4]; \
        } \
        _Pragma("unroll") \
        for (int nt = 0; nt < 8; nt++) { \
            int col = n1 + nt * 8 + gid; \
            b[nt][0] = B[(kk + tig) * LDB1 + col]; \
            b[nt][1] = B[(kk + tig + 4) * LDB1 + col]; \
        } \
        _Pragma("unroll") \
        for (int mt = 0; mt < 4; mt++) \
            _Pragma("unroll") \
            for (int nt = 0; nt < 8; nt++) \
                mma_f16(C1[mt][nt], a[mt][0], a[mt][1], a[mt][2], a[mt][3], \
                        b[nt][0], b[nt][1]); \
    } \
} while (0)

    LD_AB(0); LD_BB(0);
    ST_AB(0); ST_BB(0);
    __syncthreads();
    for (int c = 0; c < 2; c++) {
        if (c < 1) { LD_AB(1); LD_BB(1); }
        CMP_B(c & 1);
        if (c < 1) {
            ST_AB(1); ST_BB(1);
            __syncthreads();
        }
    }
#pragma unroll
    for (int mt = 0; mt < 4; mt++) {
        int r0 = m1 + mt * 16 + gid;
#pragma unroll
        for (int nt = 0; nt < 8; nt++) {
            int cl = n1 + nt * 8 + 2 * tig;
            int hk = cl >> 1;
            float b0v = b1[cl], b1v = b1[cl + 1];
            out[(size_t)(e0 + r0) * 128 + hk]     = packh2(C1[mt][nt][0] + b0v, C1[mt][nt][1] + b1v);
            out[(size_t)(e0 + r0 + 8) * 128 + hk] = packh2(C1[mt][nt][2] + b0v, C1[mt][nt][3] + b1v);
        }
    }
#undef LD_AB
#undef ST_AB
#undef LD_BB
#undef ST_BB
#undef CMP_B
}

// ======== edge kernel: H = relu(Pa[i0]+Pb[i1]+base), agg[i1] += H @ W2 + b2 ========
__global__ __launch_bounds__(256, 2) void edge_fused2(
    const uint32_t* __restrict__ Pa, const uint32_t* __restrict__ Pb,
    const uint32_t* __restrict__ base, const uint32_t* __restrict__ W2h,
    const float* __restrict__ b2,
    const int* __restrict__ i0, const int* __restrict__ i1)
{
    extern __shared__ char smc[];
    uint32_t* sH = (uint32_t*)smc;
    int* s0 = (int*)(smc + E2_I0_OFF);
    int* s1 = (int*)(smc + E2_I1_OFF);
    int tid = threadIdx.x, lane = tid & 31, w = tid >> 5;
    int gid = lane >> 2, tig = lane & 3;
    int e0 = blockIdx.x * 128;
    if (tid < 128) { s0[tid] = i0[e0 + tid]; s1[tid] = i1[e0 + tid]; }
    __syncthreads();

    // build H tile: gather + half2 add + relu (one row per warp per step; coalesced 512B)
#pragma unroll
    for (int t = 0; t < 16; t++) {
        int f = tid + t * 256;
        int r = f >> 5, j = f & 31;
        uint4 pa = ((const uint4*)(Pa + (size_t)s0[r] * 128))[j];
        uint4 pb = ((const uint4*)(Pb + (size_t)s1[r] * 128))[j];
        uint4 bs = ((const uint4*)(base + (size_t)(e0 + r) * 128))[j];
        uint4 o;
        o.x = h2add3_relu(pa.x, pb.x, bs.x);
        o.y = h2add3_relu(pa.y, pb.y, bs.y);
        o.z = h2add3_relu(pa.z, pb.z, bs.z);
        o.w = h2add3_relu(pa.w, pb.w, bs.w);
        *(uint4*)(sH + r * LDH + j * 4) = o;
    }
    __syncthreads();

    // GEMM2: K=256 from sH (kk index), N=128; warp tile 32x64 (4m x 2n)
    int m2 = (w >> 1) * 32;
    int n2 = (w & 1) * 64;
    float C2[2][8][4];
#pragma unroll
    for (int mt = 0; mt < 2; mt++)
#pragma unroll
        for (int nt = 0; nt < 8; nt++)
#pragma unroll
            for (int q = 0; q < 4; q++) C2[mt][nt][q] = 0.f;
    uint4 vb[2];

#define B2PTR(buf) ((uint32_t*)(smc + E2_SB_OFF) + (buf) * 16 * LDB2)
#define LD_B2(c) do { \
    _Pragma("unroll") \
    for (int t = 0; t < 2; t++) { \
        int f = tid + t * 256; int r = f >> 5, j = f & 31; \
        vb[t] = ((const uint4*)(W2h + (size_t)((c) * 16 + r) * 128))[j]; \
    } \
} while (0)
#define ST_B2(buf) do { \
    uint32_t* B_ = B2PTR(buf); \
    _Pragma("unroll") \
    for (int t = 0; t < 2; t++) { \
        int f = tid + t * 256; int r = f >> 5, j = f & 31; \
        *(uint4*)(B_ + r * LDB2 + j * 4) = vb[t]; \
    } \
} while (0)
#define COMPUTE2(c, buf) do { \
    uint32_t* B = B2PTR(buf); \
    _Pragma("unroll") \
    for (int ks = 0; ks < 2; ks++) { \
        int kg = (c) * 16 + ks * 8; \
        int kl = ks * 8; \
        uint32_t a[2][4], b[8][2]; \
        _Pragma("unroll") \
        for (int mt = 0; mt < 2; mt++) { \
            int rb = m2 + mt * 16; \
            a[mt][0] = sH[(rb + gid) * LDH + kg + tig]; \
            a[mt][1] = sH[(rb + gid + 8) * LDH + kg + tig]; \
            a[mt][2] = sH[(rb + gid) * LDH + kg + tig + 4]; \
            a[mt][3] = sH[(rb + gid + 8) * LDH + kg + tig + 4]; \
        } \
        _Pragma("unroll") \
        for (int nt = 0; nt < 8; nt++) { \
            int col = n2 + nt * 8 + gid; \
            b[nt][0] = B[(kl + tig) * LDB2 + col]; \
            b[nt][1] = B[(kl + tig + 4) * LDB2 + col]; \
        } \
        _Pragma("unroll") \
        for (int mt = 0; mt < 2; mt++) \
            _Pragma("unroll") \
            for (int nt = 0; nt < 8; nt++) \
                mma_f16(C2[mt][nt], a[mt][0], a[mt][1], a[mt][2], a[mt][3], \
                        b[nt][0], b[nt][1]); \
    } \
} while (0)

    LD_B2(0); ST_B2(0);
    __syncthreads();
    for (int c = 0; c < 8; c++) {
        if (c < 7) LD_B2(c + 1);
        COMPUTE2(c, c & 1);
        if (c < 7) {
            ST_B2((c + 1) & 1);
            __syncthreads();
        }
    }

    // epilogue: vector-atomic scatter to g_agg[s1]
#pragma unroll
    for (int mt = 0; mt < 2; mt++) {
        int r0 = m2 + mt * 16 + gid;
        float* p0 = g_agg + (size_t)s1[r0] * 128;
        float* p1 = g_agg + (size_t)s1[r0 + 8] * 128;
#pragma unroll
        for (int nt = 0; nt < 8; nt++) {
            int cl = n2 + nt * 8 + 2 * tig;
            float b0v = b2[cl], b1v = b2[cl + 1];
            red_add_v2(p0 + cl, C2[mt][nt][0] + b0v, C2[mt][nt][1] + b1v);
            red_add_v2(p1 + cl, C2[mt][nt][2] + b0v, C2[mt][nt][3] + b1v);
        }
    }
#undef B2PTR
#undef LD_B2
#undef ST_B2
#undef COMPUTE2
}

// ======== fused node update: h += relu([agg|h]@uw1+b1)@uw2+b2 (unchanged) ========
__global__ __launch_bounds__(256, 1) void node_fused_kernel(
    const float* __restrict__ b1, const float* __restrict__ b2)
{
    extern __shared__ char smc[];
    uint32_t* sH = (uint32_t*)smc;
    uint32_t* sA = (uint32_t*)(smc + SA_OFF);
    uint32_t* sB1 = (uint32_t*)(smc + SB1_OFF);
    int tid = threadIdx.x, lane = tid & 31, w = tid >> 5;
    int gid = lane >> 2, tig = lane & 3;
    int n0 = blockIdx.x * 128;

    int m1 = (w & 1) * 64;
    int n1 = (w >> 1) * 64;
    float C1[4][8][4];
#pragma unroll
    for (int mt = 0; mt < 4; mt++)
#pragma unroll
        for (int nt = 0; nt < 8; nt++)
#pragma unroll
            for (int q = 0; q < 4; q++) C1[mt][nt][q] = 0.f;

    float4 va[4];
    uint4 vb[4];

#define LD_A1N(c) do { \
    _Pragma("unroll") \
    for (int t = 0; t < 4; t++) { \
        int f = tid + t * 256; int r = f >> 3, j = f & 7; \
        const float* src; \
        if ((c) < 4) src = g_agg + (size_t)(n0 + r) * 128 + (c) * 32 + j * 4; \
        else         src = g_h + (size_t)(n0 + r) * 128 + ((c) - 4) * 32 + j * 4; \
        va[t] = *(const float4*)src; \
    } \
} while (0)
#define ST_A1N(buf) do { \
    _Pragma("unroll") \
    for (int t = 0; t < 4; t++) { \
        int f = tid + t * 256; int r = f >> 3, j = f & 7; \
        uint2 u; u.x = packh2(va[t].x, va[t].y); u.y = packh2(va[t].z, va[t].w); \
        *(uint2*)(sA + (buf) * 128 * LDA + r * LDA + j * 2) = u; \
    } \
} while (0)
#define LD_B1N(c) do { \
    _Pragma("unroll") \
    for (int t = 0; t < 4; t++) { \
        int f = tid + t * 256; int r = f >> 6, j = f & 63; \
        vb[t] = ((const uint4*)(g_uw1h + (size_t)((c) * 16 + r) * 256))[j]; \
    } \
} while (0)
#define ST_B1N(buf) do { \
    uint32_t* B_ = sB1 + (buf) * 16 * LDB1; \
    _Pragma("unroll") \
    for (int t = 0; t < 4; t++) { \
        int f = tid + t * 256; int r = f >> 6, j = f & 63; \
        *(uint4*)(B_ + r * LDB1 + j * 4) = vb[t]; \
    } \
} while (0)
#define COMPUTE1N(buf) do { \
    uint32_t* A = sA + (buf) * 128 * LDA; \
    uint32_t* B = sB1 + (buf) * 16 * LDB1; \
    _Pragma("unroll") \
    for (int ks = 0; ks < 2; ks++) { \
        int kk = ks * 8; \
        uint32_t a[4][4], b[8][2]; \
        _Pragma("unroll") \
        for (int mt = 0; mt < 4; mt++) { \
            int rb = m1 + mt * 16; \
            a[mt][0] = A[(rb + gid) * LDA + kk + tig]; \
            a[mt][1] = A[(rb + gid + 8) * LDA + kk + tig]; \
            a[mt][2] = A[(rb + gid) * LDA + kk + tig + 4]; \
            a[mt][3] = A[(rb + gid + 8) * LDA + kk + tig + 4]; \
        } \
        _Pragma("unroll") \
        for (int nt = 0; nt < 8; nt++) { \
            int col = n1 + nt * 8 + gid; \
            b[nt][0] = B[(kk + tig) * LDB1 + col]; \
            b[nt][1] = B[(kk + tig + 4) * LDB1 + col]; \
        } \
        _Pragma("unroll") \
        for (int mt = 0; mt < 4; mt++) \
            _Pragma("unroll") \
            for (int nt = 0; nt < 8; nt++) \
                mma_f16(C1[mt][nt], a[mt][0], a[mt][1], a[mt][2], a[mt][3], \
                        b[nt][0], b[nt][1]); \
    } \
} while (0)

    LD_A1N(0); LD_B1N(0);
    ST_A1N(0); ST_B1N(0);
    __syncthreads();
    for (int c = 0; c < 8; c++) {
        if (c < 7) { LD_A1N(c + 1); LD_B1N(c + 1); }
        COMPUTE1N(c & 1);
        if (c < 7) {
            ST_A1N((c + 1) & 1); ST_B1N((c + 1) & 1);
            __syncthreads();
        }
    }
    __syncthreads();

#pragma unroll
    for (int mt = 0; mt < 4; mt++) {
        int r0 = m1 + mt * 16 + gid;
#pragma unroll
        for (int nt = 0; nt < 8; nt++) {
            int cl = n1 + nt * 8 + 2 * tig;
            int hk = (cl >> 1);
            float b0v = b1[cl], b1v = b1[cl + 1];
            sH[r0 * LDH + hk] = packh2(fmaxf(C1[mt][nt][0] + b0v, 0.f),
                                       fmaxf(C1[mt][nt][1] + b1v, 0.f));
            sH[(r0 + 8) * LDH + hk] = packh2(fmaxf(C1[mt][nt][2] + b0v, 0.f),
                                             fmaxf(C1[mt][nt][3] + b1v, 0.f));
        }
    }
    __syncthreads();

    int m2 = (w >> 1) * 32;
    int n2 = (w & 1) * 64;
    float C2[2][8][4];
#pragma unroll
    for (int mt = 0; mt < 2; mt++)
#pragma unroll
        for (int nt = 0; nt < 8; nt++)
#pragma unroll
            for (int q = 0; q < 4; q++) C2[mt][nt][q] = 0.f;

#define B2PTRN(buf) (sA + (buf) * 16 * LDB2)
#define LD_B2N(c) do { \
    _Pragma("unroll") \
    for (int t = 0; t < 2; t++) { \
        int f = tid + t * 256; int r = f >> 5, j = f & 31; \
        vb[t] = ((const uint4*)(g_uw2h + (size_t)((c) * 16 + r) * 128))[j]; \
    } \
} while (0)
#define ST_B2N(buf) do { \
    uint32_t* B_ = B2PTRN(buf); \
    _Pragma("unroll") \
    for (int t = 0; t < 2; t++) { \
        int f = tid + t * 256; int r = f >> 5, j = f & 31; \
        *(uint4*)(B_ + r * LDB2 + j * 4) = vb[t]; \
    } \
} while (0)

    LD_B2N(0); ST_B2N(0);
    __syncthreads();
    for (int c = 0; c < 8; c++) {
        if (c < 7) LD_B2N(c + 1);
        {
            uint32_t* B = B2PTRN(c & 1);
#pragma unroll
            for (int ks = 0; ks < 2; ks++) {
                int kg = c * 16 + ks * 8;
                int kl = ks * 8;
                uint32_t a[2][4], b[8][2];
#pragma unroll
                for (int mt = 0; mt < 2; mt++) {
                    int rb = m2 + mt * 16;
                    a[mt][0] = sH[(rb + gid) * LDH + kg + tig];
                    a[mt][1] = sH[(rb + gid + 8) * LDH + kg + tig];
                    a[mt][2] = sH[(rb + gid) * LDH + kg + tig + 4];
                    a[mt][3] = sH[(rb + gid + 8) * LDH + kg + tig + 4];
                }
#pragma unroll
                for (int nt = 0; nt < 8; nt++) {
                    int col = n2 + nt * 8 + gid;
                    b[nt][0] = B[(kl + tig) * LDB2 + col];
                    b[nt][1] = B[(kl + tig + 4) * LDB2 + col];
                }
#pragma unroll
                for (int mt = 0; mt < 2; mt++)
#pragma unroll
                    for (int nt = 0; nt < 8; nt++)
                        mma_f16(C2[mt][nt], a[mt][0], a[mt][1], a[mt][2], a[mt][3],
                                b[nt][0], b[nt][1]);
            }
        }
        if (c < 7) {
            ST_B2N((c + 1) & 1);
            __syncthreads();
        }
    }

#pragma unroll
    for (int mt = 0; mt < 2; mt++) {
        int r0 = m2 + mt * 16 + gid;
        float* p0 = g_h + (size_t)(n0 + r0) * 128;
        float* p1 = g_h + (size_t)(n0 + r0 + 8) * 128;
#pragma unroll
        for (int nt = 0; nt < 8; nt++) {
            int cl = n2 + nt * 8 + 2 * tig;
            float b0v = b2[cl], b1v = b2[cl + 1];
            float2 v0 = *(float2*)(p0 + cl);
            v0.x += C2[mt][nt][0] + b0v; v0.y += C2[mt][nt][1] + b1v;
            *(float2*)(p0 + cl) = v0;
            float2 v1 = *(float2*)(p1 + cl);
            v1.x += C2[mt][nt][2] + b0v; v1.y += C2[mt][nt][3] + b1v;
            *(float2*)(p1 + cl) = v1;
        }
    }
#undef LD_A1N
#undef ST_A1N
#undef LD_B1N
#undef ST_B1N
#undef COMPUTE1N
#undef B2PTRN
#undef LD_B2N
#undef ST_B2N
}

// -------- zero agg --------
__global__ void zero_agg_kernel(int n4) {
    int i = blockIdx.x * 256 + threadIdx.x;
    if (i < n4) ((float4*)g_agg)[i] = make_float4(0.f, 0.f, 0.f, 0.f);
}

// -------- per-pair start offsets --------
__global__ void starts_kernel(const int* __restrict__ qs, const int* __restrict__ cs, int nb) {
    if (blockIdx.x == 0 && threadIdx.x == 0) {
        int s = 0;
        for (int b = 0; b < nb; b++) {
            g_qstart[b] = s; s += qs[b];
            g_cstart[b] = s; s += cs[b];
        }
    }
}

// -------- node encoder --------
__global__ __launch_bounds__(256) void enc_node_kernel(
    const float* __restrict__ nf, const float* __restrict__ W,
    const float* __restrict__ bias, int n)
{
    __shared__ float s_nf[2][32];
    int tid = threadIdx.x;
    int local = tid >> 7;
    int c = tid & 127;
    int node = blockIdx.x * 2 + local;
    if (tid < 64) {
        int e = tid >> 5, k = tid & 31;
        int nn = blockIdx.x * 2 + e;
        s_nf[e][k] = (nn < n) ? nf[(size_t)nn * 32 + k] : 0.f;
    }
    __syncthreads();
    if (node >= n) return;
    float acc = bias[c];
#pragma unroll
    for (int k = 0; k < 32; k++) acc += s_nf[local][k] * W[k * 128 + c];
    g_h[(size_t)node * 128 + c] = acc;
}

// -------- edge encoder --------
__global__ __launch_bounds__(256) void enc_edge_kernel(
    const float* __restrict__ ef, const float* __restrict__ W,
    const float* __restrict__ bias, int ne)
{
    __shared__ float s_ef[4][16];
    int tid = threadIdx.x;
    int le = tid >> 6;
    int c = tid & 63;
    int e = blockIdx.x * 4 + le;
    if (tid < 64) {
        int ee = tid >> 4, k = tid & 15;
        int eg = blockIdx.x * 4 + ee;
        s_ef[ee][k] = (eg < ne) ? ef[(size_t)eg * 16 + k] : 0.f;
    }
    __syncthreads();
    if (e >= ne) return;
    float acc = bias[c];
#pragma unroll
    for (int k = 0; k < 16; k++) acc += s_ef[le][k] * W[k * 64 + c];
    g_e[(size_t)e * 64 + c] = acc;
}

// -------- t = mlp2(h; fc1, fc2) --------
__global__ __launch_bounds__(256) void t_kernel(
    const float* __restrict__ w1, const float* __restrict__ b1,
    const float* __restrict__ w2, const float* __restrict__ b2)
{
    extern __shared__ float sm[];
    float* xs = sm;
    float* hs = sm + 32 * 128;
    int tid = threadIdx.x;
    int n0 = blockIdx.x * 32;
    for (int idx = tid; idx < 32 * 32; idx += 256) {
        int r = idx >> 5, j = idx & 31;
        *((float4*)(xs + r * 128 + j * 4)) = ((const float4*)g_h)[(size_t)(n0 + r) * 32 + j];
    }
    __syncthreads();

    int c0 = (tid & 31) * 4;
    int eg = (tid >> 5) * 4;
    float acc[4][4];
    {
        float4 bb = *(const float4*)(b1 + c0);
#pragma unroll
        for (int i = 0; i < 4; i++) { acc[i][0] = bb.x; acc[i][1] = bb.y; acc[i][2] = bb.z; acc[i][3] = bb.w; }
    }
#pragma unroll 4
    for (int k = 0; k < 128; k++) {
        float4 w = *(const float4*)(w1 + k * 128 + c0);
#pragma unroll
        for (int i = 0; i < 4; i++) {
            float x = xs[(eg + i) * 128 + k];
            acc[i][0] += x * w.x; acc[i][1] += x * w.y;
            acc[i][2] += x * w.z; acc[i][3] += x * w.w;
        }
    }
#pragma unroll
    for (int i = 0; i < 4; i++) {
        float4 r;
        r.x = fmaxf(acc[i][0], 0.f); r.y = fmaxf(acc[i][1], 0.f);
        r.z = fmaxf(acc[i][2], 0.f); r.w = fmaxf(acc[i][3], 0.f);
        *((float4*)(hs + (eg + i) * 128 + c0)) = r;
    }
    __syncthreads();

    float acc2[4][4];
    {
        float4 bb = *(const float4*)(b2 + c0);
#pragma unroll
        for (int i = 0; i < 4; i++) { acc2[i][0] = bb.x; acc2[i][1] = bb.y; acc2[i][2] = bb.z; acc2[i][3] = bb.w; }
    }
#pragma unroll 4
    for (int k = 0; k < 128; k++) {
        float4 w = *(const float4*)(w2 + k * 128 + c0);
#pragma unroll
        for (int i = 0; i < 4; i++) {
            float x = hs[(eg + i) * 128 + k];
            acc2[i][0] += x * w.x; acc2[i][1] += x * w.y;
            acc2[i][2] += x * w.z; acc2[i][3] += x * w.w;
        }
    }
#pragma unroll
    for (int i = 0; i < 4; i++) {
        float4 r = make_float4(acc2[i][0], acc2[i][1], acc2[i][2], acc2[i][3]);
        *((float4*)(g_t + (size_t)(n0 + eg + i) * 128 + c0)) = r;
    }
}

// -------- per-pair: log_alpha GEMM, Sinkhorn(20), plan@sc, relu score --------
__global__ __launch_bounds__(256) void pair_kernel(
    const int* __restrict__ qsizes, const int* __restrict__ csizes,
    float* __restrict__ out)
{
    extern __shared__ float sm[];
    const int LD = 129;
    float* A = sm;
    float* U = sm + 128 * LD;
    float* V = sm + 2 * 128 * LD;
    __shared__ float red[8];
    int tid = threadIdx.x;
    int b = blockIdx.x;
    int qs = g_qstart[b], cs = g_cstart[b];
    int qn = qsizes[b],  cn = csizes[b];

    for (int idx = tid; idx < 128 * 32; idx += 256) {
        int r = idx >> 5, j = idx & 31;
        float4 z = make_float4(0.f, 0.f, 0.f, 0.f);
        float4 u = (r < qn) ? ((const float4*)g_t)[(size_t)(qs + r) * 32 + j] : z;
        float4 v = (r < cn) ? ((const float4*)g_t)[(size_t)(cs + r) * 32 + j] : z;
        float* pu = U + r * LD + j * 4;
        float* pv = V + r * LD + j * 4;
        pu[0] = u.x; pu[1] = u.y; pu[2] = u.z; pu[3] = u.w;
        pv[0] = v.x; pv[1] = v.y; pv[2] = v.z; pv[3] = v.w;
    }
    __syncthreads();

    int q0 = (tid >> 4) * 8, c0 = (tid & 15) * 8;
    {
        float acc[8][8];
#pragma unroll
        for (int i = 0; i < 8; i++)
#pragma unroll
            for (int j = 0; j < 8; j++) acc[i][j] = 0.f;
        for (int d = 0; d < 128; d++) {
            float uq[8], vc[8];
#pragma unroll
            for (int i = 0; i < 8; i++) uq[i] = U[(q0 + i) * LD + d];
#pragma unroll
            for (int j = 0; j < 8; j++) vc[j] = V[(c0 + j) * LD + d];
#pragma unroll
            for (int i = 0; i < 8; i++)
#pragma unroll
                for (int j = 0; j < 8; j++) acc[i][j] += uq[i] * vc[j];
        }
#pragma unroll
        for (int i = 0; i < 8; i++)
#pragma unroll
            for (int j = 0; j < 8; j++) A[(q0 + i) * LD + c0 + j] = acc[i][j] * 10.0f;
    }
    __syncthreads();

    int warp = tid >> 5, lane = tid & 31;
    for (int it = 0; it < 20; it++) {
        for (int r = warp; r < 128; r += 8) {
            float v0 = A[r * LD + lane],      v1 = A[r * LD + lane + 32];
            float v2 = A[r * LD + lane + 64], v3 = A[r * LD + lane + 96];
            float m = fmaxf(fmaxf(v0, v1), fmaxf(v2, v3));
#pragma unroll
            for (int o = 16; o > 0; o >>= 1) m = fmaxf(m, __shfl_xor_sync(0xffffffffu, m, o));
            float s = __expf(v0 - m) + __expf(v1 - m) + __expf(v2 - m) + __expf(v3 - m);
#pragma unroll
            for (int o = 16; o > 0; o >>= 1) s += __shfl_xor_sync(0xffffffffu, s, o);
            float lse = m + __logf(s);
            A[r * LD + lane]      = v0 - lse; A[r * LD + lane + 32] = v1 - lse;
            A[r * LD + lane + 64] = v2 - lse; A[r * LD + lane + 96] = v3 - lse;
        }
        __syncthreads();
        for (int c = warp; c < 128; c += 8) {
            float v0 = A[lane * LD + c],        v1 = A[(lane + 32) * LD + c];
            float v2 = A[(lane + 64) * LD + c], v3 = A[(lane + 96) * LD + c];
            float m = fmaxf(fmaxf(v0, v1), fmaxf(v2, v3));
#pragma unroll
            for (int o = 16; o > 0; o >>= 1) m = fmaxf(m, __shfl_xor_sync(0xffffffffu, m, o));
            float s = __expf(v0 - m) + __expf(v1 - m) + __expf(v2 - m) + __expf(v3 - m);
#pragma unroll
            for (int o = 16; o > 0; o >>= 1) s += __shfl_xor_sync(0xffffffffu, s, o);
            float lse = m + __logf(s);
            A[lane * LD + c]        = v0 - lse; A[(lane + 32) * LD + c] = v1 - lse;
            A[(lane + 64) * LD + c] = v2 - lse; A[(lane + 96) * LD + c] = v3 - lse;
        }
        __syncthreads();
    }

    for (int idx = tid; idx < 128 * 128; idx += 256) {
        int r = idx >> 7, c = idx & 127;
        A[r * LD + c] = __expf(A[r * LD + c]);
    }
    for (int idx = tid; idx < 128 * 32; idx += 256) {
        int r = idx >> 5, j = idx & 31;
        float4 z = make_float4(0.f, 0.f, 0.f, 0.f);
        float4 u = (r < qn) ? ((const float4*)g_h)[(size_t)(qs + r) * 32 + j] : z;
        float4 v = (r < cn) ? ((const float4*)g_h)[(size_t)(cs + r) * 32 + j] : z;
        float* pu = U + r * LD + j * 4;
        float* pv = V + r * LD + j * 4;
        pu[0] = u.x; pu[1] = u.y; pu[2] = u.z; pu[3] = u.w;
        pv[0] = v.x; pv[1] = v.y; pv[2] = v.z; pv[3] = v.w;
    }
    __syncthreads();

    float local = 0.f;
    {
        int d0 = c0;
        float acc[8][8];
#pragma unroll
        for (int i = 0; i < 8; i++)
#pragma unroll
            for (int j = 0; j < 8; j++) acc[i][j] = 0.f;
        for (int c = 0; c < 128; c++) {
            float pr[8], vv[8];
#pragma unroll
            for (int i = 0; i < 8; i++) pr[i] = A[(q0 + i) * LD + c];
#pragma unroll
            for (int j = 0; j < 8; j++) vv[j] = V[c * LD + d0 + j];
#pragma unroll
            for (int i = 0; i < 8; i++)
#pragma unroll
                for (int j = 0; j < 8; j++) acc[i][j] += pr[i] * vv[j];
        }
#pragma unroll
        for (int i = 0; i < 8; i++)
#pragma unroll
            for (int j = 0; j < 8; j++)
                local += fmaxf(U[(q0 + i) * LD + d0 + j] - acc[i][j], 0.f);
    }
#pragma unroll
    for (int o = 16; o > 0; o >>= 1) local += __shfl_xor_sync(0xffffffffu, local, o);
    if (lane == 0) red[warp] = local;
    __syncthreads();
    if (tid == 0) {
        float tot = 0.f;
#pragma unroll
        for (int w = 0; w < 8; w++) tot += red[w];
        out[b] = -tot;
    }
}

// -------- launch --------
extern "C" void kernel_launch(void* const* d_in, const int* in_sizes, int n_in,
                              void* d_out, int out_size) {
    const float* node_features = (const float*)d_in[0];
    const float* edge_features = (const float*)d_in[1];
    const float* enc_node_w = (const float*)d_in[2];
    const float* enc_node_b = (const float*)d_in[3];
    const float* enc_edge_w = (const float*)d_in[4];
    const float* enc_edge_b = (const float*)d_in[5];
    const float* msg_w1 = (const float*)d_in[6];
    const float* msg_b1 = (const float*)d_in[7];
    const float* msg_w2 = (const float*)d_in[8];
    const float* msg_b2 = (const float*)d_in[9];
    const float* rmsg_w1 = (const float*)d_in[10];
    const float* rmsg_b1 = (const float*)d_in[11];
    const float* rmsg_w2 = (const float*)d_in[12];
    const float* rmsg_b2 = (const float*)d_in[13];
    const float* upd_w1 = (const float*)d_in[14];
    const float* upd_b1 = (const float*)d_in[15];
    const float* upd_w2 = (const float*)d_in[16];
    const float* upd_b2 = (const float*)d_in[17];
    const float* fc1_w = (const float*)d_in[18];
    const float* fc1_b = (const float*)d_in[19];
    const float* fc2_w = (const float*)d_in[20];
    const float* fc2_b = (const float*)d_in[21];
    const int* from_idx = (const int*)d_in[22];
    const int* to_idx = (const int*)d_in[23];
    const int* qsizes = (const int*)d_in[25];
    const int* csizes = (const int*)d_in[26];

    int N = in_sizes[0] / 32;
    int E = in_sizes[1] / 16;
    int B = in_sizes[25];

    int smem_t    = (32 * 128 * 2) * 4;
    int smem_pair = 3 * 128 * 129 * 4;

    cudaFuncSetAttribute(edge_fused2,      cudaFuncAttributeMaxDynamicSharedMemorySize, EDGE2_SMEM);
    cudaFuncSetAttribute(node_fused_kernel, cudaFuncAttributeMaxDynamicSharedMemorySize, NODE_SMEM);
    cudaFuncSetAttribute(pq_kernel,        cudaFuncAttributeMaxDynamicSharedMemorySize, PQ_SMEM);
    cudaFuncSetAttribute(base_kernel,      cudaFuncAttributeMaxDynamicSharedMemorySize, PQ_SMEM);
    cudaFuncSetAttribute(pair_kernel,      cudaFuncAttributeMaxDynamicSharedMemorySize, smem_pair);

    uint32_t *w1am, *w1bm, *w1em, *w1ar, *w1br, *w1er, *mw2h, *rw2h;
    uint32_t *pm, *qm, *pr, *qr, *basem, *baser;
    cudaGetSymbolAddress((void**)&w1am, g_w1am);
    cudaGetSymbolAddress((void**)&w1bm, g_w1bm);
    cudaGetSymbolAddress((void**)&w1em, g_w1em);
    cudaGetSymbolAddress((void**)&w1ar, g_w1ar);
    cudaGetSymbolAddress((void**)&w1br, g_w1br);
    cudaGetSymbolAddress((void**)&w1er, g_w1er);
    cudaGetSymbolAddress((void**)&mw2h, g_mw2h);
    cudaGetSymbolAddress((void**)&rw2h, g_rw2h);
    cudaGetSymbolAddress((void**)&pm, g_pm);
    cudaGetSymbolAddress((void**)&qm, g_qm);
    cudaGetSymbolAddress((void**)&pr, g_pr);
    cudaGetSymbolAddress((void**)&qr, g_qr);
    cudaGetSymbolAddress((void**)&basem, g_basem);
    cudaGetSymbolAddress((void**)&baser, g_baser);

    enc_node_kernel<<<(N + 1) / 2, 256>>>(node_features, enc_node_w, enc_node_b, N);
    enc_edge_kernel<<<(E + 3) / 4, 256>>>(edge_features, enc_edge_w, enc_edge_b, E);
    starts_kernel<<<1, 32>>>(qsizes, csizes, B);
    prep_f16<<<256, 256>>>(msg_w1, rmsg_w1, msg_w2, rmsg_w2, upd_w1, upd_w2);

    // per-edge constants (e never changes across props)
    base_kernel<<<E / 128, 256, PQ_SMEM>>>(w1em, msg_b1, basem);
    base_kernel<<<E / 128, 256, PQ_SMEM>>>(w1er, rmsg_b1, baser);

    for (int p = 0; p < 5; p++) {
        zero_agg_kernel<<<(N * 32 + 255) / 256, 256>>>(N * 32);
        // node-level GEMM1 factors
        pq_kernel<<<N / 128, 256, PQ_SMEM>>>(w1am, pm);
        pq_kernel<<<N / 128, 256, PQ_SMEM>>>(w1bm, qm);
        pq_kernel<<<N / 128, 256, PQ_SMEM>>>(w1ar, pr);
        pq_kernel<<<N / 128, 256, PQ_SMEM>>>(w1br, qr);
        // msg: H = relu(Pm[from] + Qm[to] + basem), scatter to to_idx
        edge_fused2<<<E / 128, 256, EDGE2_SMEM>>>(pm, qm, basem, mw2h, msg_b2, from_idx, to_idx);
        // rmsg: H = relu(Pr[to] + Qr[from] + baser), scatter to from_idx
        edge_fused2<<<E / 128, 256, EDGE2_SMEM>>>(pr, qr, baser, rw2h, rmsg_b2, to_idx, from_idx);
        node_fused_kernel<<<N / 128, 256, NODE_SMEM>>>(upd_b1, upd_b2);
    }
    t_kernel<<<N / 32, 256, smem_t>>>(fc1_w, fc1_b, fc2_w, fc2_b);
    pair_kernel<<<B, 256, smem_pair>>>(qsizes, csizes, (float*)d_out);
}